// round 6
// baseline (speedup 1.0000x reference)
#include <cuda_runtime.h>
#include <cuda_bf16.h>
#include <math.h>
#include <stdint.h>

// Problem constants
#define S_LEN 2048
#define B_SZ  2
#define H_DIM 2048
#define NH    16
#define DH    128
#define N3    (3 * H_DIM)          // 6144
#define M_ROWS (S_LEN * B_SZ)      // 4096
#define MASK_VALUE (-10000.0f)

// Scratch — [b][h][s][d] layout for q,k,v; [s*B+b][H] for ctx
__device__ float g_q[B_SZ * NH * S_LEN * DH];
__device__ float g_k[B_SZ * NH * S_LEN * DH];
__device__ float g_v[B_SZ * NH * S_LEN * DH];
__device__ float g_ctx[M_ROWS * H_DIM];

// ---------------------------------------------------------------------------
// helpers
// ---------------------------------------------------------------------------
__device__ __forceinline__ float to_tf32(float x)
{
    uint32_t u;
    asm("cvt.rna.tf32.f32 %0, %1;" : "=r"(u) : "f"(x));
    return __uint_as_float(u);
}

__device__ __forceinline__ void mma_tf32(float* c, const uint32_t* a, const uint32_t* b)
{
    asm volatile(
        "mma.sync.aligned.m16n8k8.row.col.f32.tf32.tf32.f32 "
        "{%0,%1,%2,%3}, {%4,%5,%6,%7}, {%8,%9}, {%0,%1,%2,%3};"
        : "+f"(c[0]), "+f"(c[1]), "+f"(c[2]), "+f"(c[3])
        : "r"(a[0]), "r"(a[1]), "r"(a[2]), "r"(a[3]),
          "r"(b[0]), "r"(b[1]));
}

__device__ __forceinline__ void mma_bf16(float* c, const uint32_t* a, const uint32_t* b)
{
    asm volatile(
        "mma.sync.aligned.m16n8k16.row.col.f32.bf16.bf16.f32 "
        "{%0,%1,%2,%3}, {%4,%5,%6,%7}, {%8,%9}, {%0,%1,%2,%3};"
        : "+f"(c[0]), "+f"(c[1]), "+f"(c[2]), "+f"(c[3])
        : "r"(a[0]), "r"(a[1]), "r"(a[2]), "r"(a[3]),
          "r"(b[0]), "r"(b[1]));
}

// Split two floats into bf16 hi/lo pairs, packed (x0 in low half).
__device__ __forceinline__ void split2_pack(float x0, float x1,
                                            uint32_t& hi, uint32_t& lo)
{
    __nv_bfloat16 h0 = __float2bfloat16_rn(x0);
    __nv_bfloat16 h1 = __float2bfloat16_rn(x1);
    __nv_bfloat16 l0 = __float2bfloat16_rn(x0 - __bfloat162float(h0));
    __nv_bfloat16 l1 = __float2bfloat16_rn(x1 - __bfloat162float(h1));
    __nv_bfloat162 hp = __halves2bfloat162(h0, h1);
    __nv_bfloat162 lp = __halves2bfloat162(l0, l1);
    hi = *reinterpret_cast<uint32_t*>(&hp);
    lo = *reinterpret_cast<uint32_t*>(&lp);
}

// ---------------------------------------------------------------------------
// Tensor-core GEMM, 3x bf16 split, FRAGMENT-LAYOUT smem + double buffering.
// C[M,N] = A[M,K] @ B[K,N]. 128x128 block tile, 256 thr, warp tile 64x32,
// BK=32 (2 k16 steps per tile).
//
// Frag layouts (uint32 units):
//   A (m16k16 frag):  idx = ((step*8 + mt)*32 + lane)*4 + reg   (2048/buf op)
//   B (n8k16  frag):  idx = ((step*16 + nt)*32 + lane)*2 + reg  (2048/buf op)
// Per buffer: [Ahi|Alo|Bhi|Blo] = 8192 u32 = 32KB; 2 buffers = 64KB.
// ---------------------------------------------------------------------------
#define GEMM_SMEM_BYTES (2 * 8192 * 4)

// Direct (unstaged) tile load for the prologue.
__device__ __forceinline__ void gemm_load_tile(
    uint32_t* buf, const float* __restrict__ A, const float* __restrict__ Bm,
    int m0, int n0, int K, int N, int k0, int tid)
{
    uint32_t* Ahi = buf;
    uint32_t* Alo = buf + 2048;
    uint32_t* Bhi = buf + 4096;
    uint32_t* Blo = buf + 6144;

    const int arw = tid >> 3;
    const int akc = (tid & 7) << 2;
    const int bpr = tid >> 5;
    const int bnc = (tid & 31) << 2;

#pragma unroll
    for (int p = 0; p < 4; p++) {
        int m = arw + p * 32;
        float4 v = *reinterpret_cast<const float4*>(&A[(size_t)(m0 + m) * K + k0 + akc]);
        int mt = m >> 4, row = m & 15;
#pragma unroll
        for (int w = 0; w < 2; w++) {
            float x0 = w ? v.z : v.x;
            float x1 = w ? v.w : v.y;
            int pw = (akc >> 1) + w;
            int step = pw >> 3, pwi = pw & 7;
            int lane_t = ((row & 7) << 2) + (pwi & 3);
            int reg = ((row >> 3) & 1) + ((pwi & 4) >> 1);
            int idx = (((step << 3) + mt) * 32 + lane_t) * 4 + reg;
            uint32_t hi, lo;
            split2_pack(x0, x1, hi, lo);
            Ahi[idx] = hi; Alo[idx] = lo;
        }
    }
#pragma unroll
    for (int p = 0; p < 2; p++) {
        int pr = bpr + p * 8;
        const float* r0 = &Bm[(size_t)(k0 + 2 * pr) * N + n0 + bnc];
        float4 u = *reinterpret_cast<const float4*>(r0);
        float4 w4 = *reinterpret_cast<const float4*>(r0 + N);
        float us[4] = {u.x, u.y, u.z, u.w};
        float ws[4] = {w4.x, w4.y, w4.z, w4.w};
        int step = pr >> 3, pwi = pr & 7;
#pragma unroll
        for (int c = 0; c < 4; c++) {
            int n = bnc + c;
            int nt = n >> 3, gt = n & 7;
            int lane_t = (gt << 2) + (pwi & 3);
            int reg = pwi >> 2;
            int idx = ((step * 16 + nt) * 32 + lane_t) * 2 + reg;
            uint32_t hi, lo;
            split2_pack(us[c], ws[c], hi, lo);
            Bhi[idx] = hi; Blo[idx] = lo;
        }
    }
}

__global__ __launch_bounds__(256, 2)
void gemm_tc(const float* __restrict__ A, const float* __restrict__ Bm,
             const float* __restrict__ bias, float* __restrict__ C,
             float* __restrict__ qd, float* __restrict__ kd, float* __restrict__ vd,
             const float* __restrict__ bdt,
             int M, int N, int K, int mode)
{
    extern __shared__ uint32_t smg[];

    const int tid  = threadIdx.x;
    const int lane = tid & 31;
    const int warp = tid >> 5;
    const int wm   = warp & 1;
    const int wn   = warp >> 1;
    const int g    = lane >> 2;
    const int cq   = lane & 3;

    const int m0 = blockIdx.y * 128;
    const int n0 = blockIdx.x * 128;

    float acc[4][4][4];
#pragma unroll
    for (int mt = 0; mt < 4; mt++)
#pragma unroll
        for (int nt = 0; nt < 4; nt++)
#pragma unroll
            for (int r = 0; r < 4; r++) acc[mt][nt][r] = 0.0f;

    const int arw = tid >> 3;
    const int akc = (tid & 7) << 2;
    const int bpr = tid >> 5;
    const int bnc = (tid & 31) << 2;

    // Prologue: tile 0 into buffer 0
    gemm_load_tile(smg, A, Bm, m0, n0, K, N, 0, tid);
    __syncthreads();

    const int NT = K / 32;
    for (int kt = 0; kt < NT; kt++) {
        const uint32_t* buf = smg + (kt & 1) * 8192;
        const uint4* Ahi4 = reinterpret_cast<const uint4*>(buf);
        const uint4* Alo4 = reinterpret_cast<const uint4*>(buf + 2048);
        const uint2* Bhi2 = reinterpret_cast<const uint2*>(buf + 4096);
        const uint2* Blo2 = reinterpret_cast<const uint2*>(buf + 6144);

        // Stage next tile's global loads (overlap with compute)
        const bool has_next = (kt + 1 < NT);
        float4 a_stg[4], b0_stg[2], b1_stg[2];
        if (has_next) {
            const int k0 = (kt + 1) * 32;
#pragma unroll
            for (int p = 0; p < 4; p++)
                a_stg[p] = *reinterpret_cast<const float4*>(
                    &A[(size_t)(m0 + arw + p * 32) * K + k0 + akc]);
#pragma unroll
            for (int p = 0; p < 2; p++) {
                int pr = bpr + p * 8;
                const float* r0 = &Bm[(size_t)(k0 + 2 * pr) * N + n0 + bnc];
                b0_stg[p] = *reinterpret_cast<const float4*>(r0);
                b1_stg[p] = *reinterpret_cast<const float4*>(r0 + N);
            }
        }

        // Compute on current buffer
#pragma unroll
        for (int kk = 0; kk < 2; kk++) {
            uint4 ah4[4], al4[4];
#pragma unroll
            for (int mtl = 0; mtl < 4; mtl++) {
                int ai = ((kk * 8) + wm * 4 + mtl) * 32 + lane;
                ah4[mtl] = Ahi4[ai];
                al4[mtl] = Alo4[ai];
            }
            uint2 bh2[4], bl2[4];
#pragma unroll
            for (int ntl = 0; ntl < 4; ntl++) {
                int bi = ((kk * 16) + wn * 4 + ntl) * 32 + lane;
                bh2[ntl] = Bhi2[bi];
                bl2[ntl] = Blo2[bi];
            }
#pragma unroll
            for (int mtl = 0; mtl < 4; mtl++)
#pragma unroll
                for (int ntl = 0; ntl < 4; ntl++) {
                    mma_bf16(acc[mtl][ntl],
                             reinterpret_cast<uint32_t*>(&ah4[mtl]),
                             reinterpret_cast<uint32_t*>(&bh2[ntl]));
                    mma_bf16(acc[mtl][ntl],
                             reinterpret_cast<uint32_t*>(&ah4[mtl]),
                             reinterpret_cast<uint32_t*>(&bl2[ntl]));
                    mma_bf16(acc[mtl][ntl],
                             reinterpret_cast<uint32_t*>(&al4[mtl]),
                             reinterpret_cast<uint32_t*>(&bh2[ntl]));
                }
        }

        // Split + store staged data into next buffer
        if (has_next) {
            uint32_t* nb = smg + ((kt + 1) & 1) * 8192;
            uint32_t* nAhi = nb;
            uint32_t* nAlo = nb + 2048;
            uint32_t* nBhi = nb + 4096;
            uint32_t* nBlo = nb + 6144;
#pragma unroll
            for (int p = 0; p < 4; p++) {
                int m = arw + p * 32;
                int mt = m >> 4, row = m & 15;
#pragma unroll
                for (int w = 0; w < 2; w++) {
                    float x0 = w ? a_stg[p].z : a_stg[p].x;
                    float x1 = w ? a_stg[p].w : a_stg[p].y;
                    int pw = (akc >> 1) + w;
                    int step = pw >> 3, pwi = pw & 7;
                    int lane_t = ((row & 7) << 2) + (pwi & 3);
                    int reg = ((row >> 3) & 1) + ((pwi & 4) >> 1);
                    int idx = (((step << 3) + mt) * 32 + lane_t) * 4 + reg;
                    uint32_t hi, lo;
                    split2_pack(x0, x1, hi, lo);
                    nAhi[idx] = hi; nAlo[idx] = lo;
                }
            }
#pragma unroll
            for (int p = 0; p < 2; p++) {
                int pr = bpr + p * 8;
                int step = pr >> 3, pwi = pr & 7;
                float us[4] = {b0_stg[p].x, b0_stg[p].y, b0_stg[p].z, b0_stg[p].w};
                float ws[4] = {b1_stg[p].x, b1_stg[p].y, b1_stg[p].z, b1_stg[p].w};
#pragma unroll
                for (int c = 0; c < 4; c++) {
                    int n = bnc + c;
                    int nt = n >> 3, gt = n & 7;
                    int lane_t = (gt << 2) + (pwi & 3);
                    int reg = pwi >> 2;
                    int idx = ((step * 16 + nt) * 32 + lane_t) * 2 + reg;
                    uint32_t hi, lo;
                    split2_pack(us[c], ws[c], hi, lo);
                    nBhi[idx] = hi; nBlo[idx] = lo;
                }
            }
        }
        __syncthreads();
    }

    if (mode == 0) {
#pragma unroll
        for (int mt = 0; mt < 4; mt++) {
#pragma unroll
            for (int nt = 0; nt < 4; nt++) {
#pragma unroll
                for (int r = 0; r < 4; r++) {
                    int m = m0 + wm * 64 + mt * 16 + g + ((r >> 1) << 3);
                    int n = n0 + wn * 32 + nt * 8 + 2 * cq + (r & 1);
                    float v = acc[mt][nt][r] + bias[n];
                    int b = m & 1;
                    int s = m >> 1;
                    int head = n / (3 * DH);
                    int rem  = n - head * (3 * DH);
                    int part = rem >> 7;
                    int d    = rem & 127;
                    size_t idx = (((size_t)(b * NH + head)) * S_LEN + s) * DH + d;
                    if (part == 0)      qd[idx] = v;
                    else if (part == 1) kd[idx] = v;
                    else                vd[idx] = v;
                }
            }
        }
    } else {
#pragma unroll
        for (int mt = 0; mt < 4; mt++) {
#pragma unroll
            for (int nt = 0; nt < 4; nt++) {
                int n = n0 + wn * 32 + nt * 8 + 2 * cq;
                int mA = m0 + wm * 64 + mt * 16 + g;
                int mB = mA + 8;
                float2 vA = make_float2(acc[mt][nt][0], acc[mt][nt][1]);
                float2 vB = make_float2(acc[mt][nt][2], acc[mt][nt][3]);
                *reinterpret_cast<float2*>(&C[(size_t)mA * N + n]) = vA;
                *reinterpret_cast<float2*>(&C[(size_t)mB * N + n]) = vB;
            }
        }
        // Fold tuple tail (b_dense) into block (0,0)
        if (bdt && blockIdx.x == 0 && blockIdx.y == 0) {
            for (int i = tid; i < H_DIM; i += 256)
                C[(size_t)M_ROWS * H_DIM + i] = bdt[i];
        }
    }
}

// ---------------------------------------------------------------------------
// Tensor-core flash attention, fragment-layout smem.
// Block = 64 queries of one (b,h), 256 threads.
// QK^T: plain tf32. P@V: 3-term bf16 split. Softmax 4 thr/row.
//
// Frag layouts (word units):
//   Qf (A m16k8, tf32):  ((step*4 + mt)*32 + lane)*4 + reg   16 steps -> 8192 f
//   Kf (B n8k8,  tf32):  ((step*8 + nt)*32 + lane)*2 + reg   16 steps -> 8192 f
//   V  (B n8k16, bf16):  ((step*16 + nt)*32 + lane)*2 + reg   4 steps -> 4096 u32/op
//   P  (A m16k16,bf16):  ((step*4 + mt)*32 + lane)*4 + reg    4 steps -> 2048 u32/op
// ---------------------------------------------------------------------------
#define SR_STRIDE 68
#define ATT_Q_OFF   0
#define ATT_K_OFF   8192
#define ATT_VHI_OFF 16384
#define ATT_VLO_OFF 20480
#define ATT_PHI_OFF 24576
#define ATT_PLO_OFF 26624
#define ATT_SR_OFF  28672
#define ATT_ROW_OFF 33024
#define ATT_SMEM_BYTES ((33024 + 192) * 4)

__global__ __launch_bounds__(256)
void attn_tc(const unsigned char* __restrict__ mask,
             const float* __restrict__ gq, const float* __restrict__ gk,
             const float* __restrict__ gv, float* __restrict__ gctx)
{
    extern __shared__ uint32_t sma[];
    float*    Qf   = reinterpret_cast<float*>(sma + ATT_Q_OFF);
    float*    Kf   = reinterpret_cast<float*>(sma + ATT_K_OFF);
    uint32_t* Vhi  = sma + ATT_VHI_OFF;
    uint32_t* Vlo  = sma + ATT_VLO_OFF;
    uint32_t* Phi  = sma + ATT_PHI_OFF;
    uint32_t* Plo  = sma + ATT_PLO_OFF;
    float*    Sraw = reinterpret_cast<float*>(sma + ATT_SR_OFF);
    float*    mrow = reinterpret_cast<float*>(sma + ATT_ROW_OFF);
    float*    lrow = mrow + 64;
    float*    arow = lrow + 64;

    const int tid  = threadIdx.x;
    const int lane = tid & 31;
    const int warp = tid >> 5;
    const int g    = lane >> 2;
    const int cq   = lane & 3;

    const int bh = blockIdx.y;
    const int b  = bh / NH;
    const int h  = bh - b * NH;
    const int q0 = blockIdx.x * 64;

    const float* qp = gq + (size_t)bh * S_LEN * DH;
    const float* kp = gk + (size_t)bh * S_LEN * DH;
    const float* vp = gv + (size_t)bh * S_LEN * DH;
    const unsigned char* mp = mask + (size_t)b * S_LEN * S_LEN;
    const float inv_norm = 1.0f / sqrtf((float)H_DIM);

    // Load Q tile -> tf32 A-frag layout
    for (int e = tid; e < 64 * 32; e += 256) {
        int r = e >> 5;
        int c = (e & 31) << 2;
        float4 q4 = *reinterpret_cast<const float4*>(&qp[(size_t)(q0 + r) * DH + c]);
        float qv[4] = {q4.x, q4.y, q4.z, q4.w};
        int mt = r >> 4, row = r & 15;
#pragma unroll
        for (int j = 0; j < 4; j++) {
            int k = c + j;
            int step = k >> 3, kk = k & 7;
            int lane_t = ((row & 7) << 2) + (kk & 3);
            int reg = ((row >> 3) & 1) + ((kk & 4) >> 1);
            Qf[((step * 4 + mt) * 32 + lane_t) * 4 + reg] = to_tf32(qv[j]);
        }
    }
    if (tid < 64) { mrow[tid] = -INFINITY; lrow[tid] = 0.0f; }
    __syncthreads();

    const int wmv = warp & 3;
    const int wnv = warp >> 2;
    float o[8][4];
#pragma unroll
    for (int nt = 0; nt < 8; nt++)
#pragma unroll
        for (int r = 0; r < 4; r++) o[nt][r] = 0.0f;

    const int wmq = warp & 3;
    const int wnq = warp >> 2;

    for (int kt = 0; kt < S_LEN / 64; kt++) {
        const int t0 = kt * 64;

        // K tile -> tf32 B-frag layout
        for (int e = tid; e < 64 * 32; e += 256) {
            int r = e >> 5;
            int c = (e & 31) << 2;
            float4 k4 = *reinterpret_cast<const float4*>(&kp[(size_t)(t0 + r) * DH + c]);
            float kv[4] = {k4.x, k4.y, k4.z, k4.w};
            int nt = r >> 3, gt = r & 7;
#pragma unroll
            for (int j = 0; j < 4; j++) {
                int k = c + j;
                int step = k >> 3, kk = k & 7;
                int lane_t = (gt << 2) + (kk & 3);
                int reg = (kk & 4) >> 2;
                Kf[((step * 8 + nt) * 32 + lane_t) * 2 + reg] = to_tf32(kv[j]);
            }
        }
        // V tile -> bf16 hi/lo B-frag layout (pairs along seq)
        for (int e = tid; e < 32 * 32; e += 256) {
            int sp = e >> 5;
            int c  = (e & 31) << 2;
            const float* r0 = &vp[(size_t)(t0 + 2 * sp) * DH + c];
            float4 u = *reinterpret_cast<const float4*>(r0);
            float4 w4 = *reinterpret_cast<const float4*>(r0 + DH);
            float us[4] = {u.x, u.y, u.z, u.w};
            float ws[4] = {w4.x, w4.y, w4.z, w4.w};
            int step = sp >> 3, pwi = sp & 7;
#pragma unroll
            for (int j = 0; j < 4; j++) {
                int d = c + j;
                int nt = d >> 3, gt = d & 7;
                int lane_t = (gt << 2) + (pwi & 3);
                int reg = pwi >> 2;
                int idx = ((step * 16 + nt) * 32 + lane_t) * 2 + reg;
                uint32_t hi, lo;
                split2_pack(us[j], ws[j], hi, lo);
                Vhi[idx] = hi; Vlo[idx] = lo;
            }
        }
        __syncthreads();

        // --- QK^T (tf32): S[64,64] ---
        float sacc[4][4];
#pragma unroll
        for (int nt = 0; nt < 4; nt++)
#pragma unroll
            for (int r = 0; r < 4; r++) sacc[nt][r] = 0.0f;

#pragma unroll
        for (int ks = 0; ks < 16; ks++) {
            uint4 a4 = reinterpret_cast<const uint4*>(Qf)[(ks * 4 + wmq) * 32 + lane];
#pragma unroll
            for (int ntl = 0; ntl < 4; ntl++) {
                int nt = wnq * 4 + ntl;
                uint2 b2 = reinterpret_cast<const uint2*>(Kf)[(ks * 8 + nt) * 32 + lane];
                mma_tf32(sacc[ntl], reinterpret_cast<uint32_t*>(&a4),
                         reinterpret_cast<uint32_t*>(&b2));
            }
        }
        const int mbq = wmq * 16;
        const int nbq = wnq * 32;
#pragma unroll
        for (int nt = 0; nt < 4; nt++) {
#pragma unroll
            for (int r = 0; r < 4; r++) {
                int rr = mbq + g + ((r >> 1) << 3);
                int cc = nbq + nt * 8 + 2 * cq + (r & 1);
                Sraw[rr * SR_STRIDE + cc] = sacc[nt][r];
            }
        }
        __syncthreads();

        // --- softmax: 4 threads per row; pack P hi/lo into A-frag layout ---
        {
            const int row = tid >> 2;
            const int sub = tid & 3;          // == k16 step for this row's P words
            const int cb  = sub * 16;
            float* srow = &Sraw[row * SR_STRIDE + cb];
            const unsigned char* mr = mp + (size_t)(q0 + row) * S_LEN + t0 + cb;

            float v[16];
            float rmax = -INFINITY;
#pragma unroll
            for (int i = 0; i < 16; i += 4) {
                uchar4 mk = *reinterpret_cast<const uchar4*>(mr + i);
                float s0 = srow[i + 0] * inv_norm; if (mk.x) s0 = MASK_VALUE;
                float s1 = srow[i + 1] * inv_norm; if (mk.y) s1 = MASK_VALUE;
                float s2 = srow[i + 2] * inv_norm; if (mk.z) s2 = MASK_VALUE;
                float s3 = srow[i + 3] * inv_norm; if (mk.w) s3 = MASK_VALUE;
                v[i + 0] = s0; v[i + 1] = s1; v[i + 2] = s2; v[i + 3] = s3;
                rmax = fmaxf(rmax, fmaxf(fmaxf(s0, s1), fmaxf(s2, s3)));
            }
            rmax = fmaxf(rmax, __shfl_xor_sync(0xffffffffu, rmax, 1));
            rmax = fmaxf(rmax, __shfl_xor_sync(0xffffffffu, rmax, 2));
            float m_old = mrow[row];
            float m_new = fmaxf(m_old, rmax);
            float alpha = __expf(m_old - m_new);
            float sum = 0.0f;
            const int mt = row >> 4;
            const int rlow = row & 15;
#pragma unroll
            for (int i = 0; i < 16; i += 2) {
                float p0 = __expf(v[i + 0] - m_new);
                float p1 = __expf(v[i + 1] - m_new);
                sum += p0 + p1;
                uint32_t hh, ll;
                split2_pack(p0, p1, hh, ll);
                int pwi = i >> 1;
                int lane_t = ((rlow & 7) << 2) + (pwi & 3);
                int reg = ((rlow >> 3) & 1) + ((pwi & 4) >> 1);
                int idx = ((sub * 4 + mt) * 32 + lane_t) * 4 + reg;
                Phi[idx] = hh;
                Plo[idx] = ll;
            }
            sum += __shfl_xor_sync(0xffffffffu, sum, 1);
            sum += __shfl_xor_sync(0xffffffffu, sum, 2);
            if (sub == 0) {
                lrow[row] = lrow[row] * alpha + sum;
                mrow[row] = m_new;
                arow[row] = alpha;
            }
        }
        __syncthreads();

        // --- rescale O, then P@V (bf16 3-split, 4 k16 steps) ---
        const int mbv = wmv * 16;
        {
            float al0 = arow[mbv + g];
            float al1 = arow[mbv + g + 8];
#pragma unroll
            for (int nt = 0; nt < 8; nt++) {
                o[nt][0] *= al0; o[nt][1] *= al0;
                o[nt][2] *= al1; o[nt][3] *= al1;
            }
        }
#pragma unroll
        for (int ks = 0; ks < 4; ks++) {
            int pi = (ks * 4 + wmv) * 32 + lane;
            uint4 ah4 = reinterpret_cast<const uint4*>(Phi)[pi];
            uint4 al4 = reinterpret_cast<const uint4*>(Plo)[pi];
#pragma unroll
            for (int ntl = 0; ntl < 8; ntl++) {
                int nt = wnv * 8 + ntl;
                int vi = (ks * 16 + nt) * 32 + lane;
                uint2 bh2 = reinterpret_cast<const uint2*>(Vhi)[vi];
                uint2 bl2 = reinterpret_cast<const uint2*>(Vlo)[vi];
                mma_bf16(o[ntl], reinterpret_cast<uint32_t*>(&ah4),
                         reinterpret_cast<uint32_t*>(&bh2));
                mma_bf16(o[ntl], reinterpret_cast<uint32_t*>(&ah4),
                         reinterpret_cast<uint32_t*>(&bl2));
                mma_bf16(o[ntl], reinterpret_cast<uint32_t*>(&al4),
                         reinterpret_cast<uint32_t*>(&bh2));
            }
        }
        __syncthreads();
    }

    // Epilogue: O /= l, write ctx
    {
        const int mbv = wmv * 16;
        const int nbv = wnv * 64;
        float li0 = 1.0f / lrow[mbv + g];
        float li1 = 1.0f / lrow[mbv + g + 8];
        int s0r = q0 + mbv + g;
        int s1r = s0r + 8;
#pragma unroll
        for (int nt = 0; nt < 8; nt++) {
            int col = h * DH + nbv + nt * 8 + 2 * cq;
            float2 w0 = make_float2(o[nt][0] * li0, o[nt][1] * li0);
            float2 w1 = make_float2(o[nt][2] * li1, o[nt][3] * li1);
            *reinterpret_cast<float2*>(&gctx[((size_t)s0r * B_SZ + b) * H_DIM + col]) = w0;
            *reinterpret_cast<float2*>(&gctx[((size_t)s1r * B_SZ + b) * H_DIM + col]) = w1;
        }
    }
}

extern "C" void kernel_launch(void* const* d_in, const int* in_sizes, int n_in,
                              void* d_out, int out_size)
{
    const float* hidden = (const float*)d_in[0];
    const unsigned char* mask = (const unsigned char*)d_in[1];
    const float* W_qkv = (const float*)d_in[2];
    const float* b_qkv = (const float*)d_in[3];
    const float* W_dense = (const float*)d_in[4];
    const float* b_dense = (const float*)d_in[5];
    float* out = (float*)d_out;

    float *qd = nullptr, *kd = nullptr, *vd = nullptr, *ctxd = nullptr;
    cudaGetSymbolAddress((void**)&qd,   g_q);
    cudaGetSymbolAddress((void**)&kd,   g_k);
    cudaGetSymbolAddress((void**)&vd,   g_v);
    cudaGetSymbolAddress((void**)&ctxd, g_ctx);

    cudaFuncSetAttribute(gemm_tc,
                         cudaFuncAttributeMaxDynamicSharedMemorySize,
                         GEMM_SMEM_BYTES);
    cudaFuncSetAttribute(attn_tc,
                         cudaFuncAttributeMaxDynamicSharedMemorySize,
                         ATT_SMEM_BYTES);

    const float* bdt = (out_size >= M_ROWS * H_DIM + H_DIM) ? b_dense : nullptr;

    // 1) QKV GEMM + scatter
    {
        dim3 grid(N3 / 128, M_ROWS / 128);
        gemm_tc<<<grid, 256, GEMM_SMEM_BYTES>>>(hidden, W_qkv, b_qkv, nullptr,
                                                qd, kd, vd, nullptr,
                                                M_ROWS, N3, H_DIM, 0);
    }
    // 2) Tensor-core flash attention
    {
        dim3 grid(S_LEN / 64, B_SZ * NH);
        attn_tc<<<grid, 256, ATT_SMEM_BYTES>>>(mask, qd, kd, vd, ctxd);
    }
    // 3) Dense GEMM -> out (+ folded b_dense tail)
    {
        dim3 grid(H_DIM / 128, M_ROWS / 128);
        gemm_tc<<<grid, 256, GEMM_SMEM_BYTES>>>(ctxd, W_dense, nullptr, out,
                                                nullptr, nullptr, nullptr, bdt,
                                                M_ROWS, H_DIM, H_DIM, 1);
    }
}

// round 7
// speedup vs baseline: 2.0631x; 2.0631x over previous
#include <cuda_runtime.h>
#include <cuda_bf16.h>
#include <math.h>
#include <stdint.h>

// Problem constants
#define S_LEN 2048
#define B_SZ  2
#define H_DIM 2048
#define NH    16
#define DH    128
#define N3    (3 * H_DIM)          // 6144
#define M_ROWS (S_LEN * B_SZ)      // 4096
#define HP    (H_DIM / 2)          // 1024 pair-words per row
#define MASK_VALUE (-10000.0f)

// fp32 scratch
__device__ float g_q[B_SZ * NH * S_LEN * DH];   // tf32-rounded values
__device__ float g_k[B_SZ * NH * S_LEN * DH];   // tf32-rounded values
__device__ float g_v[B_SZ * NH * S_LEN * DH];   // fp32
// pre-split bf16-pair words (pairs along k / seq, x0 in low half)
__device__ uint32_t g_ahi[M_ROWS * HP];         // hidden
__device__ uint32_t g_alo[M_ROWS * HP];
__device__ uint32_t g_wqhi[HP * N3];            // W_qkv  [k/2][n]
__device__ uint32_t g_wqlo[HP * N3];
__device__ uint32_t g_wdhi[HP * H_DIM];         // W_dense [k/2][n]
__device__ uint32_t g_wdlo[HP * H_DIM];
__device__ uint32_t g_chi[M_ROWS * HP];         // ctx (pairs along H)
__device__ uint32_t g_clo[M_ROWS * HP];
__device__ uint32_t g_vhi[B_SZ * NH * (S_LEN/2) * DH]; // v (pairs along s)
__device__ uint32_t g_vlo[B_SZ * NH * (S_LEN/2) * DH];

// ---------------------------------------------------------------------------
// helpers
// ---------------------------------------------------------------------------
__device__ __forceinline__ float to_tf32(float x)
{
    uint32_t u;
    asm("cvt.rna.tf32.f32 %0, %1;" : "=r"(u) : "f"(x));
    return __uint_as_float(u);
}

__device__ __forceinline__ void mma_tf32(float* c, const uint32_t* a, const uint32_t* b)
{
    asm volatile(
        "mma.sync.aligned.m16n8k8.row.col.f32.tf32.tf32.f32 "
        "{%0,%1,%2,%3}, {%4,%5,%6,%7}, {%8,%9}, {%0,%1,%2,%3};"
        : "+f"(c[0]), "+f"(c[1]), "+f"(c[2]), "+f"(c[3])
        : "r"(a[0]), "r"(a[1]), "r"(a[2]), "r"(a[3]),
          "r"(b[0]), "r"(b[1]));
}

__device__ __forceinline__ void mma_bf16(float* c, const uint32_t* a, const uint32_t* b)
{
    asm volatile(
        "mma.sync.aligned.m16n8k16.row.col.f32.bf16.bf16.f32 "
        "{%0,%1,%2,%3}, {%4,%5,%6,%7}, {%8,%9}, {%0,%1,%2,%3};"
        : "+f"(c[0]), "+f"(c[1]), "+f"(c[2]), "+f"(c[3])
        : "r"(a[0]), "r"(a[1]), "r"(a[2]), "r"(a[3]),
          "r"(b[0]), "r"(b[1]));
}

__device__ __forceinline__ void split2_pack(float x0, float x1,
                                            uint32_t& hi, uint32_t& lo)
{
    __nv_bfloat16 h0 = __float2bfloat16_rn(x0);
    __nv_bfloat16 h1 = __float2bfloat16_rn(x1);
    __nv_bfloat16 l0 = __float2bfloat16_rn(x0 - __bfloat162float(h0));
    __nv_bfloat16 l1 = __float2bfloat16_rn(x1 - __bfloat162float(h1));
    __nv_bfloat162 hp = __halves2bfloat162(h0, h1);
    __nv_bfloat162 lp = __halves2bfloat162(l0, l1);
    hi = *reinterpret_cast<uint32_t*>(&hp);
    lo = *reinterpret_cast<uint32_t*>(&lp);
}

// ---------------------------------------------------------------------------
// Pre-split kernels (run once per call; cheap, bandwidth-bound)
// ---------------------------------------------------------------------------
// Row-major [M][K]: pairs adjacent in memory. One float4 -> two words.
__global__ void presplit_rows(const float* __restrict__ src,
                              uint32_t* __restrict__ hi, uint32_t* __restrict__ lo,
                              long total_f4)
{
    long i = (long)blockIdx.x * blockDim.x + threadIdx.x;
    if (i >= total_f4) return;
    float4 v = reinterpret_cast<const float4*>(src)[i];
    uint32_t h0, l0, h1, l1;
    split2_pack(v.x, v.y, h0, l0);
    split2_pack(v.z, v.w, h1, l1);
    reinterpret_cast<uint2*>(hi)[i] = make_uint2(h0, h1);
    reinterpret_cast<uint2*>(lo)[i] = make_uint2(l0, l1);
}

// Column-pairing [K][N] -> [K/2][N]: word w pairs rows 2*pr and 2*pr+1 at col n.
__global__ void presplit_cols(const float* __restrict__ src,
                              uint32_t* __restrict__ hi, uint32_t* __restrict__ lo,
                              int N, long total_words)
{
    long w = (long)blockIdx.x * blockDim.x + threadIdx.x;
    if (w >= total_words) return;
    long pr = w / N;
    int  n  = (int)(w - pr * N);
    float a = src[(2 * pr) * (long)N + n];
    float b = src[(2 * pr + 1) * (long)N + n];
    uint32_t h, l;
    split2_pack(a, b, h, l);
    hi[w] = h; lo[w] = l;
}

// ---------------------------------------------------------------------------
// Tensor-core GEMM, 3x bf16 split, PRE-SPLIT operands (R5 smem layout).
// C[M,N] = A[M,K] @ B[K,N]. 128x128 tile, 256 thr, warp tile 64x32, BK=32.
// mode 0: QKV — bias, scatter q/k (tf32-rounded) + v (fp32). mode 1: store C.
// ---------------------------------------------------------------------------
#define APK_STRIDE 20
#define BPK_STRIDE 136

__global__ __launch_bounds__(256)
void gemm_tc(const uint32_t* __restrict__ Ahi_g, const uint32_t* __restrict__ Alo_g,
             const uint32_t* __restrict__ Bhi_g, const uint32_t* __restrict__ Blo_g,
             const float* __restrict__ bias, float* __restrict__ C,
             float* __restrict__ qd, float* __restrict__ kd, float* __restrict__ vd,
             const float* __restrict__ bdt,
             int M, int N, int K, int mode)
{
    __shared__ uint32_t Ahi[128][APK_STRIDE];
    __shared__ uint32_t Alo[128][APK_STRIDE];
    __shared__ uint32_t Bhi[16][BPK_STRIDE];
    __shared__ uint32_t Blo[16][BPK_STRIDE];

    const int tid  = threadIdx.x;
    const int lane = tid & 31;
    const int warp = tid >> 5;
    const int wm   = warp & 1;
    const int wn   = warp >> 1;
    const int g    = lane >> 2;
    const int cq   = lane & 3;

    const int m0 = blockIdx.y * 128;
    const int n0 = blockIdx.x * 128;
    const int Kp = K >> 1;

    float acc[4][4][4];
#pragma unroll
    for (int mt = 0; mt < 4; mt++)
#pragma unroll
        for (int nt = 0; nt < 4; nt++)
#pragma unroll
            for (int r = 0; r < 4; r++) acc[mt][nt][r] = 0.0f;

    const int arw = tid >> 3;              // 0..31 (+32 per pass)
    const int akp = (tid & 7) << 1;        // pair-word offset 0..14
    const int bpr = tid >> 5;              // pair-row 0..7 (+8 per pass)
    const int bnc = (tid & 31) << 2;       // n offset

    for (int k0p = 0; k0p < Kp; k0p += 16) {
#pragma unroll
        for (int p = 0; p < 4; p++) {
            int m = arw + p * 32;
            size_t ai = (size_t)(m0 + m) * Kp + k0p + akp;
            uint2 h = *reinterpret_cast<const uint2*>(&Ahi_g[ai]);
            uint2 l = *reinterpret_cast<const uint2*>(&Alo_g[ai]);
            *reinterpret_cast<uint2*>(&Ahi[m][akp]) = h;
            *reinterpret_cast<uint2*>(&Alo[m][akp]) = l;
        }
#pragma unroll
        for (int p = 0; p < 2; p++) {
            int pr = bpr + p * 8;
            size_t bi = (size_t)(k0p + pr) * N + n0 + bnc;
            uint4 h = *reinterpret_cast<const uint4*>(&Bhi_g[bi]);
            uint4 l = *reinterpret_cast<const uint4*>(&Blo_g[bi]);
            *reinterpret_cast<uint4*>(&Bhi[pr][bnc]) = h;
            *reinterpret_cast<uint4*>(&Blo[pr][bnc]) = l;
        }
        __syncthreads();

#pragma unroll
        for (int kk = 0; kk < 2; kk++) {   // two k16 steps
            const int kb = kk * 8;
            uint32_t ah[4][4], al[4][4];
#pragma unroll
            for (int mt = 0; mt < 4; mt++) {
                const int mb = wm * 64 + mt * 16;
                ah[mt][0] = Ahi[mb + g][kb + cq];
                ah[mt][1] = Ahi[mb + g + 8][kb + cq];
                ah[mt][2] = Ahi[mb + g][kb + cq + 4];
                ah[mt][3] = Ahi[mb + g + 8][kb + cq + 4];
                al[mt][0] = Alo[mb + g][kb + cq];
                al[mt][1] = Alo[mb + g + 8][kb + cq];
                al[mt][2] = Alo[mb + g][kb + cq + 4];
                al[mt][3] = Alo[mb + g + 8][kb + cq + 4];
            }
            uint32_t bh[4][2], bl[4][2];
#pragma unroll
            for (int nt = 0; nt < 4; nt++) {
                const int nb = wn * 32 + nt * 8;
                bh[nt][0] = Bhi[kb + cq][nb + g];
                bh[nt][1] = Bhi[kb + cq + 4][nb + g];
                bl[nt][0] = Blo[kb + cq][nb + g];
                bl[nt][1] = Blo[kb + cq + 4][nb + g];
            }
#pragma unroll
            for (int mt = 0; mt < 4; mt++)
#pragma unroll
                for (int nt = 0; nt < 4; nt++) {
                    mma_bf16(acc[mt][nt], ah[mt], bh[nt]);
                    mma_bf16(acc[mt][nt], ah[mt], bl[nt]);
                    mma_bf16(acc[mt][nt], al[mt], bh[nt]);
                }
        }
        __syncthreads();
    }

    if (mode == 0) {
#pragma unroll
        for (int mt = 0; mt < 4; mt++) {
#pragma unroll
            for (int nt = 0; nt < 4; nt++) {
#pragma unroll
                for (int r = 0; r < 4; r++) {
                    int m = m0 + wm * 64 + mt * 16 + g + ((r >> 1) << 3);
                    int n = n0 + wn * 32 + nt * 8 + 2 * cq + (r & 1);
                    float v = acc[mt][nt][r] + bias[n];
                    int b = m & 1;
                    int s = m >> 1;
                    int head = n / (3 * DH);
                    int rem  = n - head * (3 * DH);
                    int part = rem >> 7;
                    int d    = rem & 127;
                    size_t idx = (((size_t)(b * NH + head)) * S_LEN + s) * DH + d;
                    if (part == 0)      qd[idx] = to_tf32(v);
                    else if (part == 1) kd[idx] = to_tf32(v);
                    else                vd[idx] = v;
                }
            }
        }
    } else {
#pragma unroll
        for (int mt = 0; mt < 4; mt++) {
#pragma unroll
            for (int nt = 0; nt < 4; nt++) {
                int n = n0 + wn * 32 + nt * 8 + 2 * cq;
                int mA = m0 + wm * 64 + mt * 16 + g;
                int mB = mA + 8;
                float2 vA = make_float2(acc[mt][nt][0], acc[mt][nt][1]);
                float2 vB = make_float2(acc[mt][nt][2], acc[mt][nt][3]);
                *reinterpret_cast<float2*>(&C[(size_t)mA * N + n]) = vA;
                *reinterpret_cast<float2*>(&C[(size_t)mB * N + n]) = vB;
            }
        }
        // Fold tuple tail (b_dense)
        if (bdt && blockIdx.x == 0 && blockIdx.y == 0) {
            for (int i = tid; i < H_DIM; i += 256)
                C[(size_t)M_ROWS * H_DIM + i] = bdt[i];
        }
    }
}

// ---------------------------------------------------------------------------
// Tensor-core flash attention (R5 layout; loads are pure copies now).
// Block = 64 queries of one (b,h), 256 threads.
// QK^T: tf32 (q,k pre-rounded). P@V: 3-term bf16 split (V pre-split).
// Epilogue writes ctx directly as bf16 hi/lo pair words.
// ---------------------------------------------------------------------------
#define QS_STRIDE 132
#define VPK_STRIDE 136
#define PPK_STRIDE 36
#define SR_STRIDE 68
#define ATT_SMEM_BYTES ((64*QS_STRIDE*2 + 32*VPK_STRIDE*2 + 64*PPK_STRIDE*2 \
                         + 64*SR_STRIDE + 3*64) * 4)

__global__ __launch_bounds__(256)
void attn_tc(const unsigned char* __restrict__ mask,
             const float* __restrict__ gq, const float* __restrict__ gk,
             const uint32_t* __restrict__ gvhi, const uint32_t* __restrict__ gvlo,
             uint32_t* __restrict__ gchi, uint32_t* __restrict__ gclo)
{
    extern __shared__ float sm[];
    float*    Qs   = sm;                                   // 64 x 132
    float*    Ks   = Qs + 64 * QS_STRIDE;                  // 64 x 132
    uint32_t* Vhi  = reinterpret_cast<uint32_t*>(Ks + 64 * QS_STRIDE); // 32x136
    uint32_t* Vlo  = Vhi + 32 * VPK_STRIDE;
    uint32_t* Phi  = Vlo + 32 * VPK_STRIDE;                // 64 x 36
    uint32_t* Plo  = Phi + 64 * PPK_STRIDE;
    float*    Sraw = reinterpret_cast<float*>(Plo + 64 * PPK_STRIDE);  // 64x68
    float*    mrow = Sraw + 64 * SR_STRIDE;
    float*    lrow = mrow + 64;
    float*    arow = lrow + 64;

    const int tid  = threadIdx.x;
    const int lane = tid & 31;
    const int warp = tid >> 5;
    const int g    = lane >> 2;
    const int cq   = lane & 3;

    const int bh = blockIdx.y;
    const int b  = bh / NH;
    const int h  = bh - b * NH;
    const int q0 = blockIdx.x * 64;

    const float* qp = gq + (size_t)bh * S_LEN * DH;
    const float* kp = gk + (size_t)bh * S_LEN * DH;
    const uint32_t* vhp = gvhi + (size_t)bh * (S_LEN / 2) * DH;
    const uint32_t* vlp = gvlo + (size_t)bh * (S_LEN / 2) * DH;
    const unsigned char* mp = mask + (size_t)b * S_LEN * S_LEN;
    const float inv_norm = 1.0f / sqrtf((float)H_DIM);

    // Q tile: straight copy (already tf32-rounded)
    for (int e = tid; e < 64 * 32; e += 256) {
        int r = e >> 5;
        int c = (e & 31) << 2;
        float4 q4 = *reinterpret_cast<const float4*>(&qp[(size_t)(q0 + r) * DH + c]);
        *reinterpret_cast<float4*>(&Qs[r * QS_STRIDE + c]) = q4;
    }
    if (tid < 64) { mrow[tid] = -INFINITY; lrow[tid] = 0.0f; }
    __syncthreads();

    const int wmv = warp & 3;
    const int wnv = warp >> 2;
    float o[8][4];
#pragma unroll
    for (int nt = 0; nt < 8; nt++)
#pragma unroll
        for (int r = 0; r < 4; r++) o[nt][r] = 0.0f;

    const int wmq = warp & 3;
    const int wnq = warp >> 2;

    for (int kt = 0; kt < S_LEN / 64; kt++) {
        const int t0 = kt * 64;

        // K tile: straight copy
        for (int e = tid; e < 64 * 32; e += 256) {
            int r = e >> 5;
            int c = (e & 31) << 2;
            float4 k4 = *reinterpret_cast<const float4*>(&kp[(size_t)(t0 + r) * DH + c]);
            *reinterpret_cast<float4*>(&Ks[r * QS_STRIDE + c]) = k4;
        }
        // V tile: straight copy of pre-split pair words
        for (int e = tid; e < 32 * 32; e += 256) {
            int sp = e >> 5;
            int c  = (e & 31) << 2;
            size_t base = ((size_t)(t0 >> 1) + sp) * DH + c;
            uint4 h4 = *reinterpret_cast<const uint4*>(&vhp[base]);
            uint4 l4 = *reinterpret_cast<const uint4*>(&vlp[base]);
            *reinterpret_cast<uint4*>(&Vhi[sp * VPK_STRIDE + c]) = h4;
            *reinterpret_cast<uint4*>(&Vlo[sp * VPK_STRIDE + c]) = l4;
        }
        __syncthreads();

        // --- QK^T (tf32): S[64,64] ---
        float sacc[4][4];
#pragma unroll
        for (int nt = 0; nt < 4; nt++)
#pragma unroll
            for (int r = 0; r < 4; r++) sacc[nt][r] = 0.0f;

        const int mbq = wmq * 16;
        const int nbq = wnq * 32;
#pragma unroll
        for (int ks = 0; ks < 16; ks++) {
            const int kb = ks * 8;
            uint32_t a[4];
            a[0] = __float_as_uint(Qs[(mbq + g) * QS_STRIDE + kb + cq]);
            a[1] = __float_as_uint(Qs[(mbq + g + 8) * QS_STRIDE + kb + cq]);
            a[2] = __float_as_uint(Qs[(mbq + g) * QS_STRIDE + kb + cq + 4]);
            a[3] = __float_as_uint(Qs[(mbq + g + 8) * QS_STRIDE + kb + cq + 4]);
#pragma unroll
            for (int nt = 0; nt < 4; nt++) {
                const int nr = nbq + nt * 8 + g;
                uint32_t bfr[2];
                bfr[0] = __float_as_uint(Ks[nr * QS_STRIDE + kb + cq]);
                bfr[1] = __float_as_uint(Ks[nr * QS_STRIDE + kb + cq + 4]);
                mma_tf32(sacc[nt], a, bfr);
            }
        }
#pragma unroll
        for (int nt = 0; nt < 4; nt++) {
#pragma unroll
            for (int r = 0; r < 4; r++) {
                int rr = mbq + g + ((r >> 1) << 3);
                int cc = nbq + nt * 8 + 2 * cq + (r & 1);
                Sraw[rr * SR_STRIDE + cc] = sacc[nt][r];
            }
        }
        __syncthreads();

        // --- softmax: 4 threads per row; pack P hi/lo pairs along seq ---
        {
            const int row = tid >> 2;
            const int sub = tid & 3;
            const int cb  = sub * 16;
            float* srow = &Sraw[row * SR_STRIDE + cb];
            uint32_t* ph = &Phi[row * PPK_STRIDE + sub * 8];
            uint32_t* pl = &Plo[row * PPK_STRIDE + sub * 8];
            const unsigned char* mr = mp + (size_t)(q0 + row) * S_LEN + t0 + cb;

            float v[16];
            float rmax = -INFINITY;
#pragma unroll
            for (int i = 0; i < 16; i += 4) {
                uchar4 mk = *reinterpret_cast<const uchar4*>(mr + i);
                float s0 = srow[i + 0] * inv_norm; if (mk.x) s0 = MASK_VALUE;
                float s1 = srow[i + 1] * inv_norm; if (mk.y) s1 = MASK_VALUE;
                float s2 = srow[i + 2] * inv_norm; if (mk.z) s2 = MASK_VALUE;
                float s3 = srow[i + 3] * inv_norm; if (mk.w) s3 = MASK_VALUE;
                v[i + 0] = s0; v[i + 1] = s1; v[i + 2] = s2; v[i + 3] = s3;
                rmax = fmaxf(rmax, fmaxf(fmaxf(s0, s1), fmaxf(s2, s3)));
            }
            rmax = fmaxf(rmax, __shfl_xor_sync(0xffffffffu, rmax, 1));
            rmax = fmaxf(rmax, __shfl_xor_sync(0xffffffffu, rmax, 2));
            float m_old = mrow[row];
            float m_new = fmaxf(m_old, rmax);
            float alpha = __expf(m_old - m_new);
            float sum = 0.0f;
#pragma unroll
            for (int i = 0; i < 16; i += 2) {
                float p0 = __expf(v[i + 0] - m_new);
                float p1 = __expf(v[i + 1] - m_new);
                sum += p0 + p1;
                uint32_t hh, ll;
                split2_pack(p0, p1, hh, ll);
                ph[i >> 1] = hh;
                pl[i >> 1] = ll;
            }
            sum += __shfl_xor_sync(0xffffffffu, sum, 1);
            sum += __shfl_xor_sync(0xffffffffu, sum, 2);
            if (sub == 0) {
                lrow[row] = lrow[row] * alpha + sum;
                mrow[row] = m_new;
                arow[row] = alpha;
            }
        }
        __syncthreads();

        // --- rescale O, then P@V (bf16 3-split, 4 k16 steps) ---
        const int mbv = wmv * 16;
        const int nbv = wnv * 64;
        {
            float al0 = arow[mbv + g];
            float al1 = arow[mbv + g + 8];
#pragma unroll
            for (int nt = 0; nt < 8; nt++) {
                o[nt][0] *= al0; o[nt][1] *= al0;
                o[nt][2] *= al1; o[nt][3] *= al1;
            }
        }
#pragma unroll
        for (int ks = 0; ks < 4; ks++) {
            const int kb = ks * 8;
            uint32_t ah[4], al_[4];
            ah[0]  = Phi[(mbv + g) * PPK_STRIDE + kb + cq];
            ah[1]  = Phi[(mbv + g + 8) * PPK_STRIDE + kb + cq];
            ah[2]  = Phi[(mbv + g) * PPK_STRIDE + kb + cq + 4];
            ah[3]  = Phi[(mbv + g + 8) * PPK_STRIDE + kb + cq + 4];
            al_[0] = Plo[(mbv + g) * PPK_STRIDE + kb + cq];
            al_[1] = Plo[(mbv + g + 8) * PPK_STRIDE + kb + cq];
            al_[2] = Plo[(mbv + g) * PPK_STRIDE + kb + cq + 4];
            al_[3] = Plo[(mbv + g + 8) * PPK_STRIDE + kb + cq + 4];
#pragma unroll
            for (int nt = 0; nt < 8; nt++) {
                const int nc = nbv + nt * 8 + g;
                uint32_t bhv[2], blv[2];
                bhv[0] = Vhi[(kb + cq) * VPK_STRIDE + nc];
                bhv[1] = Vhi[(kb + cq + 4) * VPK_STRIDE + nc];
                blv[0] = Vlo[(kb + cq) * VPK_STRIDE + nc];
                blv[1] = Vlo[(kb + cq + 4) * VPK_STRIDE + nc];
                mma_bf16(o[nt], ah, bhv);
                mma_bf16(o[nt], ah, blv);
                mma_bf16(o[nt], al_, bhv);
            }
        }
        __syncthreads();
    }

    // Epilogue: O /= l, write ctx as bf16 hi/lo pair words (pairs along H)
    {
        const int mbv = wmv * 16;
        const int nbv = wnv * 64;
        float li0 = 1.0f / lrow[mbv + g];
        float li1 = 1.0f / lrow[mbv + g + 8];
        int s0r = q0 + mbv + g;
        int s1r = s0r + 8;
#pragma unroll
        for (int nt = 0; nt < 8; nt++) {
            int colw = (h * DH + nbv + nt * 8) / 2 + cq;   // pair-word index
            uint32_t hw0, lw0, hw1, lw1;
            split2_pack(o[nt][0] * li0, o[nt][1] * li0, hw0, lw0);
            split2_pack(o[nt][2] * li1, o[nt][3] * li1, hw1, lw1);
            size_t r0 = ((size_t)s0r * B_SZ + b) * HP + colw;
            size_t r1 = ((size_t)s1r * B_SZ + b) * HP + colw;
            gchi[r0] = hw0; gclo[r0] = lw0;
            gchi[r1] = hw1; gclo[r1] = lw1;
        }
    }
}

extern "C" void kernel_launch(void* const* d_in, const int* in_sizes, int n_in,
                              void* d_out, int out_size)
{
    const float* hidden = (const float*)d_in[0];
    const unsigned char* mask = (const unsigned char*)d_in[1];
    const float* W_qkv = (const float*)d_in[2];
    const float* b_qkv = (const float*)d_in[3];
    const float* W_dense = (const float*)d_in[4];
    const float* b_dense = (const float*)d_in[5];
    float* out = (float*)d_out;

    float *qd, *kd, *vd;
    uint32_t *ahi, *alo, *wqhi, *wqlo, *wdhi, *wdlo, *chi, *clo, *vhi, *vlo;
    cudaGetSymbolAddress((void**)&qd,   g_q);
    cudaGetSymbolAddress((void**)&kd,   g_k);
    cudaGetSymbolAddress((void**)&vd,   g_v);
    cudaGetSymbolAddress((void**)&ahi,  g_ahi);
    cudaGetSymbolAddress((void**)&alo,  g_alo);
    cudaGetSymbolAddress((void**)&wqhi, g_wqhi);
    cudaGetSymbolAddress((void**)&wqlo, g_wqlo);
    cudaGetSymbolAddress((void**)&wdhi, g_wdhi);
    cudaGetSymbolAddress((void**)&wdlo, g_wdlo);
    cudaGetSymbolAddress((void**)&chi,  g_chi);
    cudaGetSymbolAddress((void**)&clo,  g_clo);
    cudaGetSymbolAddress((void**)&vhi,  g_vhi);
    cudaGetSymbolAddress((void**)&vlo,  g_vlo);

    cudaFuncSetAttribute(attn_tc,
                         cudaFuncAttributeMaxDynamicSharedMemorySize,
                         ATT_SMEM_BYTES);

    const float* bdt = (out_size >= M_ROWS * H_DIM + H_DIM) ? b_dense : nullptr;

    // 0) Pre-split inputs
    {
        long f4 = (long)M_ROWS * H_DIM / 4;
        presplit_rows<<<(unsigned)((f4 + 255) / 256), 256>>>(hidden, ahi, alo, f4);
        long wq = (long)HP * N3;
        presplit_cols<<<(unsigned)((wq + 255) / 256), 256>>>(W_qkv, wqhi, wqlo, N3, wq);
        long wd = (long)HP * H_DIM;
        presplit_cols<<<(unsigned)((wd + 255) / 256), 256>>>(W_dense, wdhi, wdlo, H_DIM, wd);
    }
    // 1) QKV GEMM + scatter (q,k tf32-rounded; v fp32)
    {
        dim3 grid(N3 / 128, M_ROWS / 128);
        gemm_tc<<<grid, 256>>>(ahi, alo, wqhi, wqlo, b_qkv, nullptr,
                               qd, kd, vd, nullptr, M_ROWS, N3, H_DIM, 0);
    }
    // 1b) Pre-split V (pairs along seq)
    {
        long vw = (long)B_SZ * NH * (S_LEN / 2) * DH;
        presplit_cols<<<(unsigned)((vw + 255) / 256), 256>>>(vd, vhi, vlo, DH, vw);
    }
    // 2) Flash attention (writes ctx hi/lo)
    {
        dim3 grid(S_LEN / 64, B_SZ * NH);
        attn_tc<<<grid, 256, ATT_SMEM_BYTES>>>(mask, qd, kd, vhi, vlo, chi, clo);
    }
    // 3) Dense GEMM -> out (+ folded b_dense tail)
    {
        dim3 grid(H_DIM / 128, M_ROWS / 128);
        gemm_tc<<<grid, 256>>>(chi, clo, wdhi, wdlo, nullptr, out,
                               nullptr, nullptr, nullptr, bdt,
                               M_ROWS, H_DIM, H_DIM, 1);
    }
}

// round 8
// speedup vs baseline: 2.1075x; 1.0215x over previous
#include <cuda_runtime.h>
#include <cuda_bf16.h>
#include <math.h>
#include <stdint.h>

// Problem constants
#define S_LEN 2048
#define B_SZ  2
#define H_DIM 2048
#define NH    16
#define DH    128
#define N3    (3 * H_DIM)          // 6144
#define M_ROWS (S_LEN * B_SZ)      // 4096
#define HP    (H_DIM / 2)          // 1024 pair-words per row
#define MASK_VALUE (-10000.0f)

// fp32 scratch
__device__ float g_q[B_SZ * NH * S_LEN * DH];   // tf32-rounded values
__device__ float g_k[B_SZ * NH * S_LEN * DH];   // tf32-rounded values
__device__ float g_v[B_SZ * NH * S_LEN * DH];   // fp32
// pre-split bf16-pair words (pairs along k / seq, x0 in low half)
__device__ uint32_t g_ahi[M_ROWS * HP];         // hidden
__device__ uint32_t g_alo[M_ROWS * HP];
__device__ uint32_t g_wqhi[HP * N3];            // W_qkv  [k/2][n]
__device__ uint32_t g_wqlo[HP * N3];
__device__ uint32_t g_wdhi[HP * H_DIM];         // W_dense [k/2][n]
__device__ uint32_t g_wdlo[HP * H_DIM];
__device__ uint32_t g_chi[M_ROWS * HP];         // ctx (pairs along H)
__device__ uint32_t g_clo[M_ROWS * HP];
__device__ uint32_t g_vhi[B_SZ * NH * (S_LEN/2) * DH]; // v (pairs along s)
__device__ uint32_t g_vlo[B_SZ * NH * (S_LEN/2) * DH];

// ---------------------------------------------------------------------------
// helpers
// ---------------------------------------------------------------------------
__device__ __forceinline__ float to_tf32(float x)
{
    uint32_t u;
    asm("cvt.rna.tf32.f32 %0, %1;" : "=r"(u) : "f"(x));
    return __uint_as_float(u);
}

__device__ __forceinline__ void mma_tf32(float* c, const uint32_t* a, const uint32_t* b)
{
    asm volatile(
        "mma.sync.aligned.m16n8k8.row.col.f32.tf32.tf32.f32 "
        "{%0,%1,%2,%3}, {%4,%5,%6,%7}, {%8,%9}, {%0,%1,%2,%3};"
        : "+f"(c[0]), "+f"(c[1]), "+f"(c[2]), "+f"(c[3])
        : "r"(a[0]), "r"(a[1]), "r"(a[2]), "r"(a[3]),
          "r"(b[0]), "r"(b[1]));
}

__device__ __forceinline__ void mma_bf16(float* c, const uint32_t* a, const uint32_t* b)
{
    asm volatile(
        "mma.sync.aligned.m16n8k16.row.col.f32.bf16.bf16.f32 "
        "{%0,%1,%2,%3}, {%4,%5,%6,%7}, {%8,%9}, {%0,%1,%2,%3};"
        : "+f"(c[0]), "+f"(c[1]), "+f"(c[2]), "+f"(c[3])
        : "r"(a[0]), "r"(a[1]), "r"(a[2]), "r"(a[3]),
          "r"(b[0]), "r"(b[1]));
}

__device__ __forceinline__ void split2_pack(float x0, float x1,
                                            uint32_t& hi, uint32_t& lo)
{
    __nv_bfloat16 h0 = __float2bfloat16_rn(x0);
    __nv_bfloat16 h1 = __float2bfloat16_rn(x1);
    __nv_bfloat16 l0 = __float2bfloat16_rn(x0 - __bfloat162float(h0));
    __nv_bfloat16 l1 = __float2bfloat16_rn(x1 - __bfloat162float(h1));
    __nv_bfloat162 hp = __halves2bfloat162(h0, h1);
    __nv_bfloat162 lp = __halves2bfloat162(l0, l1);
    hi = *reinterpret_cast<uint32_t*>(&hp);
    lo = *reinterpret_cast<uint32_t*>(&lp);
}

// ---------------------------------------------------------------------------
// Pre-split kernels
// ---------------------------------------------------------------------------
__global__ void presplit_rows(const float* __restrict__ src,
                              uint32_t* __restrict__ hi, uint32_t* __restrict__ lo,
                              long total_f4)
{
    long i = (long)blockIdx.x * blockDim.x + threadIdx.x;
    if (i >= total_f4) return;
    float4 v = reinterpret_cast<const float4*>(src)[i];
    uint32_t h0, l0, h1, l1;
    split2_pack(v.x, v.y, h0, l0);
    split2_pack(v.z, v.w, h1, l1);
    reinterpret_cast<uint2*>(hi)[i] = make_uint2(h0, h1);
    reinterpret_cast<uint2*>(lo)[i] = make_uint2(l0, l1);
}

__global__ void presplit_cols(const float* __restrict__ src,
                              uint32_t* __restrict__ hi, uint32_t* __restrict__ lo,
                              int N, long total_words)
{
    long w = (long)blockIdx.x * blockDim.x + threadIdx.x;
    if (w >= total_words) return;
    long pr = w / N;
    int  n  = (int)(w - pr * N);
    float a = src[(2 * pr) * (long)N + n];
    float b = src[(2 * pr + 1) * (long)N + n];
    uint32_t h, l;
    split2_pack(a, b, h, l);
    hi[w] = h; lo[w] = l;
}

// ---------------------------------------------------------------------------
// Tensor-core GEMM (unchanged from R7): 3x bf16 split, pre-split operands.
// ---------------------------------------------------------------------------
#define APK_STRIDE 20
#define BPK_STRIDE 136

__global__ __launch_bounds__(256)
void gemm_tc(const uint32_t* __restrict__ Ahi_g, const uint32_t* __restrict__ Alo_g,
             const uint32_t* __restrict__ Bhi_g, const uint32_t* __restrict__ Blo_g,
             const float* __restrict__ bias, float* __restrict__ C,
             float* __restrict__ qd, float* __restrict__ kd, float* __restrict__ vd,
             const float* __restrict__ bdt,
             int M, int N, int K, int mode)
{
    __shared__ uint32_t Ahi[128][APK_STRIDE];
    __shared__ uint32_t Alo[128][APK_STRIDE];
    __shared__ uint32_t Bhi[16][BPK_STRIDE];
    __shared__ uint32_t Blo[16][BPK_STRIDE];

    const int tid  = threadIdx.x;
    const int lane = tid & 31;
    const int warp = tid >> 5;
    const int wm   = warp & 1;
    const int wn   = warp >> 1;
    const int g    = lane >> 2;
    const int cq   = lane & 3;

    const int m0 = blockIdx.y * 128;
    const int n0 = blockIdx.x * 128;
    const int Kp = K >> 1;

    float acc[4][4][4];
#pragma unroll
    for (int mt = 0; mt < 4; mt++)
#pragma unroll
        for (int nt = 0; nt < 4; nt++)
#pragma unroll
            for (int r = 0; r < 4; r++) acc[mt][nt][r] = 0.0f;

    const int arw = tid >> 3;
    const int akp = (tid & 7) << 1;
    const int bpr = tid >> 5;
    const int bnc = (tid & 31) << 2;

    for (int k0p = 0; k0p < Kp; k0p += 16) {
#pragma unroll
        for (int p = 0; p < 4; p++) {
            int m = arw + p * 32;
            size_t ai = (size_t)(m0 + m) * Kp + k0p + akp;
            uint2 h = *reinterpret_cast<const uint2*>(&Ahi_g[ai]);
            uint2 l = *reinterpret_cast<const uint2*>(&Alo_g[ai]);
            *reinterpret_cast<uint2*>(&Ahi[m][akp]) = h;
            *reinterpret_cast<uint2*>(&Alo[m][akp]) = l;
        }
#pragma unroll
        for (int p = 0; p < 2; p++) {
            int pr = bpr + p * 8;
            size_t bi = (size_t)(k0p + pr) * N + n0 + bnc;
            uint4 h = *reinterpret_cast<const uint4*>(&Bhi_g[bi]);
            uint4 l = *reinterpret_cast<const uint4*>(&Blo_g[bi]);
            *reinterpret_cast<uint4*>(&Bhi[pr][bnc]) = h;
            *reinterpret_cast<uint4*>(&Blo[pr][bnc]) = l;
        }
        __syncthreads();

#pragma unroll
        for (int kk = 0; kk < 2; kk++) {
            const int kb = kk * 8;
            uint32_t ah[4][4], al[4][4];
#pragma unroll
            for (int mt = 0; mt < 4; mt++) {
                const int mb = wm * 64 + mt * 16;
                ah[mt][0] = Ahi[mb + g][kb + cq];
                ah[mt][1] = Ahi[mb + g + 8][kb + cq];
                ah[mt][2] = Ahi[mb + g][kb + cq + 4];
                ah[mt][3] = Ahi[mb + g + 8][kb + cq + 4];
                al[mt][0] = Alo[mb + g][kb + cq];
                al[mt][1] = Alo[mb + g + 8][kb + cq];
                al[mt][2] = Alo[mb + g][kb + cq + 4];
                al[mt][3] = Alo[mb + g + 8][kb + cq + 4];
            }
            uint32_t bh[4][2], bl[4][2];
#pragma unroll
            for (int nt = 0; nt < 4; nt++) {
                const int nb = wn * 32 + nt * 8;
                bh[nt][0] = Bhi[kb + cq][nb + g];
                bh[nt][1] = Bhi[kb + cq + 4][nb + g];
                bl[nt][0] = Blo[kb + cq][nb + g];
                bl[nt][1] = Blo[kb + cq + 4][nb + g];
            }
#pragma unroll
            for (int mt = 0; mt < 4; mt++)
#pragma unroll
                for (int nt = 0; nt < 4; nt++) {
                    mma_bf16(acc[mt][nt], ah[mt], bh[nt]);
                    mma_bf16(acc[mt][nt], ah[mt], bl[nt]);
                    mma_bf16(acc[mt][nt], al[mt], bh[nt]);
                }
        }
        __syncthreads();
    }

    if (mode == 0) {
#pragma unroll
        for (int mt = 0; mt < 4; mt++) {
#pragma unroll
            for (int nt = 0; nt < 4; nt++) {
#pragma unroll
                for (int r = 0; r < 4; r++) {
                    int m = m0 + wm * 64 + mt * 16 + g + ((r >> 1) << 3);
                    int n = n0 + wn * 32 + nt * 8 + 2 * cq + (r & 1);
                    float v = acc[mt][nt][r] + bias[n];
                    int b = m & 1;
                    int s = m >> 1;
                    int head = n / (3 * DH);
                    int rem  = n - head * (3 * DH);
                    int part = rem >> 7;
                    int d    = rem & 127;
                    size_t idx = (((size_t)(b * NH + head)) * S_LEN + s) * DH + d;
                    if (part == 0)      qd[idx] = to_tf32(v);
                    else if (part == 1) kd[idx] = to_tf32(v);
                    else                vd[idx] = v;
                }
            }
        }
    } else {
#pragma unroll
        for (int mt = 0; mt < 4; mt++) {
#pragma unroll
            for (int nt = 0; nt < 4; nt++) {
                int n = n0 + wn * 32 + nt * 8 + 2 * cq;
                int mA = m0 + wm * 64 + mt * 16 + g;
                int mB = mA + 8;
                float2 vA = make_float2(acc[mt][nt][0], acc[mt][nt][1]);
                float2 vB = make_float2(acc[mt][nt][2], acc[mt][nt][3]);
                *reinterpret_cast<float2*>(&C[(size_t)mA * N + n]) = vA;
                *reinterpret_cast<float2*>(&C[(size_t)mB * N + n]) = vB;
            }
        }
        if (bdt && blockIdx.x == 0 && blockIdx.y == 0) {
            for (int i = tid; i < H_DIM; i += 256)
                C[(size_t)M_ROWS * H_DIM + i] = bdt[i];
        }
    }
}

// ---------------------------------------------------------------------------
// Tensor-core flash attention — 512 threads (16 warps) for latency hiding.
// Block = 64 queries of one (b,h). QK: tf32, warp tile m16n16 (4x4 warps).
// P@V: bf16 3-split, warp tile m16n32 (4m x 4n). Softmax: 8 threads/row.
// ---------------------------------------------------------------------------
#define QS_STRIDE 132
#define VPK_STRIDE 136
#define PPK_STRIDE 36
#define SR_STRIDE 68
#define ATT_THREADS 512
#define ATT_SMEM_BYTES ((64*QS_STRIDE*2 + 32*VPK_STRIDE*2 + 64*PPK_STRIDE*2 \
                         + 64*SR_STRIDE + 3*64) * 4)

__global__ __launch_bounds__(ATT_THREADS)
void attn_tc(const unsigned char* __restrict__ mask,
             const float* __restrict__ gq, const float* __restrict__ gk,
             const uint32_t* __restrict__ gvhi, const uint32_t* __restrict__ gvlo,
             uint32_t* __restrict__ gchi, uint32_t* __restrict__ gclo)
{
    extern __shared__ float sm[];
    float*    Qs   = sm;                                   // 64 x 132
    float*    Ks   = Qs + 64 * QS_STRIDE;                  // 64 x 132
    uint32_t* Vhi  = reinterpret_cast<uint32_t*>(Ks + 64 * QS_STRIDE); // 32x136
    uint32_t* Vlo  = Vhi + 32 * VPK_STRIDE;
    uint32_t* Phi  = Vlo + 32 * VPK_STRIDE;                // 64 x 36
    uint32_t* Plo  = Phi + 64 * PPK_STRIDE;
    float*    Sraw = reinterpret_cast<float*>(Plo + 64 * PPK_STRIDE);  // 64x68
    float*    mrow = Sraw + 64 * SR_STRIDE;
    float*    lrow = mrow + 64;
    float*    arow = lrow + 64;

    const int tid  = threadIdx.x;
    const int lane = tid & 31;
    const int warp = tid >> 5;          // 0..15
    const int g    = lane >> 2;
    const int cq   = lane & 3;

    const int bh = blockIdx.y;
    const int b  = bh / NH;
    const int h  = bh - b * NH;
    const int q0 = blockIdx.x * 64;

    const float* qp = gq + (size_t)bh * S_LEN * DH;
    const float* kp = gk + (size_t)bh * S_LEN * DH;
    const uint32_t* vhp = gvhi + (size_t)bh * (S_LEN / 2) * DH;
    const uint32_t* vlp = gvlo + (size_t)bh * (S_LEN / 2) * DH;
    const unsigned char* mp = mask + (size_t)b * S_LEN * S_LEN;
    const float inv_norm = 1.0f / sqrtf((float)H_DIM);

    // Q tile: straight copy (already tf32-rounded)
    for (int e = tid; e < 64 * 32; e += ATT_THREADS) {
        int r = e >> 5;
        int c = (e & 31) << 2;
        float4 q4 = *reinterpret_cast<const float4*>(&qp[(size_t)(q0 + r) * DH + c]);
        *reinterpret_cast<float4*>(&Qs[r * QS_STRIDE + c]) = q4;
    }
    if (tid < 64) { mrow[tid] = -INFINITY; lrow[tid] = 0.0f; }
    __syncthreads();

    // QK tiling: m16n16 per warp. PV tiling: m16n32 per warp.
    const int wmq = warp & 3;           // m-slab (16 rows)
    const int wnq = warp >> 2;          // n-slab (16 cols)
    const int wmv = warp & 3;           // PV m-slab
    const int wnv = warp >> 2;          // PV n-slab (32 cols)

    float o[4][4];
#pragma unroll
    for (int nt = 0; nt < 4; nt++)
#pragma unroll
        for (int r = 0; r < 4; r++) o[nt][r] = 0.0f;

    for (int kt = 0; kt < S_LEN / 64; kt++) {
        const int t0 = kt * 64;

        // K tile: straight copy
        for (int e = tid; e < 64 * 32; e += ATT_THREADS) {
            int r = e >> 5;
            int c = (e & 31) << 2;
            float4 k4 = *reinterpret_cast<const float4*>(&kp[(size_t)(t0 + r) * DH + c]);
            *reinterpret_cast<float4*>(&Ks[r * QS_STRIDE + c]) = k4;
        }
        // V tile: straight copy of pre-split pair words
        for (int e = tid; e < 32 * 32; e += ATT_THREADS) {
            int sp = e >> 5;
            int c  = (e & 31) << 2;
            size_t base = ((size_t)(t0 >> 1) + sp) * DH + c;
            uint4 h4 = *reinterpret_cast<const uint4*>(&vhp[base]);
            uint4 l4 = *reinterpret_cast<const uint4*>(&vlp[base]);
            *reinterpret_cast<uint4*>(&Vhi[sp * VPK_STRIDE + c]) = h4;
            *reinterpret_cast<uint4*>(&Vlo[sp * VPK_STRIDE + c]) = l4;
        }
        __syncthreads();

        // --- QK^T (tf32): warp computes m16 x n16 of S[64,64] ---
        float sacc[2][4];
#pragma unroll
        for (int nt = 0; nt < 2; nt++)
#pragma unroll
            for (int r = 0; r < 4; r++) sacc[nt][r] = 0.0f;

        const int mbq = wmq * 16;
        const int nbq = wnq * 16;
#pragma unroll
        for (int ks = 0; ks < 16; ks++) {
            const int kb = ks * 8;
            uint32_t a[4];
            a[0] = __float_as_uint(Qs[(mbq + g) * QS_STRIDE + kb + cq]);
            a[1] = __float_as_uint(Qs[(mbq + g + 8) * QS_STRIDE + kb + cq]);
            a[2] = __float_as_uint(Qs[(mbq + g) * QS_STRIDE + kb + cq + 4]);
            a[3] = __float_as_uint(Qs[(mbq + g + 8) * QS_STRIDE + kb + cq + 4]);
#pragma unroll
            for (int nt = 0; nt < 2; nt++) {
                const int nr = nbq + nt * 8 + g;
                uint32_t bfr[2];
                bfr[0] = __float_as_uint(Ks[nr * QS_STRIDE + kb + cq]);
                bfr[1] = __float_as_uint(Ks[nr * QS_STRIDE + kb + cq + 4]);
                mma_tf32(sacc[nt], a, bfr);
            }
        }
#pragma unroll
        for (int nt = 0; nt < 2; nt++) {
#pragma unroll
            for (int r = 0; r < 4; r++) {
                int rr = mbq + g + ((r >> 1) << 3);
                int cc = nbq + nt * 8 + 2 * cq + (r & 1);
                Sraw[rr * SR_STRIDE + cc] = sacc[nt][r];
            }
        }
        __syncthreads();

        // --- softmax: 8 threads per row (512 thr / 64 rows) ---
        {
            const int row = tid >> 3;
            const int sub = tid & 7;
            const int cb  = sub * 8;
            float* srow = &Sraw[row * SR_STRIDE + cb];
            uint32_t* ph = &Phi[row * PPK_STRIDE + sub * 4];
            uint32_t* pl = &Plo[row * PPK_STRIDE + sub * 4];
            const unsigned char* mr = mp + (size_t)(q0 + row) * S_LEN + t0 + cb;

            float v[8];
            float rmax = -INFINITY;
#pragma unroll
            for (int i = 0; i < 8; i += 4) {
                uchar4 mk = *reinterpret_cast<const uchar4*>(mr + i);
                float s0 = srow[i + 0] * inv_norm; if (mk.x) s0 = MASK_VALUE;
                float s1 = srow[i + 1] * inv_norm; if (mk.y) s1 = MASK_VALUE;
                float s2 = srow[i + 2] * inv_norm; if (mk.z) s2 = MASK_VALUE;
                float s3 = srow[i + 3] * inv_norm; if (mk.w) s3 = MASK_VALUE;
                v[i + 0] = s0; v[i + 1] = s1; v[i + 2] = s2; v[i + 3] = s3;
                rmax = fmaxf(rmax, fmaxf(fmaxf(s0, s1), fmaxf(s2, s3)));
            }
            rmax = fmaxf(rmax, __shfl_xor_sync(0xffffffffu, rmax, 1));
            rmax = fmaxf(rmax, __shfl_xor_sync(0xffffffffu, rmax, 2));
            rmax = fmaxf(rmax, __shfl_xor_sync(0xffffffffu, rmax, 4));
            float m_old = mrow[row];
            float m_new = fmaxf(m_old, rmax);
            float alpha = __expf(m_old - m_new);
            float sum = 0.0f;
#pragma unroll
            for (int i = 0; i < 8; i += 2) {
                float p0 = __expf(v[i + 0] - m_new);
                float p1 = __expf(v[i + 1] - m_new);
                sum += p0 + p1;
                uint32_t hh, ll;
                split2_pack(p0, p1, hh, ll);
                ph[i >> 1] = hh;
                pl[i >> 1] = ll;
            }
            sum += __shfl_xor_sync(0xffffffffu, sum, 1);
            sum += __shfl_xor_sync(0xffffffffu, sum, 2);
            sum += __shfl_xor_sync(0xffffffffu, sum, 4);
            if (sub == 0) {
                lrow[row] = lrow[row] * alpha + sum;
                mrow[row] = m_new;
                arow[row] = alpha;
            }
        }
        __syncthreads();

        // --- rescale O, then P@V (bf16 3-split): warp m16 x n32 ---
        const int mbv = wmv * 16;
        const int nbv = wnv * 32;
        {
            float al0 = arow[mbv + g];
            float al1 = arow[mbv + g + 8];
#pragma unroll
            for (int nt = 0; nt < 4; nt++) {
                o[nt][0] *= al0; o[nt][1] *= al0;
                o[nt][2] *= al1; o[nt][3] *= al1;
            }
        }
#pragma unroll
        for (int ks = 0; ks < 4; ks++) {
            const int kb = ks * 8;
            uint32_t ah[4], al_[4];
            ah[0]  = Phi[(mbv + g) * PPK_STRIDE + kb + cq];
            ah[1]  = Phi[(mbv + g + 8) * PPK_STRIDE + kb + cq];
            ah[2]  = Phi[(mbv + g) * PPK_STRIDE + kb + cq + 4];
            ah[3]  = Phi[(mbv + g + 8) * PPK_STRIDE + kb + cq + 4];
            al_[0] = Plo[(mbv + g) * PPK_STRIDE + kb + cq];
            al_[1] = Plo[(mbv + g + 8) * PPK_STRIDE + kb + cq];
            al_[2] = Plo[(mbv + g) * PPK_STRIDE + kb + cq + 4];
            al_[3] = Plo[(mbv + g + 8) * PPK_STRIDE + kb + cq + 4];
#pragma unroll
            for (int nt = 0; nt < 4; nt++) {
                const int nc = nbv + nt * 8 + g;
                uint32_t bhv[2], blv[2];
                bhv[0] = Vhi[(kb + cq) * VPK_STRIDE + nc];
                bhv[1] = Vhi[(kb + cq + 4) * VPK_STRIDE + nc];
                blv[0] = Vlo[(kb + cq) * VPK_STRIDE + nc];
                blv[1] = Vlo[(kb + cq + 4) * VPK_STRIDE + nc];
                mma_bf16(o[nt], ah, bhv);
                mma_bf16(o[nt], ah, blv);
                mma_bf16(o[nt], al_, bhv);
            }
        }
        __syncthreads();
    }

    // Epilogue: O /= l, write ctx as bf16 hi/lo pair words (pairs along H)
    {
        const int mbv = wmv * 16;
        const int nbv = wnv * 32;
        float li0 = 1.0f / lrow[mbv + g];
        float li1 = 1.0f / lrow[mbv + g + 8];
        int s0r = q0 + mbv + g;
        int s1r = s0r + 8;
#pragma unroll
        for (int nt = 0; nt < 4; nt++) {
            int colw = (h * DH + nbv + nt * 8) / 2 + cq;
            uint32_t hw0, lw0, hw1, lw1;
            split2_pack(o[nt][0] * li0, o[nt][1] * li0, hw0, lw0);
            split2_pack(o[nt][2] * li1, o[nt][3] * li1, hw1, lw1);
            size_t r0 = ((size_t)s0r * B_SZ + b) * HP + colw;
            size_t r1 = ((size_t)s1r * B_SZ + b) * HP + colw;
            gchi[r0] = hw0; gclo[r0] = lw0;
            gchi[r1] = hw1; gclo[r1] = lw1;
        }
    }
}

extern "C" void kernel_launch(void* const* d_in, const int* in_sizes, int n_in,
                              void* d_out, int out_size)
{
    const float* hidden = (const float*)d_in[0];
    const unsigned char* mask = (const unsigned char*)d_in[1];
    const float* W_qkv = (const float*)d_in[2];
    const float* b_qkv = (const float*)d_in[3];
    const float* W_dense = (const float*)d_in[4];
    const float* b_dense = (const float*)d_in[5];
    float* out = (float*)d_out;

    float *qd, *kd, *vd;
    uint32_t *ahi, *alo, *wqhi, *wqlo, *wdhi, *wdlo, *chi, *clo, *vhi, *vlo;
    cudaGetSymbolAddress((void**)&qd,   g_q);
    cudaGetSymbolAddress((void**)&kd,   g_k);
    cudaGetSymbolAddress((void**)&vd,   g_v);
    cudaGetSymbolAddress((void**)&ahi,  g_ahi);
    cudaGetSymbolAddress((void**)&alo,  g_alo);
    cudaGetSymbolAddress((void**)&wqhi, g_wqhi);
    cudaGetSymbolAddress((void**)&wqlo, g_wqlo);
    cudaGetSymbolAddress((void**)&wdhi, g_wdhi);
    cudaGetSymbolAddress((void**)&wdlo, g_wdlo);
    cudaGetSymbolAddress((void**)&chi,  g_chi);
    cudaGetSymbolAddress((void**)&clo,  g_clo);
    cudaGetSymbolAddress((void**)&vhi,  g_vhi);
    cudaGetSymbolAddress((void**)&vlo,  g_vlo);

    cudaFuncSetAttribute(attn_tc,
                         cudaFuncAttributeMaxDynamicSharedMemorySize,
                         ATT_SMEM_BYTES);

    const float* bdt = (out_size >= M_ROWS * H_DIM + H_DIM) ? b_dense : nullptr;

    // 0) Pre-split inputs
    {
        long f4 = (long)M_ROWS * H_DIM / 4;
        presplit_rows<<<(unsigned)((f4 + 255) / 256), 256>>>(hidden, ahi, alo, f4);
        long wq = (long)HP * N3;
        presplit_cols<<<(unsigned)((wq + 255) / 256), 256>>>(W_qkv, wqhi, wqlo, N3, wq);
        long wd = (long)HP * H_DIM;
        presplit_cols<<<(unsigned)((wd + 255) / 256), 256>>>(W_dense, wdhi, wdlo, H_DIM, wd);
    }
    // 1) QKV GEMM + scatter (q,k tf32-rounded; v fp32)
    {
        dim3 grid(N3 / 128, M_ROWS / 128);
        gemm_tc<<<grid, 256>>>(ahi, alo, wqhi, wqlo, b_qkv, nullptr,
                               qd, kd, vd, nullptr, M_ROWS, N3, H_DIM, 0);
    }
    // 1b) Pre-split V (pairs along seq)
    {
        long vw = (long)B_SZ * NH * (S_LEN / 2) * DH;
        presplit_cols<<<(unsigned)((vw + 255) / 256), 256>>>(vd, vhi, vlo, DH, vw);
    }
    // 2) Flash attention (512 threads; writes ctx hi/lo)
    {
        dim3 grid(S_LEN / 64, B_SZ * NH);
        attn_tc<<<grid, ATT_THREADS, ATT_SMEM_BYTES>>>(mask, qd, kd, vhi, vlo, chi, clo);
    }
    // 3) Dense GEMM -> out (+ folded b_dense tail)
    {
        dim3 grid(H_DIM / 128, M_ROWS / 128);
        gemm_tc<<<grid, 256>>>(chi, clo, wdhi, wdlo, nullptr, out,
                               nullptr, nullptr, nullptr, bdt,
                               M_ROWS, H_DIM, H_DIM, 1);
    }
}

// round 9
// speedup vs baseline: 2.5536x; 1.2117x over previous
#include <cuda_runtime.h>
#include <cuda_bf16.h>
#include <math.h>
#include <stdint.h>

// Problem constants
#define S_LEN 2048
#define B_SZ  2
#define H_DIM 2048
#define NH    16
#define DH    128
#define N3    (3 * H_DIM)          // 6144
#define M_ROWS (S_LEN * B_SZ)      // 4096
#define HP    (H_DIM / 2)          // 1024 pair-words per row
#define MASK_VALUE (-10000.0f)

// fp32 scratch
__device__ float g_q[B_SZ * NH * S_LEN * DH];   // tf32-rounded values
__device__ float g_k[B_SZ * NH * S_LEN * DH];   // tf32-rounded values
__device__ float g_v[B_SZ * NH * S_LEN * DH];   // fp32
// pre-split bf16-pair words
__device__ uint32_t g_ahi[M_ROWS * HP];
__device__ uint32_t g_alo[M_ROWS * HP];
__device__ uint32_t g_wqhi[HP * N3];
__device__ uint32_t g_wqlo[HP * N3];
__device__ uint32_t g_wdhi[HP * H_DIM];
__device__ uint32_t g_wdlo[HP * H_DIM];
__device__ uint32_t g_chi[M_ROWS * HP];
__device__ uint32_t g_clo[M_ROWS * HP];
__device__ uint32_t g_vhi[B_SZ * NH * (S_LEN/2) * DH];
__device__ uint32_t g_vlo[B_SZ * NH * (S_LEN/2) * DH];

// ---------------------------------------------------------------------------
// helpers
// ---------------------------------------------------------------------------
__device__ __forceinline__ float to_tf32(float x)
{
    uint32_t u;
    asm("cvt.rna.tf32.f32 %0, %1;" : "=r"(u) : "f"(x));
    return __uint_as_float(u);
}

__device__ __forceinline__ void mma_tf32(float* c, const uint32_t* a, const uint32_t* b)
{
    asm volatile(
        "mma.sync.aligned.m16n8k8.row.col.f32.tf32.tf32.f32 "
        "{%0,%1,%2,%3}, {%4,%5,%6,%7}, {%8,%9}, {%0,%1,%2,%3};"
        : "+f"(c[0]), "+f"(c[1]), "+f"(c[2]), "+f"(c[3])
        : "r"(a[0]), "r"(a[1]), "r"(a[2]), "r"(a[3]),
          "r"(b[0]), "r"(b[1]));
}

__device__ __forceinline__ void mma_bf16(float* c, const uint32_t* a, const uint32_t* b)
{
    asm volatile(
        "mma.sync.aligned.m16n8k16.row.col.f32.bf16.bf16.f32 "
        "{%0,%1,%2,%3}, {%4,%5,%6,%7}, {%8,%9}, {%0,%1,%2,%3};"
        : "+f"(c[0]), "+f"(c[1]), "+f"(c[2]), "+f"(c[3])
        : "r"(a[0]), "r"(a[1]), "r"(a[2]), "r"(a[3]),
          "r"(b[0]), "r"(b[1]));
}

__device__ __forceinline__ void split2_pack(float x0, float x1,
                                            uint32_t& hi, uint32_t& lo)
{
    __nv_bfloat16 h0 = __float2bfloat16_rn(x0);
    __nv_bfloat16 h1 = __float2bfloat16_rn(x1);
    __nv_bfloat16 l0 = __float2bfloat16_rn(x0 - __bfloat162float(h0));
    __nv_bfloat16 l1 = __float2bfloat16_rn(x1 - __bfloat162float(h1));
    __nv_bfloat162 hp = __halves2bfloat162(h0, h1);
    __nv_bfloat162 lp = __halves2bfloat162(l0, l1);
    hi = *reinterpret_cast<uint32_t*>(&hp);
    lo = *reinterpret_cast<uint32_t*>(&lp);
}

// ---------------------------------------------------------------------------
// Pre-split kernels
// ---------------------------------------------------------------------------
__global__ void presplit_rows(const float* __restrict__ src,
                              uint32_t* __restrict__ hi, uint32_t* __restrict__ lo,
                              long total_f4)
{
    long i = (long)blockIdx.x * blockDim.x + threadIdx.x;
    if (i >= total_f4) return;
    float4 v = reinterpret_cast<const float4*>(src)[i];
    uint32_t h0, l0, h1, l1;
    split2_pack(v.x, v.y, h0, l0);
    split2_pack(v.z, v.w, h1, l1);
    reinterpret_cast<uint2*>(hi)[i] = make_uint2(h0, h1);
    reinterpret_cast<uint2*>(lo)[i] = make_uint2(l0, l1);
}

__global__ void presplit_cols(const float* __restrict__ src,
                              uint32_t* __restrict__ hi, uint32_t* __restrict__ lo,
                              int N, long total_words)
{
    long w = (long)blockIdx.x * blockDim.x + threadIdx.x;
    if (w >= total_words) return;
    long pr = w / N;
    int  n  = (int)(w - pr * N);
    float a = src[(2 * pr) * (long)N + n];
    float b = src[(2 * pr + 1) * (long)N + n];
    uint32_t h, l;
    split2_pack(a, b, h, l);
    hi[w] = h; lo[w] = l;
}

// ---------------------------------------------------------------------------
// Tensor-core GEMM (unchanged from R8)
// ---------------------------------------------------------------------------
#define APK_STRIDE 20
#define BPK_STRIDE 136

__global__ __launch_bounds__(256)
void gemm_tc(const uint32_t* __restrict__ Ahi_g, const uint32_t* __restrict__ Alo_g,
             const uint32_t* __restrict__ Bhi_g, const uint32_t* __restrict__ Blo_g,
             const float* __restrict__ bias, float* __restrict__ C,
             float* __restrict__ qd, float* __restrict__ kd, float* __restrict__ vd,
             const float* __restrict__ bdt,
             int M, int N, int K, int mode)
{
    __shared__ uint32_t Ahi[128][APK_STRIDE];
    __shared__ uint32_t Alo[128][APK_STRIDE];
    __shared__ uint32_t Bhi[16][BPK_STRIDE];
    __shared__ uint32_t Blo[16][BPK_STRIDE];

    const int tid  = threadIdx.x;
    const int lane = tid & 31;
    const int warp = tid >> 5;
    const int wm   = warp & 1;
    const int wn   = warp >> 1;
    const int g    = lane >> 2;
    const int cq   = lane & 3;

    const int m0 = blockIdx.y * 128;
    const int n0 = blockIdx.x * 128;
    const int Kp = K >> 1;

    float acc[4][4][4];
#pragma unroll
    for (int mt = 0; mt < 4; mt++)
#pragma unroll
        for (int nt = 0; nt < 4; nt++)
#pragma unroll
            for (int r = 0; r < 4; r++) acc[mt][nt][r] = 0.0f;

    const int arw = tid >> 3;
    const int akp = (tid & 7) << 1;
    const int bpr = tid >> 5;
    const int bnc = (tid & 31) << 2;

    for (int k0p = 0; k0p < Kp; k0p += 16) {
#pragma unroll
        for (int p = 0; p < 4; p++) {
            int m = arw + p * 32;
            size_t ai = (size_t)(m0 + m) * Kp + k0p + akp;
            uint2 h = *reinterpret_cast<const uint2*>(&Ahi_g[ai]);
            uint2 l = *reinterpret_cast<const uint2*>(&Alo_g[ai]);
            *reinterpret_cast<uint2*>(&Ahi[m][akp]) = h;
            *reinterpret_cast<uint2*>(&Alo[m][akp]) = l;
        }
#pragma unroll
        for (int p = 0; p < 2; p++) {
            int pr = bpr + p * 8;
            size_t bi = (size_t)(k0p + pr) * N + n0 + bnc;
            uint4 h = *reinterpret_cast<const uint4*>(&Bhi_g[bi]);
            uint4 l = *reinterpret_cast<const uint4*>(&Blo_g[bi]);
            *reinterpret_cast<uint4*>(&Bhi[pr][bnc]) = h;
            *reinterpret_cast<uint4*>(&Blo[pr][bnc]) = l;
        }
        __syncthreads();

#pragma unroll
        for (int kk = 0; kk < 2; kk++) {
            const int kb = kk * 8;
            uint32_t ah[4][4], al[4][4];
#pragma unroll
            for (int mt = 0; mt < 4; mt++) {
                const int mb = wm * 64 + mt * 16;
                ah[mt][0] = Ahi[mb + g][kb + cq];
                ah[mt][1] = Ahi[mb + g + 8][kb + cq];
                ah[mt][2] = Ahi[mb + g][kb + cq + 4];
                ah[mt][3] = Ahi[mb + g + 8][kb + cq + 4];
                al[mt][0] = Alo[mb + g][kb + cq];
                al[mt][1] = Alo[mb + g + 8][kb + cq];
                al[mt][2] = Alo[mb + g][kb + cq + 4];
                al[mt][3] = Alo[mb + g + 8][kb + cq + 4];
            }
            uint32_t bh[4][2], bl[4][2];
#pragma unroll
            for (int nt = 0; nt < 4; nt++) {
                const int nb = wn * 32 + nt * 8;
                bh[nt][0] = Bhi[kb + cq][nb + g];
                bh[nt][1] = Bhi[kb + cq + 4][nb + g];
                bl[nt][0] = Blo[kb + cq][nb + g];
                bl[nt][1] = Blo[kb + cq + 4][nb + g];
            }
#pragma unroll
            for (int mt = 0; mt < 4; mt++)
#pragma unroll
                for (int nt = 0; nt < 4; nt++) {
                    mma_bf16(acc[mt][nt], ah[mt], bh[nt]);
                    mma_bf16(acc[mt][nt], ah[mt], bl[nt]);
                    mma_bf16(acc[mt][nt], al[mt], bh[nt]);
                }
        }
        __syncthreads();
    }

    if (mode == 0) {
#pragma unroll
        for (int mt = 0; mt < 4; mt++) {
#pragma unroll
            for (int nt = 0; nt < 4; nt++) {
#pragma unroll
                for (int r = 0; r < 4; r++) {
                    int m = m0 + wm * 64 + mt * 16 + g + ((r >> 1) << 3);
                    int n = n0 + wn * 32 + nt * 8 + 2 * cq + (r & 1);
                    float v = acc[mt][nt][r] + bias[n];
                    int b = m & 1;
                    int s = m >> 1;
                    int head = n / (3 * DH);
                    int rem  = n - head * (3 * DH);
                    int part = rem >> 7;
                    int d    = rem & 127;
                    size_t idx = (((size_t)(b * NH + head)) * S_LEN + s) * DH + d;
                    if (part == 0)      qd[idx] = to_tf32(v);
                    else if (part == 1) kd[idx] = to_tf32(v);
                    else                vd[idx] = v;
                }
            }
        }
    } else {
#pragma unroll
        for (int mt = 0; mt < 4; mt++) {
#pragma unroll
            for (int nt = 0; nt < 4; nt++) {
                int n = n0 + wn * 32 + nt * 8 + 2 * cq;
                int mA = m0 + wm * 64 + mt * 16 + g;
                int mB = mA + 8;
                float2 vA = make_float2(acc[mt][nt][0], acc[mt][nt][1]);
                float2 vB = make_float2(acc[mt][nt][2], acc[mt][nt][3]);
                *reinterpret_cast<float2*>(&C[(size_t)mA * N + n]) = vA;
                *reinterpret_cast<float2*>(&C[(size_t)mB * N + n]) = vB;
            }
        }
        if (bdt && blockIdx.x == 0 && blockIdx.y == 0) {
            for (int i = tid; i < H_DIM; i += 256)
                C[(size_t)M_ROWS * H_DIM + i] = bdt[i];
        }
    }
}

// ---------------------------------------------------------------------------
// Tensor-core flash attention — Q_TILE=128, 512 threads, K/V reg-prefetch.
// Block = 128 queries of one (b,h). QK: tf32, warp m16n32 (8m x 2n).
// P@V: bf16 3-split, warp m16n64 (8m x 2n). Softmax: 4 threads/row.
// ---------------------------------------------------------------------------
#define QS_STRIDE 132
#define VPK_STRIDE 136
#define PPK_STRIDE 36
#define SR_STRIDE 68
#define ATT_THREADS 512
// word offsets
#define AQ_OFF   0                         // 128*132 = 16896
#define AK_OFF   16896                     // 64*132  = 8448
#define AVHI_OFF 25344                     // 32*136  = 4352
#define AVLO_OFF 29696
#define APHI_OFF 34048                     // 128*36  = 4608
#define APLO_OFF 38656
#define ASR_OFF  43264                     // 128*68  = 8704
#define AROW_OFF 51968                     // 3*128
#define ATT_SMEM_BYTES ((51968 + 384) * 4) // 209408 B

__global__ __launch_bounds__(ATT_THREADS)
void attn_tc(const unsigned char* __restrict__ mask,
             const float* __restrict__ gq, const float* __restrict__ gk,
             const uint32_t* __restrict__ gvhi, const uint32_t* __restrict__ gvlo,
             uint32_t* __restrict__ gchi, uint32_t* __restrict__ gclo)
{
    extern __shared__ float sm[];
    float*    Qs   = sm + AQ_OFF;
    float*    Ks   = sm + AK_OFF;
    uint32_t* Vhi  = reinterpret_cast<uint32_t*>(sm) + AVHI_OFF;
    uint32_t* Vlo  = reinterpret_cast<uint32_t*>(sm) + AVLO_OFF;
    uint32_t* Phi  = reinterpret_cast<uint32_t*>(sm) + APHI_OFF;
    uint32_t* Plo  = reinterpret_cast<uint32_t*>(sm) + APLO_OFF;
    float*    Sraw = sm + ASR_OFF;
    float*    mrow = sm + AROW_OFF;
    float*    lrow = mrow + 128;
    float*    arow = lrow + 128;

    const int tid  = threadIdx.x;
    const int lane = tid & 31;
    const int warp = tid >> 5;          // 0..15
    const int g    = lane >> 2;
    const int cq   = lane & 3;

    const int bh = blockIdx.y;
    const int b  = bh / NH;
    const int h  = bh - b * NH;
    const int q0 = blockIdx.x * 128;

    const float* qp = gq + (size_t)bh * S_LEN * DH;
    const float* kp = gk + (size_t)bh * S_LEN * DH;
    const uint32_t* vhp = gvhi + (size_t)bh * (S_LEN / 2) * DH;
    const uint32_t* vlp = gvlo + (size_t)bh * (S_LEN / 2) * DH;
    const unsigned char* mp = mask + (size_t)b * S_LEN * S_LEN;
    const float inv_norm = 1.0f / sqrtf((float)H_DIM);

    // Q tile: 128 x 128 floats (straight copy; already tf32-rounded)
    for (int e = tid; e < 128 * 32; e += ATT_THREADS) {
        int r = e >> 5;
        int c = (e & 31) << 2;
        float4 q4 = *reinterpret_cast<const float4*>(&qp[(size_t)(q0 + r) * DH + c]);
        *reinterpret_cast<float4*>(&Qs[r * QS_STRIDE + c]) = q4;
    }
    if (tid < 128) { mrow[tid] = -INFINITY; lrow[tid] = 0.0f; }
    // K,V tile 0
    for (int e = tid; e < 64 * 32; e += ATT_THREADS) {
        int r = e >> 5;
        int c = (e & 31) << 2;
        float4 k4 = *reinterpret_cast<const float4*>(&kp[(size_t)r * DH + c]);
        *reinterpret_cast<float4*>(&Ks[r * QS_STRIDE + c]) = k4;
    }
    for (int e = tid; e < 32 * 32; e += ATT_THREADS) {
        int sp = e >> 5;
        int c  = (e & 31) << 2;
        size_t base = (size_t)sp * DH + c;
        *reinterpret_cast<uint4*>(&Vhi[sp * VPK_STRIDE + c]) =
            *reinterpret_cast<const uint4*>(&vhp[base]);
        *reinterpret_cast<uint4*>(&Vlo[sp * VPK_STRIDE + c]) =
            *reinterpret_cast<const uint4*>(&vlp[base]);
    }
    __syncthreads();

    const int wm = warp & 7;            // m-slab (16 rows of 128)
    const int wn = warp >> 3;           // n-slab
    const int mb = wm * 16;

    float o[8][4];
#pragma unroll
    for (int nt = 0; nt < 8; nt++)
#pragma unroll
        for (int r = 0; r < 4; r++) o[nt][r] = 0.0f;

    // reg-staged K/V loads
    const int kr = tid >> 5;            // base row for K staging (x4 passes of 16)
    const int kc = (lane) << 2;         // wrong width; recompute below per-pass

    for (int kt = 0; kt < S_LEN / 64; kt++) {
        const int t0 = kt * 64;
        const bool has_next = (kt + 1 < S_LEN / 64);
        const int t1 = t0 + 64;

        // Stage next K/V tile into registers (LDG overlaps QK+softmax)
        float4 kst[4];
        uint4 vhst[2], vlst[2];
        if (has_next) {
#pragma unroll
            for (int p = 0; p < 4; p++) {
                int e = tid + p * ATT_THREADS;
                int r = e >> 5;
                int c = (e & 31) << 2;
                kst[p] = *reinterpret_cast<const float4*>(&kp[(size_t)(t1 + r) * DH + c]);
            }
#pragma unroll
            for (int p = 0; p < 2; p++) {
                int e = tid + p * ATT_THREADS;
                int sp = e >> 5;
                int c  = (e & 31) << 2;
                size_t base = ((size_t)(t1 >> 1) + sp) * DH + c;
                vhst[p] = *reinterpret_cast<const uint4*>(&vhp[base]);
                vlst[p] = *reinterpret_cast<const uint4*>(&vlp[base]);
            }
        }

        // --- QK^T (tf32): warp computes m16 x n32 of S[128,64] ---
        {
            float sacc[4][4];
#pragma unroll
            for (int nt = 0; nt < 4; nt++)
#pragma unroll
                for (int r = 0; r < 4; r++) sacc[nt][r] = 0.0f;

            const int nbq = wn * 32;
#pragma unroll
            for (int ks = 0; ks < 16; ks++) {
                const int kb = ks * 8;
                uint32_t a[4];
                a[0] = __float_as_uint(Qs[(mb + g) * QS_STRIDE + kb + cq]);
                a[1] = __float_as_uint(Qs[(mb + g + 8) * QS_STRIDE + kb + cq]);
                a[2] = __float_as_uint(Qs[(mb + g) * QS_STRIDE + kb + cq + 4]);
                a[3] = __float_as_uint(Qs[(mb + g + 8) * QS_STRIDE + kb + cq + 4]);
#pragma unroll
                for (int nt = 0; nt < 4; nt++) {
                    const int nr = nbq + nt * 8 + g;
                    uint32_t bfr[2];
                    bfr[0] = __float_as_uint(Ks[nr * QS_STRIDE + kb + cq]);
                    bfr[1] = __float_as_uint(Ks[nr * QS_STRIDE + kb + cq + 4]);
                    mma_tf32(sacc[nt], a, bfr);
                }
            }
#pragma unroll
            for (int nt = 0; nt < 4; nt++) {
#pragma unroll
                for (int r = 0; r < 4; r++) {
                    int rr = mb + g + ((r >> 1) << 3);
                    int cc = nbq + nt * 8 + 2 * cq + (r & 1);
                    Sraw[rr * SR_STRIDE + cc] = sacc[nt][r];
                }
            }
        }
        __syncthreads();

        // --- softmax: 4 threads per row (512 thr / 128 rows) ---
        {
            const int row = tid >> 2;
            const int sub = tid & 3;
            const int cb  = sub * 16;
            float* srow = &Sraw[row * SR_STRIDE + cb];
            uint32_t* ph = &Phi[row * PPK_STRIDE + sub * 8];
            uint32_t* pl = &Plo[row * PPK_STRIDE + sub * 8];
            const unsigned char* mr = mp + (size_t)(q0 + row) * S_LEN + t0 + cb;

            float v[16];
            float rmax = -INFINITY;
#pragma unroll
            for (int i = 0; i < 16; i += 4) {
                uchar4 mk = *reinterpret_cast<const uchar4*>(mr + i);
                float s0 = srow[i + 0] * inv_norm; if (mk.x) s0 = MASK_VALUE;
                float s1 = srow[i + 1] * inv_norm; if (mk.y) s1 = MASK_VALUE;
                float s2 = srow[i + 2] * inv_norm; if (mk.z) s2 = MASK_VALUE;
                float s3 = srow[i + 3] * inv_norm; if (mk.w) s3 = MASK_VALUE;
                v[i + 0] = s0; v[i + 1] = s1; v[i + 2] = s2; v[i + 3] = s3;
                rmax = fmaxf(rmax, fmaxf(fmaxf(s0, s1), fmaxf(s2, s3)));
            }
            rmax = fmaxf(rmax, __shfl_xor_sync(0xffffffffu, rmax, 1));
            rmax = fmaxf(rmax, __shfl_xor_sync(0xffffffffu, rmax, 2));
            float m_old = mrow[row];
            float m_new = fmaxf(m_old, rmax);
            float alpha = __expf(m_old - m_new);
            float sum = 0.0f;
#pragma unroll
            for (int i = 0; i < 16; i += 2) {
                float p0 = __expf(v[i + 0] - m_new);
                float p1 = __expf(v[i + 1] - m_new);
                sum += p0 + p1;
                uint32_t hh, ll;
                split2_pack(p0, p1, hh, ll);
                ph[i >> 1] = hh;
                pl[i >> 1] = ll;
            }
            sum += __shfl_xor_sync(0xffffffffu, sum, 1);
            sum += __shfl_xor_sync(0xffffffffu, sum, 2);
            if (sub == 0) {
                lrow[row] = lrow[row] * alpha + sum;
                mrow[row] = m_new;
                arow[row] = alpha;
            }
        }
        __syncthreads();

        // --- rescale O, then P@V (bf16 3-split): warp m16 x n64 ---
        {
            const int nbv = wn * 64;
            float al0 = arow[mb + g];
            float al1 = arow[mb + g + 8];
#pragma unroll
            for (int nt = 0; nt < 8; nt++) {
                o[nt][0] *= al0; o[nt][1] *= al0;
                o[nt][2] *= al1; o[nt][3] *= al1;
            }
#pragma unroll
            for (int ks = 0; ks < 4; ks++) {
                const int kb = ks * 8;
                uint32_t ah[4], al_[4];
                ah[0]  = Phi[(mb + g) * PPK_STRIDE + kb + cq];
                ah[1]  = Phi[(mb + g + 8) * PPK_STRIDE + kb + cq];
                ah[2]  = Phi[(mb + g) * PPK_STRIDE + kb + cq + 4];
                ah[3]  = Phi[(mb + g + 8) * PPK_STRIDE + kb + cq + 4];
                al_[0] = Plo[(mb + g) * PPK_STRIDE + kb + cq];
                al_[1] = Plo[(mb + g + 8) * PPK_STRIDE + kb + cq];
                al_[2] = Plo[(mb + g) * PPK_STRIDE + kb + cq + 4];
                al_[3] = Plo[(mb + g + 8) * PPK_STRIDE + kb + cq + 4];
#pragma unroll
                for (int nt = 0; nt < 8; nt++) {
                    const int nc = nbv + nt * 8 + g;
                    uint32_t bhv[2], blv[2];
                    bhv[0] = Vhi[(kb + cq) * VPK_STRIDE + nc];
                    bhv[1] = Vhi[(kb + cq + 4) * VPK_STRIDE + nc];
                    blv[0] = Vlo[(kb + cq) * VPK_STRIDE + nc];
                    blv[1] = Vlo[(kb + cq + 4) * VPK_STRIDE + nc];
                    mma_bf16(o[nt], ah, bhv);
                    mma_bf16(o[nt], ah, blv);
                    mma_bf16(o[nt], al_, bhv);
                }
            }
        }
        __syncthreads();

        // --- write staged K/V into smem for next tile ---
        if (has_next) {
#pragma unroll
            for (int p = 0; p < 4; p++) {
                int e = tid + p * ATT_THREADS;
                int r = e >> 5;
                int c = (e & 31) << 2;
                *reinterpret_cast<float4*>(&Ks[r * QS_STRIDE + c]) = kst[p];
            }
#pragma unroll
            for (int p = 0; p < 2; p++) {
                int e = tid + p * ATT_THREADS;
                int sp = e >> 5;
                int c  = (e & 31) << 2;
                *reinterpret_cast<uint4*>(&Vhi[sp * VPK_STRIDE + c]) = vhst[p];
                *reinterpret_cast<uint4*>(&Vlo[sp * VPK_STRIDE + c]) = vlst[p];
            }
            __syncthreads();
        }
    }

    // Epilogue: O /= l, write ctx as bf16 hi/lo pair words
    {
        const int nbv = wn * 64;
        float li0 = 1.0f / lrow[mb + g];
        float li1 = 1.0f / lrow[mb + g + 8];
        int s0r = q0 + mb + g;
        int s1r = s0r + 8;
#pragma unroll
        for (int nt = 0; nt < 8; nt++) {
            int colw = (h * DH + nbv + nt * 8) / 2 + cq;
            uint32_t hw0, lw0, hw1, lw1;
            split2_pack(o[nt][0] * li0, o[nt][1] * li0, hw0, lw0);
            split2_pack(o[nt][2] * li1, o[nt][3] * li1, hw1, lw1);
            size_t r0 = ((size_t)s0r * B_SZ + b) * HP + colw;
            size_t r1 = ((size_t)s1r * B_SZ + b) * HP + colw;
            gchi[r0] = hw0; gclo[r0] = lw0;
            gchi[r1] = hw1; gclo[r1] = lw1;
        }
    }
}

extern "C" void kernel_launch(void* const* d_in, const int* in_sizes, int n_in,
                              void* d_out, int out_size)
{
    const float* hidden = (const float*)d_in[0];
    const unsigned char* mask = (const unsigned char*)d_in[1];
    const float* W_qkv = (const float*)d_in[2];
    const float* b_qkv = (const float*)d_in[3];
    const float* W_dense = (const float*)d_in[4];
    const float* b_dense = (const float*)d_in[5];
    float* out = (float*)d_out;

    float *qd, *kd, *vd;
    uint32_t *ahi, *alo, *wqhi, *wqlo, *wdhi, *wdlo, *chi, *clo, *vhi, *vlo;
    cudaGetSymbolAddress((void**)&qd,   g_q);
    cudaGetSymbolAddress((void**)&kd,   g_k);
    cudaGetSymbolAddress((void**)&vd,   g_v);
    cudaGetSymbolAddress((void**)&ahi,  g_ahi);
    cudaGetSymbolAddress((void**)&alo,  g_alo);
    cudaGetSymbolAddress((void**)&wqhi, g_wqhi);
    cudaGetSymbolAddress((void**)&wqlo, g_wqlo);
    cudaGetSymbolAddress((void**)&wdhi, g_wdhi);
    cudaGetSymbolAddress((void**)&wdlo, g_wdlo);
    cudaGetSymbolAddress((void**)&chi,  g_chi);
    cudaGetSymbolAddress((void**)&clo,  g_clo);
    cudaGetSymbolAddress((void**)&vhi,  g_vhi);
    cudaGetSymbolAddress((void**)&vlo,  g_vlo);

    cudaFuncSetAttribute(attn_tc,
                         cudaFuncAttributeMaxDynamicSharedMemorySize,
                         ATT_SMEM_BYTES);

    const float* bdt = (out_size >= M_ROWS * H_DIM + H_DIM) ? b_dense : nullptr;

    // 0) Pre-split inputs
    {
        long f4 = (long)M_ROWS * H_DIM / 4;
        presplit_rows<<<(unsigned)((f4 + 255) / 256), 256>>>(hidden, ahi, alo, f4);
        long wq = (long)HP * N3;
        presplit_cols<<<(unsigned)((wq + 255) / 256), 256>>>(W_qkv, wqhi, wqlo, N3, wq);
        long wd = (long)HP * H_DIM;
        presplit_cols<<<(unsigned)((wd + 255) / 256), 256>>>(W_dense, wdhi, wdlo, H_DIM, wd);
    }
    // 1) QKV GEMM + scatter
    {
        dim3 grid(N3 / 128, M_ROWS / 128);
        gemm_tc<<<grid, 256>>>(ahi, alo, wqhi, wqlo, b_qkv, nullptr,
                               qd, kd, vd, nullptr, M_ROWS, N3, H_DIM, 0);
    }
    // 1b) Pre-split V
    {
        long vw = (long)B_SZ * NH * (S_LEN / 2) * DH;
        presplit_cols<<<(unsigned)((vw + 255) / 256), 256>>>(vd, vhi, vlo, DH, vw);
    }
    // 2) Flash attention (Q_TILE=128)
    {
        dim3 grid(S_LEN / 128, B_SZ * NH);
        attn_tc<<<grid, ATT_THREADS, ATT_SMEM_BYTES>>>(mask, qd, kd, vhi, vlo, chi, clo);
    }
    // 3) Dense GEMM -> out (+ folded b_dense tail)
    {
        dim3 grid(H_DIM / 128, M_ROWS / 128);
        gemm_tc<<<grid, 256>>>(chi, clo, wdhi, wdlo, nullptr, out,
                               nullptr, nullptr, nullptr, bdt,
                               M_ROWS, H_DIM, H_DIM, 1);
    }
}

// round 10
// speedup vs baseline: 2.6668x; 1.0443x over previous
#include <cuda_runtime.h>
#include <cuda_bf16.h>
#include <math.h>
#include <stdint.h>

// Problem constants
#define S_LEN 2048
#define B_SZ  2
#define H_DIM 2048
#define NH    16
#define DH    128
#define N3    (3 * H_DIM)          // 6144
#define M_ROWS (S_LEN * B_SZ)      // 4096
#define HP    (H_DIM / 2)          // 1024 pair-words per row
#define MASK_VALUE (-10000.0f)

// fp32 scratch
__device__ float g_q[B_SZ * NH * S_LEN * DH];   // tf32-rounded
__device__ float g_k[B_SZ * NH * S_LEN * DH];   // tf32-rounded
__device__ float g_v[B_SZ * NH * S_LEN * DH];   // fp32
// pre-split bf16-pair words
__device__ uint32_t g_ahi[M_ROWS * HP];
__device__ uint32_t g_alo[M_ROWS * HP];
__device__ uint32_t g_wqhi[HP * N3];
__device__ uint32_t g_wqlo[HP * N3];
__device__ uint32_t g_wdhi[HP * H_DIM];
__device__ uint32_t g_wdlo[HP * H_DIM];
__device__ uint32_t g_chi[M_ROWS * HP];
__device__ uint32_t g_clo[M_ROWS * HP];
__device__ uint32_t g_vhi[B_SZ * NH * (S_LEN/2) * DH];
__device__ uint32_t g_vlo[B_SZ * NH * (S_LEN/2) * DH];

// ---------------------------------------------------------------------------
// helpers
// ---------------------------------------------------------------------------
__device__ __forceinline__ float to_tf32(float x)
{
    uint32_t u;
    asm("cvt.rna.tf32.f32 %0, %1;" : "=r"(u) : "f"(x));
    return __uint_as_float(u);
}

__device__ __forceinline__ void mma_tf32(float* c, const uint32_t* a, const uint32_t* b)
{
    asm volatile(
        "mma.sync.aligned.m16n8k8.row.col.f32.tf32.tf32.f32 "
        "{%0,%1,%2,%3}, {%4,%5,%6,%7}, {%8,%9}, {%0,%1,%2,%3};"
        : "+f"(c[0]), "+f"(c[1]), "+f"(c[2]), "+f"(c[3])
        : "r"(a[0]), "r"(a[1]), "r"(a[2]), "r"(a[3]),
          "r"(b[0]), "r"(b[1]));
}

__device__ __forceinline__ void mma_bf16(float* c, const uint32_t* a, const uint32_t* b)
{
    asm volatile(
        "mma.sync.aligned.m16n8k16.row.col.f32.bf16.bf16.f32 "
        "{%0,%1,%2,%3}, {%4,%5,%6,%7}, {%8,%9}, {%0,%1,%2,%3};"
        : "+f"(c[0]), "+f"(c[1]), "+f"(c[2]), "+f"(c[3])
        : "r"(a[0]), "r"(a[1]), "r"(a[2]), "r"(a[3]),
          "r"(b[0]), "r"(b[1]));
}

__device__ __forceinline__ void split2_pack(float x0, float x1,
                                            uint32_t& hi, uint32_t& lo)
{
    __nv_bfloat16 h0 = __float2bfloat16_rn(x0);
    __nv_bfloat16 h1 = __float2bfloat16_rn(x1);
    __nv_bfloat16 l0 = __float2bfloat16_rn(x0 - __bfloat162float(h0));
    __nv_bfloat16 l1 = __float2bfloat16_rn(x1 - __bfloat162float(h1));
    __nv_bfloat162 hp = __halves2bfloat162(h0, h1);
    __nv_bfloat162 lp = __halves2bfloat162(l0, l1);
    hi = *reinterpret_cast<uint32_t*>(&hp);
    lo = *reinterpret_cast<uint32_t*>(&lp);
}

// ---------------------------------------------------------------------------
// Pre-split kernels
// ---------------------------------------------------------------------------
__global__ void presplit_rows(const float* __restrict__ src,
                              uint32_t* __restrict__ hi, uint32_t* __restrict__ lo,
                              long total_f4)
{
    long i = (long)blockIdx.x * blockDim.x + threadIdx.x;
    if (i >= total_f4) return;
    float4 v = reinterpret_cast<const float4*>(src)[i];
    uint32_t h0, l0, h1, l1;
    split2_pack(v.x, v.y, h0, l0);
    split2_pack(v.z, v.w, h1, l1);
    reinterpret_cast<uint2*>(hi)[i] = make_uint2(h0, h1);
    reinterpret_cast<uint2*>(lo)[i] = make_uint2(l0, l1);
}

__global__ void presplit_cols(const float* __restrict__ src,
                              uint32_t* __restrict__ hi, uint32_t* __restrict__ lo,
                              int N, long total_words)
{
    long w = (long)blockIdx.x * blockDim.x + threadIdx.x;
    if (w >= total_words) return;
    long pr = w / N;
    int  n  = (int)(w - pr * N);
    float a = src[(2 * pr) * (long)N + n];
    float b = src[(2 * pr + 1) * (long)N + n];
    uint32_t h, l;
    split2_pack(a, b, h, l);
    hi[w] = h; lo[w] = l;
}

// ---------------------------------------------------------------------------
// Tensor-core GEMM (unchanged)
// ---------------------------------------------------------------------------
#define APK_STRIDE 20
#define BPK_STRIDE 136

__global__ __launch_bounds__(256)
void gemm_tc(const uint32_t* __restrict__ Ahi_g, const uint32_t* __restrict__ Alo_g,
             const uint32_t* __restrict__ Bhi_g, const uint32_t* __restrict__ Blo_g,
             const float* __restrict__ bias, float* __restrict__ C,
             float* __restrict__ qd, float* __restrict__ kd, float* __restrict__ vd,
             const float* __restrict__ bdt,
             int M, int N, int K, int mode)
{
    __shared__ uint32_t Ahi[128][APK_STRIDE];
    __shared__ uint32_t Alo[128][APK_STRIDE];
    __shared__ uint32_t Bhi[16][BPK_STRIDE];
    __shared__ uint32_t Blo[16][BPK_STRIDE];

    const int tid  = threadIdx.x;
    const int lane = tid & 31;
    const int warp = tid >> 5;
    const int wm   = warp & 1;
    const int wn   = warp >> 1;
    const int g    = lane >> 2;
    const int cq   = lane & 3;

    const int m0 = blockIdx.y * 128;
    const int n0 = blockIdx.x * 128;
    const int Kp = K >> 1;

    float acc[4][4][4];
#pragma unroll
    for (int mt = 0; mt < 4; mt++)
#pragma unroll
        for (int nt = 0; nt < 4; nt++)
#pragma unroll
            for (int r = 0; r < 4; r++) acc[mt][nt][r] = 0.0f;

    const int arw = tid >> 3;
    const int akp = (tid & 7) << 1;
    const int bpr = tid >> 5;
    const int bnc = (tid & 31) << 2;

    for (int k0p = 0; k0p < Kp; k0p += 16) {
#pragma unroll
        for (int p = 0; p < 4; p++) {
            int m = arw + p * 32;
            size_t ai = (size_t)(m0 + m) * Kp + k0p + akp;
            uint2 h = *reinterpret_cast<const uint2*>(&Ahi_g[ai]);
            uint2 l = *reinterpret_cast<const uint2*>(&Alo_g[ai]);
            *reinterpret_cast<uint2*>(&Ahi[m][akp]) = h;
            *reinterpret_cast<uint2*>(&Alo[m][akp]) = l;
        }
#pragma unroll
        for (int p = 0; p < 2; p++) {
            int pr = bpr + p * 8;
            size_t bi = (size_t)(k0p + pr) * N + n0 + bnc;
            uint4 h = *reinterpret_cast<const uint4*>(&Bhi_g[bi]);
            uint4 l = *reinterpret_cast<const uint4*>(&Blo_g[bi]);
            *reinterpret_cast<uint4*>(&Bhi[pr][bnc]) = h;
            *reinterpret_cast<uint4*>(&Blo[pr][bnc]) = l;
        }
        __syncthreads();

#pragma unroll
        for (int kk = 0; kk < 2; kk++) {
            const int kb = kk * 8;
            uint32_t ah[4][4], al[4][4];
#pragma unroll
            for (int mt = 0; mt < 4; mt++) {
                const int mb = wm * 64 + mt * 16;
                ah[mt][0] = Ahi[mb + g][kb + cq];
                ah[mt][1] = Ahi[mb + g + 8][kb + cq];
                ah[mt][2] = Ahi[mb + g][kb + cq + 4];
                ah[mt][3] = Ahi[mb + g + 8][kb + cq + 4];
                al[mt][0] = Alo[mb + g][kb + cq];
                al[mt][1] = Alo[mb + g + 8][kb + cq];
                al[mt][2] = Alo[mb + g][kb + cq + 4];
                al[mt][3] = Alo[mb + g + 8][kb + cq + 4];
            }
            uint32_t bh[4][2], bl[4][2];
#pragma unroll
            for (int nt = 0; nt < 4; nt++) {
                const int nb = wn * 32 + nt * 8;
                bh[nt][0] = Bhi[kb + cq][nb + g];
                bh[nt][1] = Bhi[kb + cq + 4][nb + g];
                bl[nt][0] = Blo[kb + cq][nb + g];
                bl[nt][1] = Blo[kb + cq + 4][nb + g];
            }
#pragma unroll
            for (int mt = 0; mt < 4; mt++)
#pragma unroll
                for (int nt = 0; nt < 4; nt++) {
                    mma_bf16(acc[mt][nt], ah[mt], bh[nt]);
                    mma_bf16(acc[mt][nt], ah[mt], bl[nt]);
                    mma_bf16(acc[mt][nt], al[mt], bh[nt]);
                }
        }
        __syncthreads();
    }

    if (mode == 0) {
#pragma unroll
        for (int mt = 0; mt < 4; mt++) {
#pragma unroll
            for (int nt = 0; nt < 4; nt++) {
#pragma unroll
                for (int r = 0; r < 4; r++) {
                    int m = m0 + wm * 64 + mt * 16 + g + ((r >> 1) << 3);
                    int n = n0 + wn * 32 + nt * 8 + 2 * cq + (r & 1);
                    float v = acc[mt][nt][r] + bias[n];
                    int b = m & 1;
                    int s = m >> 1;
                    int head = n / (3 * DH);
                    int rem  = n - head * (3 * DH);
                    int part = rem >> 7;
                    int d    = rem & 127;
                    size_t idx = (((size_t)(b * NH + head)) * S_LEN + s) * DH + d;
                    if (part == 0)      qd[idx] = to_tf32(v);
                    else if (part == 1) kd[idx] = to_tf32(v);
                    else                vd[idx] = v;
                }
            }
        }
    } else {
#pragma unroll
        for (int mt = 0; mt < 4; mt++) {
#pragma unroll
            for (int nt = 0; nt < 4; nt++) {
                int n = n0 + wn * 32 + nt * 8 + 2 * cq;
                int mA = m0 + wm * 64 + mt * 16 + g;
                int mB = mA + 8;
                float2 vA = make_float2(acc[mt][nt][0], acc[mt][nt][1]);
                float2 vB = make_float2(acc[mt][nt][2], acc[mt][nt][3]);
                *reinterpret_cast<float2*>(&C[(size_t)mA * N + n]) = vA;
                *reinterpret_cast<float2*>(&C[(size_t)mB * N + n]) = vB;
            }
        }
        if (bdt && blockIdx.x == 0 && blockIdx.y == 0) {
            for (int i = tid; i < H_DIM; i += 256)
                C[(size_t)M_ROWS * H_DIM + i] = bdt[i];
        }
    }
}

// ---------------------------------------------------------------------------
// Flash attention, FA2-style register-resident S/P/m/l.
// Q_TILE=128, 256 threads (8 warps = 8 m-slabs of 16 rows; full 64-key span
// per warp). S never touches smem; softmax is warp-local (quad shuffles);
// O accumulates full d=128 in registers. 2 barriers per key tile.
// ---------------------------------------------------------------------------
#define QS_STRIDE 132
#define VPK_STRIDE 136
#define ATT_THREADS 256
// word offsets
#define AQ_OFF   0                          // 128*132 = 16896
#define AK_OFF   16896                      // 64*132  = 8448
#define AVHI_OFF 25344                      // 32*136  = 4352
#define AVLO_OFF 29696                      // 32*136
#define ATT_SMEM_BYTES ((34048) * 4)        // 136192 B

__global__ __launch_bounds__(ATT_THREADS)
void attn_tc(const unsigned char* __restrict__ mask,
             const float* __restrict__ gq, const float* __restrict__ gk,
             const uint32_t* __restrict__ gvhi, const uint32_t* __restrict__ gvlo,
             uint32_t* __restrict__ gchi, uint32_t* __restrict__ gclo)
{
    extern __shared__ float sm[];
    float*    Qs  = sm + AQ_OFF;
    float*    Ks  = sm + AK_OFF;
    uint32_t* Vhi = reinterpret_cast<uint32_t*>(sm) + AVHI_OFF;
    uint32_t* Vlo = reinterpret_cast<uint32_t*>(sm) + AVLO_OFF;

    const int tid  = threadIdx.x;
    const int lane = tid & 31;
    const int warp = tid >> 5;          // 0..7 = m-slab
    const int g    = lane >> 2;
    const int cq   = lane & 3;
    const int mb   = warp * 16;

    const int bh = blockIdx.y;
    const int b  = bh / NH;
    const int h  = bh - b * NH;
    const int q0 = blockIdx.x * 128;

    const float* qp = gq + (size_t)bh * S_LEN * DH;
    const float* kp = gk + (size_t)bh * S_LEN * DH;
    const uint32_t* vhp = gvhi + (size_t)bh * (S_LEN / 2) * DH;
    const uint32_t* vlp = gvlo + (size_t)bh * (S_LEN / 2) * DH;
    const unsigned char* mp = mask + (size_t)b * S_LEN * S_LEN;
    const float inv_norm = 1.0f / sqrtf((float)H_DIM);

    // Q tile: 128 x 128 floats
    for (int e = tid; e < 128 * 32; e += ATT_THREADS) {
        int r = e >> 5;
        int c = (e & 31) << 2;
        float4 q4 = *reinterpret_cast<const float4*>(&qp[(size_t)(q0 + r) * DH + c]);
        *reinterpret_cast<float4*>(&Qs[r * QS_STRIDE + c]) = q4;
    }
    // K,V tile 0
    for (int e = tid; e < 64 * 32; e += ATT_THREADS) {
        int r = e >> 5;
        int c = (e & 31) << 2;
        float4 k4 = *reinterpret_cast<const float4*>(&kp[(size_t)r * DH + c]);
        *reinterpret_cast<float4*>(&Ks[r * QS_STRIDE + c]) = k4;
    }
    for (int e = tid; e < 32 * 32; e += ATT_THREADS) {
        int sp = e >> 5;
        int c  = (e & 31) << 2;
        size_t base = (size_t)sp * DH + c;
        *reinterpret_cast<uint4*>(&Vhi[sp * VPK_STRIDE + c]) =
            *reinterpret_cast<const uint4*>(&vhp[base]);
        *reinterpret_cast<uint4*>(&Vlo[sp * VPK_STRIDE + c]) =
            *reinterpret_cast<const uint4*>(&vlp[base]);
    }
    __syncthreads();

    // register state
    float o[16][4];
#pragma unroll
    for (int nt = 0; nt < 16; nt++)
#pragma unroll
        for (int r = 0; r < 4; r++) o[nt][r] = 0.0f;
    float m0r = -INFINITY, m1r = -INFINITY;   // rows g, g+8
    float l0r = 0.0f, l1r = 0.0f;

    const unsigned char* mr0 = mp + (size_t)(q0 + mb + g) * S_LEN;
    const unsigned char* mr1 = mp + (size_t)(q0 + mb + g + 8) * S_LEN;

    for (int kt = 0; kt < S_LEN / 64; kt++) {
        const int t0 = kt * 64;
        const bool has_next = (kt + 1 < S_LEN / 64);
        const int t1 = t0 + 64;

        // Stage next K/V tile into registers (overlaps QK/softmax/PV)
        float4 kst[8];
        uint4 vhst[4], vlst[4];
        if (has_next) {
#pragma unroll
            for (int p = 0; p < 8; p++) {
                int e = tid + p * ATT_THREADS;
                int r = e >> 5;
                int c = (e & 31) << 2;
                kst[p] = *reinterpret_cast<const float4*>(&kp[(size_t)(t1 + r) * DH + c]);
            }
#pragma unroll
            for (int p = 0; p < 4; p++) {
                int e = tid + p * ATT_THREADS;
                int sp = e >> 5;
                int c  = (e & 31) << 2;
                size_t base = ((size_t)(t1 >> 1) + sp) * DH + c;
                vhst[p] = *reinterpret_cast<const uint4*>(&vhp[base]);
                vlst[p] = *reinterpret_cast<const uint4*>(&vlp[base]);
            }
        }

        // --- QK^T (tf32): warp computes m16 x n64, S stays in registers ---
        float s[8][4];
#pragma unroll
        for (int nt = 0; nt < 8; nt++)
#pragma unroll
            for (int r = 0; r < 4; r++) s[nt][r] = 0.0f;

#pragma unroll
        for (int ks = 0; ks < 16; ks++) {
            const int kb = ks * 8;
            uint32_t a[4];
            a[0] = __float_as_uint(Qs[(mb + g) * QS_STRIDE + kb + cq]);
            a[1] = __float_as_uint(Qs[(mb + g + 8) * QS_STRIDE + kb + cq]);
            a[2] = __float_as_uint(Qs[(mb + g) * QS_STRIDE + kb + cq + 4]);
            a[3] = __float_as_uint(Qs[(mb + g + 8) * QS_STRIDE + kb + cq + 4]);
#pragma unroll
            for (int nt = 0; nt < 8; nt++) {
                const int nr = nt * 8 + g;
                uint32_t bfr[2];
                bfr[0] = __float_as_uint(Ks[nr * QS_STRIDE + kb + cq]);
                bfr[1] = __float_as_uint(Ks[nr * QS_STRIDE + kb + cq + 4]);
                mma_tf32(s[nt], a, bfr);
            }
        }

        // --- scale + mask (register-resident) ---
        float pmax0 = -INFINITY, pmax1 = -INFINITY;
#pragma unroll
        for (int nt = 0; nt < 8; nt++) {
            int cc = t0 + nt * 8 + 2 * cq;
            uchar2 mk0 = *reinterpret_cast<const uchar2*>(mr0 + cc);
            uchar2 mk1 = *reinterpret_cast<const uchar2*>(mr1 + cc);
            float v0 = s[nt][0] * inv_norm; if (mk0.x) v0 = MASK_VALUE;
            float v1 = s[nt][1] * inv_norm; if (mk0.y) v1 = MASK_VALUE;
            float v2 = s[nt][2] * inv_norm; if (mk1.x) v2 = MASK_VALUE;
            float v3 = s[nt][3] * inv_norm; if (mk1.y) v3 = MASK_VALUE;
            s[nt][0] = v0; s[nt][1] = v1; s[nt][2] = v2; s[nt][3] = v3;
            pmax0 = fmaxf(pmax0, fmaxf(v0, v1));
            pmax1 = fmaxf(pmax1, fmaxf(v2, v3));
        }
        // quad reduce over the row's 64 cols (lanes share g, differ in cq)
        pmax0 = fmaxf(pmax0, __shfl_xor_sync(0xffffffffu, pmax0, 1));
        pmax0 = fmaxf(pmax0, __shfl_xor_sync(0xffffffffu, pmax0, 2));
        pmax1 = fmaxf(pmax1, __shfl_xor_sync(0xffffffffu, pmax1, 1));
        pmax1 = fmaxf(pmax1, __shfl_xor_sync(0xffffffffu, pmax1, 2));

        float mn0 = fmaxf(m0r, pmax0);
        float mn1 = fmaxf(m1r, pmax1);
        float alpha0 = __expf(m0r - mn0);
        float alpha1 = __expf(m1r - mn1);

        // exp + row sums + bf16 hi/lo pack (P stays in registers)
        uint32_t ph[4][4], pl[4][4];
        float sum0 = 0.0f, sum1 = 0.0f;
#pragma unroll
        for (int nt = 0; nt < 8; nt++) {
            float p0 = __expf(s[nt][0] - mn0);
            float p1 = __expf(s[nt][1] - mn0);
            float p2 = __expf(s[nt][2] - mn1);
            float p3 = __expf(s[nt][3] - mn1);
            sum0 += p0 + p1;
            sum1 += p2 + p3;
            int ks  = nt >> 1;          // k16 step
            int half = nt & 1;          // low/high k8 of the step
            split2_pack(p0, p1, ph[ks][half * 2 + 0], pl[ks][half * 2 + 0]);
            split2_pack(p2, p3, ph[ks][half * 2 + 1], pl[ks][half * 2 + 1]);
        }
        sum0 += __shfl_xor_sync(0xffffffffu, sum0, 1);
        sum0 += __shfl_xor_sync(0xffffffffu, sum0, 2);
        sum1 += __shfl_xor_sync(0xffffffffu, sum1, 1);
        sum1 += __shfl_xor_sync(0xffffffffu, sum1, 2);

        l0r = l0r * alpha0 + sum0;
        l1r = l1r * alpha1 + sum1;
        m0r = mn0; m1r = mn1;

        // rescale O
#pragma unroll
        for (int nt = 0; nt < 16; nt++) {
            o[nt][0] *= alpha0; o[nt][1] *= alpha0;
            o[nt][2] *= alpha1; o[nt][3] *= alpha1;
        }

        // --- P@V (bf16 3-split): 4 k16 steps x full d=128 ---
#pragma unroll
        for (int ks = 0; ks < 4; ks++) {
            const int kb = ks * 8;      // pair-row base
#pragma unroll
            for (int nt = 0; nt < 16; nt++) {
                const int nc = nt * 8 + g;
                uint32_t bhv[2], blv[2];
                bhv[0] = Vhi[(kb + cq) * VPK_STRIDE + nc];
                bhv[1] = Vhi[(kb + cq + 4) * VPK_STRIDE + nc];
                blv[0] = Vlo[(kb + cq) * VPK_STRIDE + nc];
                blv[1] = Vlo[(kb + cq + 4) * VPK_STRIDE + nc];
                mma_bf16(o[nt], ph[ks], bhv);
                mma_bf16(o[nt], ph[ks], blv);
                mma_bf16(o[nt], pl[ks], bhv);
            }
        }
        __syncthreads();

        // --- write staged K/V for next tile ---
        if (has_next) {
#pragma unroll
            for (int p = 0; p < 8; p++) {
                int e = tid + p * ATT_THREADS;
                int r = e >> 5;
                int c = (e & 31) << 2;
                *reinterpret_cast<float4*>(&Ks[r * QS_STRIDE + c]) = kst[p];
            }
#pragma unroll
            for (int p = 0; p < 4; p++) {
                int e = tid + p * ATT_THREADS;
                int sp = e >> 5;
                int c  = (e & 31) << 2;
                *reinterpret_cast<uint4*>(&Vhi[sp * VPK_STRIDE + c]) = vhst[p];
                *reinterpret_cast<uint4*>(&Vlo[sp * VPK_STRIDE + c]) = vlst[p];
            }
            __syncthreads();
        }
    }

    // Epilogue: O /= l, write ctx as bf16 hi/lo pair words (warp owns rows)
    {
        float li0 = 1.0f / l0r;
        float li1 = 1.0f / l1r;
        int s0r = q0 + mb + g;
        int s1r = s0r + 8;
#pragma unroll
        for (int nt = 0; nt < 16; nt++) {
            int colw = h * (DH / 2) + nt * 4 + cq;
            uint32_t hw0, lw0, hw1, lw1;
            split2_pack(o[nt][0] * li0, o[nt][1] * li0, hw0, lw0);
            split2_pack(o[nt][2] * li1, o[nt][3] * li1, hw1, lw1);
            size_t r0 = ((size_t)s0r * B_SZ + b) * HP + colw;
            size_t r1 = ((size_t)s1r * B_SZ + b) * HP + colw;
            gchi[r0] = hw0; gclo[r0] = lw0;
            gchi[r1] = hw1; gclo[r1] = lw1;
        }
    }
}

extern "C" void kernel_launch(void* const* d_in, const int* in_sizes, int n_in,
                              void* d_out, int out_size)
{
    const float* hidden = (const float*)d_in[0];
    const unsigned char* mask = (const unsigned char*)d_in[1];
    const float* W_qkv = (const float*)d_in[2];
    const float* b_qkv = (const float*)d_in[3];
    const float* W_dense = (const float*)d_in[4];
    const float* b_dense = (const float*)d_in[5];
    float* out = (float*)d_out;

    float *qd, *kd, *vd;
    uint32_t *ahi, *alo, *wqhi, *wqlo, *wdhi, *wdlo, *chi, *clo, *vhi, *vlo;
    cudaGetSymbolAddress((void**)&qd,   g_q);
    cudaGetSymbolAddress((void**)&kd,   g_k);
    cudaGetSymbolAddress((void**)&vd,   g_v);
    cudaGetSymbolAddress((void**)&ahi,  g_ahi);
    cudaGetSymbolAddress((void**)&alo,  g_alo);
    cudaGetSymbolAddress((void**)&wqhi, g_wqhi);
    cudaGetSymbolAddress((void**)&wqlo, g_wqlo);
    cudaGetSymbolAddress((void**)&wdhi, g_wdhi);
    cudaGetSymbolAddress((void**)&wdlo, g_wdlo);
    cudaGetSymbolAddress((void**)&chi,  g_chi);
    cudaGetSymbolAddress((void**)&clo,  g_clo);
    cudaGetSymbolAddress((void**)&vhi,  g_vhi);
    cudaGetSymbolAddress((void**)&vlo,  g_vlo);

    cudaFuncSetAttribute(attn_tc,
                         cudaFuncAttributeMaxDynamicSharedMemorySize,
                         ATT_SMEM_BYTES);

    const float* bdt = (out_size >= M_ROWS * H_DIM + H_DIM) ? b_dense : nullptr;

    // 0) Pre-split inputs
    {
        long f4 = (long)M_ROWS * H_DIM / 4;
        presplit_rows<<<(unsigned)((f4 + 255) / 256), 256>>>(hidden, ahi, alo, f4);
        long wq = (long)HP * N3;
        presplit_cols<<<(unsigned)((wq + 255) / 256), 256>>>(W_qkv, wqhi, wqlo, N3, wq);
        long wd = (long)HP * H_DIM;
        presplit_cols<<<(unsigned)((wd + 255) / 256), 256>>>(W_dense, wdhi, wdlo, H_DIM, wd);
    }
    // 1) QKV GEMM + scatter
    {
        dim3 grid(N3 / 128, M_ROWS / 128);
        gemm_tc<<<grid, 256>>>(ahi, alo, wqhi, wqlo, b_qkv, nullptr,
                               qd, kd, vd, nullptr, M_ROWS, N3, H_DIM, 0);
    }
    // 1b) Pre-split V
    {
        long vw = (long)B_SZ * NH * (S_LEN / 2) * DH;
        presplit_cols<<<(unsigned)((vw + 255) / 256), 256>>>(vd, vhi, vlo, DH, vw);
    }
    // 2) Flash attention (FA2 register-resident)
    {
        dim3 grid(S_LEN / 128, B_SZ * NH);
        attn_tc<<<grid, ATT_THREADS, ATT_SMEM_BYTES>>>(mask, qd, kd, vhi, vlo, chi, clo);
    }
    // 3) Dense GEMM -> out (+ folded b_dense tail)
    {
        dim3 grid(H_DIM / 128, M_ROWS / 128);
        gemm_tc<<<grid, 256>>>(chi, clo, wdhi, wdlo, nullptr, out,
                               nullptr, nullptr, nullptr, bdt,
                               M_ROWS, H_DIM, H_DIM, 1);
    }
}

// round 11
// speedup vs baseline: 2.7663x; 1.0373x over previous
#include <cuda_runtime.h>
#include <cuda_bf16.h>
#include <math.h>
#include <stdint.h>

// Problem constants
#define S_LEN 2048
#define B_SZ  2
#define H_DIM 2048
#define NH    16
#define DH    128
#define N3    (3 * H_DIM)          // 6144
#define M_ROWS (S_LEN * B_SZ)      // 4096
#define HP    (H_DIM / 2)          // 1024 pair-words per row
#define MASK_VALUE (-10000.0f)

// fp32 scratch.
// g_q: per bh, per 128-row q-tile, tf32 A-frag order:
//      word = qtile*16384 + ((ks*8 + wm)*32 + lane)*4 + reg   (ks=k8 step 0..15)
// g_k: per bh, per 64-row k-tile, tf32 B-frag order:
//      word = ktile*8192 + ((ks*8 + nt)*32 + lane)*2 + reg
// g_v: linear fp32 [bh][s][d] (input to presplit_v)
__device__ float g_q[B_SZ * NH * S_LEN * DH];
__device__ float g_k[B_SZ * NH * S_LEN * DH];
__device__ float g_v[B_SZ * NH * S_LEN * DH];
// pre-split bf16-pair words
__device__ uint32_t g_ahi[M_ROWS * HP];
__device__ uint32_t g_alo[M_ROWS * HP];
__device__ uint32_t g_wqhi[HP * N3];
__device__ uint32_t g_wqlo[HP * N3];
__device__ uint32_t g_wdhi[HP * H_DIM];
__device__ uint32_t g_wdlo[HP * H_DIM];
__device__ uint32_t g_chi[M_ROWS * HP];
__device__ uint32_t g_clo[M_ROWS * HP];
// g_vhi/lo: per bh, per 64-key tile, bf16 B-frag (n8k16) order:
//      word = ktile*4096 + ((ks*16 + nt)*32 + lane)*2 + reg   (ks=k16 step 0..3)
__device__ uint32_t g_vhi[B_SZ * NH * (S_LEN/2) * DH];
__device__ uint32_t g_vlo[B_SZ * NH * (S_LEN/2) * DH];

// ---------------------------------------------------------------------------
// helpers
// ---------------------------------------------------------------------------
__device__ __forceinline__ float to_tf32(float x)
{
    uint32_t u;
    asm("cvt.rna.tf32.f32 %0, %1;" : "=r"(u) : "f"(x));
    return __uint_as_float(u);
}

__device__ __forceinline__ void mma_tf32(float* c, const uint32_t* a, const uint32_t* b)
{
    asm volatile(
        "mma.sync.aligned.m16n8k8.row.col.f32.tf32.tf32.f32 "
        "{%0,%1,%2,%3}, {%4,%5,%6,%7}, {%8,%9}, {%0,%1,%2,%3};"
        : "+f"(c[0]), "+f"(c[1]), "+f"(c[2]), "+f"(c[3])
        : "r"(a[0]), "r"(a[1]), "r"(a[2]), "r"(a[3]),
          "r"(b[0]), "r"(b[1]));
}

__device__ __forceinline__ void mma_bf16(float* c, const uint32_t* a, const uint32_t* b)
{
    asm volatile(
        "mma.sync.aligned.m16n8k16.row.col.f32.bf16.bf16.f32 "
        "{%0,%1,%2,%3}, {%4,%5,%6,%7}, {%8,%9}, {%0,%1,%2,%3};"
        : "+f"(c[0]), "+f"(c[1]), "+f"(c[2]), "+f"(c[3])
        : "r"(a[0]), "r"(a[1]), "r"(a[2]), "r"(a[3]),
          "r"(b[0]), "r"(b[1]));
}

__device__ __forceinline__ void split2_pack(float x0, float x1,
                                            uint32_t& hi, uint32_t& lo)
{
    __nv_bfloat16 h0 = __float2bfloat16_rn(x0);
    __nv_bfloat16 h1 = __float2bfloat16_rn(x1);
    __nv_bfloat16 l0 = __float2bfloat16_rn(x0 - __bfloat162float(h0));
    __nv_bfloat16 l1 = __float2bfloat16_rn(x1 - __bfloat162float(h1));
    __nv_bfloat162 hp = __halves2bfloat162(h0, h1);
    __nv_bfloat162 lp = __halves2bfloat162(l0, l1);
    hi = *reinterpret_cast<uint32_t*>(&hp);
    lo = *reinterpret_cast<uint32_t*>(&lp);
}

// ---------------------------------------------------------------------------
// Pre-split kernels
// ---------------------------------------------------------------------------
__global__ void presplit_rows(const float* __restrict__ src,
                              uint32_t* __restrict__ hi, uint32_t* __restrict__ lo,
                              long total_f4)
{
    long i = (long)blockIdx.x * blockDim.x + threadIdx.x;
    if (i >= total_f4) return;
    float4 v = reinterpret_cast<const float4*>(src)[i];
    uint32_t h0, l0, h1, l1;
    split2_pack(v.x, v.y, h0, l0);
    split2_pack(v.z, v.w, h1, l1);
    reinterpret_cast<uint2*>(hi)[i] = make_uint2(h0, h1);
    reinterpret_cast<uint2*>(lo)[i] = make_uint2(l0, l1);
}

__global__ void presplit_cols(const float* __restrict__ src,
                              uint32_t* __restrict__ hi, uint32_t* __restrict__ lo,
                              int N, long total_words)
{
    long w = (long)blockIdx.x * blockDim.x + threadIdx.x;
    if (w >= total_words) return;
    long pr = w / N;
    int  n  = (int)(w - pr * N);
    float a = src[(2 * pr) * (long)N + n];
    float b = src[(2 * pr + 1) * (long)N + n];
    uint32_t h, l;
    split2_pack(a, b, h, l);
    hi[w] = h; lo[w] = l;
}

// V: linear fp32 [bh][s][d] -> bf16 hi/lo in B-frag (n8k16) order per 64-key tile.
__global__ void presplit_v_frag(const float* __restrict__ vd,
                                uint32_t* __restrict__ hi, uint32_t* __restrict__ lo,
                                long total_words)
{
    long w = (long)blockIdx.x * blockDim.x + threadIdx.x;
    if (w >= total_words) return;
    // decompose: per bh 131072 words; per tile 4096 words
    long bhw  = w >> 17;               // / 131072
    int  rem  = (int)(w & 131071);
    int  tile = rem >> 12;             // / 4096
    int  r2   = rem & 4095;
    int  reg  = r2 & 1;
    int  t2   = r2 >> 1;
    int  lane = t2 & 31;
    int  t3   = t2 >> 5;
    int  nt   = t3 & 15;
    int  ks   = t3 >> 4;
    int  gt   = lane >> 2;
    int  cqq  = lane & 3;
    int  pwi  = cqq + (reg << 2);
    int  s0   = tile * 64 + (ks * 8 + pwi) * 2;
    int  d    = nt * 8 + gt;
    const float* vb = vd + bhw * (long)S_LEN * DH;
    float a = vb[(size_t)s0 * DH + d];
    float b = vb[(size_t)(s0 + 1) * DH + d];
    uint32_t h, l;
    split2_pack(a, b, h, l);
    hi[w] = h; lo[w] = l;
}

// ---------------------------------------------------------------------------
// Tensor-core GEMM (epilogue mode 0 now scatters q/k into fragment order)
// ---------------------------------------------------------------------------
#define APK_STRIDE 20
#define BPK_STRIDE 136

__global__ __launch_bounds__(256)
void gemm_tc(const uint32_t* __restrict__ Ahi_g, const uint32_t* __restrict__ Alo_g,
             const uint32_t* __restrict__ Bhi_g, const uint32_t* __restrict__ Blo_g,
             const float* __restrict__ bias, float* __restrict__ C,
             float* __restrict__ qd, float* __restrict__ kd, float* __restrict__ vd,
             const float* __restrict__ bdt,
             int M, int N, int K, int mode)
{
    __shared__ uint32_t Ahi[128][APK_STRIDE];
    __shared__ uint32_t Alo[128][APK_STRIDE];
    __shared__ uint32_t Bhi[16][BPK_STRIDE];
    __shared__ uint32_t Blo[16][BPK_STRIDE];

    const int tid  = threadIdx.x;
    const int lane = tid & 31;
    const int warp = tid >> 5;
    const int wm   = warp & 1;
    const int wn   = warp >> 1;
    const int g    = lane >> 2;
    const int cq   = lane & 3;

    const int m0 = blockIdx.y * 128;
    const int n0 = blockIdx.x * 128;
    const int Kp = K >> 1;

    float acc[4][4][4];
#pragma unroll
    for (int mt = 0; mt < 4; mt++)
#pragma unroll
        for (int nt = 0; nt < 4; nt++)
#pragma unroll
            for (int r = 0; r < 4; r++) acc[mt][nt][r] = 0.0f;

    const int arw = tid >> 3;
    const int akp = (tid & 7) << 1;
    const int bpr = tid >> 5;
    const int bnc = (tid & 31) << 2;

    for (int k0p = 0; k0p < Kp; k0p += 16) {
#pragma unroll
        for (int p = 0; p < 4; p++) {
            int m = arw + p * 32;
            size_t ai = (size_t)(m0 + m) * Kp + k0p + akp;
            uint2 h = *reinterpret_cast<const uint2*>(&Ahi_g[ai]);
            uint2 l = *reinterpret_cast<const uint2*>(&Alo_g[ai]);
            *reinterpret_cast<uint2*>(&Ahi[m][akp]) = h;
            *reinterpret_cast<uint2*>(&Alo[m][akp]) = l;
        }
#pragma unroll
        for (int p = 0; p < 2; p++) {
            int pr = bpr + p * 8;
            size_t bi = (size_t)(k0p + pr) * N + n0 + bnc;
            uint4 h = *reinterpret_cast<const uint4*>(&Bhi_g[bi]);
            uint4 l = *reinterpret_cast<const uint4*>(&Blo_g[bi]);
            *reinterpret_cast<uint4*>(&Bhi[pr][bnc]) = h;
            *reinterpret_cast<uint4*>(&Blo[pr][bnc]) = l;
        }
        __syncthreads();

#pragma unroll
        for (int kk = 0; kk < 2; kk++) {
            const int kb = kk * 8;
            uint32_t ah[4][4], al[4][4];
#pragma unroll
            for (int mt = 0; mt < 4; mt++) {
                const int mb = wm * 64 + mt * 16;
                ah[mt][0] = Ahi[mb + g][kb + cq];
                ah[mt][1] = Ahi[mb + g + 8][kb + cq];
                ah[mt][2] = Ahi[mb + g][kb + cq + 4];
                ah[mt][3] = Ahi[mb + g + 8][kb + cq + 4];
                al[mt][0] = Alo[mb + g][kb + cq];
                al[mt][1] = Alo[mb + g + 8][kb + cq];
                al[mt][2] = Alo[mb + g][kb + cq + 4];
                al[mt][3] = Alo[mb + g + 8][kb + cq + 4];
            }
            uint32_t bh[4][2], bl[4][2];
#pragma unroll
            for (int nt = 0; nt < 4; nt++) {
                const int nb = wn * 32 + nt * 8;
                bh[nt][0] = Bhi[kb + cq][nb + g];
                bh[nt][1] = Bhi[kb + cq + 4][nb + g];
                bl[nt][0] = Blo[kb + cq][nb + g];
                bl[nt][1] = Blo[kb + cq + 4][nb + g];
            }
#pragma unroll
            for (int mt = 0; mt < 4; mt++)
#pragma unroll
                for (int nt = 0; nt < 4; nt++) {
                    mma_bf16(acc[mt][nt], ah[mt], bh[nt]);
                    mma_bf16(acc[mt][nt], ah[mt], bl[nt]);
                    mma_bf16(acc[mt][nt], al[mt], bh[nt]);
                }
        }
        __syncthreads();
    }

    if (mode == 0) {
#pragma unroll
        for (int mt = 0; mt < 4; mt++) {
#pragma unroll
            for (int nt = 0; nt < 4; nt++) {
#pragma unroll
                for (int r = 0; r < 4; r++) {
                    int m = m0 + wm * 64 + mt * 16 + g + ((r >> 1) << 3);
                    int n = n0 + wn * 32 + nt * 8 + 2 * cq + (r & 1);
                    float v = acc[mt][nt][r] + bias[n];
                    int b = m & 1;
                    int s = m >> 1;
                    int head = n / (3 * DH);
                    int rem  = n - head * (3 * DH);
                    int part = rem >> 7;
                    int d    = rem & 127;
                    size_t bhbase = (size_t)(b * NH + head) * S_LEN * DH;
                    int ks = d >> 3, kk = d & 7;
                    if (part == 0) {
                        // q: tf32 A-frag order per 128-row tile
                        int qtile = s >> 7;
                        int wmr   = (s >> 4) & 7;
                        int r16   = s & 15;
                        int lt    = ((r16 & 7) << 2) + (kk & 3);
                        int rg    = (r16 >> 3) + ((kk >> 2) << 1);
                        size_t idx = bhbase + (size_t)qtile * 16384
                                   + (((ks * 8 + wmr) * 32 + lt) << 2) + rg;
                        qd[idx] = to_tf32(v);
                    } else if (part == 1) {
                        // k: tf32 B-frag order per 64-row tile
                        int ktile = s >> 6;
                        int ntk   = (s >> 3) & 7;
                        int lt    = ((s & 7) << 2) + (kk & 3);
                        int rg    = kk >> 2;
                        size_t idx = bhbase + (size_t)ktile * 8192
                                   + (((ks * 8 + ntk) * 32 + lt) << 1) + rg;
                        kd[idx] = to_tf32(v);
                    } else {
                        vd[bhbase + (size_t)s * DH + d] = v;
                    }
                }
            }
        }
    } else {
#pragma unroll
        for (int mt = 0; mt < 4; mt++) {
#pragma unroll
            for (int nt = 0; nt < 4; nt++) {
                int n = n0 + wn * 32 + nt * 8 + 2 * cq;
                int mA = m0 + wm * 64 + mt * 16 + g;
                int mB = mA + 8;
                float2 vA = make_float2(acc[mt][nt][0], acc[mt][nt][1]);
                float2 vB = make_float2(acc[mt][nt][2], acc[mt][nt][3]);
                *reinterpret_cast<float2*>(&C[(size_t)mA * N + n]) = vA;
                *reinterpret_cast<float2*>(&C[(size_t)mB * N + n]) = vB;
            }
        }
        if (bdt && blockIdx.x == 0 && blockIdx.y == 0) {
            for (int i = tid; i < H_DIM; i += 256)
                C[(size_t)M_ROWS * H_DIM + i] = bdt[i];
        }
    }
}

// ---------------------------------------------------------------------------
// Flash attention, FA2 register-resident, FRAGMENT-ORDERED smem (wide LDS).
// Q_TILE=128, 256 threads (8 warps = 8 m-slabs). 2 barriers/tile.
// smem (words): Qf 16384 | Kf 8192 | Vhi 4096 | Vlo 4096  = 131072 B
// ---------------------------------------------------------------------------
#define ATT_THREADS 256
#define AQF_OFF  0
#define AKF_OFF  16384
#define AVH_OFF  24576
#define AVL_OFF  28672
#define ATT_SMEM_BYTES (32768 * 4)

__global__ __launch_bounds__(ATT_THREADS)
void attn_tc(const unsigned char* __restrict__ mask,
             const float* __restrict__ gq, const float* __restrict__ gk,
             const uint32_t* __restrict__ gvhi, const uint32_t* __restrict__ gvlo,
             uint32_t* __restrict__ gchi, uint32_t* __restrict__ gclo)
{
    extern __shared__ uint32_t smw[];
    uint4* Qf4 = reinterpret_cast<uint4*>(smw + AQF_OFF);
    uint2* Kf2 = reinterpret_cast<uint2*>(smw + AKF_OFF);
    uint2* Vh2 = reinterpret_cast<uint2*>(smw + AVH_OFF);
    uint2* Vl2 = reinterpret_cast<uint2*>(smw + AVL_OFF);

    const int tid  = threadIdx.x;
    const int lane = tid & 31;
    const int warp = tid >> 5;          // 0..7 = m-slab
    const int g    = lane >> 2;
    const int cq   = lane & 3;
    const int mb   = warp * 16;

    const int bh = blockIdx.y;
    const int b  = bh / NH;
    const int h  = bh - b * NH;
    const int q0 = blockIdx.x * 128;

    const uint32_t* qw = reinterpret_cast<const uint32_t*>(gq)
                       + (size_t)bh * S_LEN * DH + (size_t)blockIdx.x * 16384;
    const uint32_t* kw = reinterpret_cast<const uint32_t*>(gk)
                       + (size_t)bh * S_LEN * DH;
    const uint32_t* vhp = gvhi + (size_t)bh * (S_LEN / 2) * DH;
    const uint32_t* vlp = gvlo + (size_t)bh * (S_LEN / 2) * DH;
    const unsigned char* mp = mask + (size_t)b * S_LEN * S_LEN;
    const float inv_norm = 1.0f / sqrtf((float)H_DIM);

    // Q tile (frag order, straight copy): 4096 uint4
    {
        const uint4* src = reinterpret_cast<const uint4*>(qw);
#pragma unroll
        for (int p = 0; p < 16; p++)
            Qf4[tid + p * ATT_THREADS] = src[tid + p * ATT_THREADS];
    }
    // K,V tile 0 (frag order, straight copy)
    {
        const uint2* ks = reinterpret_cast<const uint2*>(kw);
#pragma unroll
        for (int p = 0; p < 16; p++)
            Kf2[tid + p * ATT_THREADS] = ks[tid + p * ATT_THREADS];
        const uint2* vh = reinterpret_cast<const uint2*>(vhp);
        const uint2* vl = reinterpret_cast<const uint2*>(vlp);
#pragma unroll
        for (int p = 0; p < 8; p++) {
            Vh2[tid + p * ATT_THREADS] = vh[tid + p * ATT_THREADS];
            Vl2[tid + p * ATT_THREADS] = vl[tid + p * ATT_THREADS];
        }
    }
    __syncthreads();

    float o[16][4];
#pragma unroll
    for (int nt = 0; nt < 16; nt++)
#pragma unroll
        for (int r = 0; r < 4; r++) o[nt][r] = 0.0f;
    float m0r = -INFINITY, m1r = -INFINITY;
    float l0r = 0.0f, l1r = 0.0f;

    const unsigned char* mr0 = mp + (size_t)(q0 + mb + g) * S_LEN;
    const unsigned char* mr1 = mp + (size_t)(q0 + mb + g + 8) * S_LEN;

    for (int kt = 0; kt < S_LEN / 64; kt++) {
        const int t0 = kt * 64;
        const bool has_next = (kt + 1 < S_LEN / 64);

        // Stage next K/V tile into registers (frag order = linear copy)
        uint2 kst[16];
        uint2 vhst[8], vlst[8];
        if (has_next) {
            const uint2* ksn = reinterpret_cast<const uint2*>(kw + (size_t)(kt + 1) * 8192);
#pragma unroll
            for (int p = 0; p < 16; p++)
                kst[p] = ksn[tid + p * ATT_THREADS];
            const uint2* vhn = reinterpret_cast<const uint2*>(vhp + (size_t)(kt + 1) * 4096);
            const uint2* vln = reinterpret_cast<const uint2*>(vlp + (size_t)(kt + 1) * 4096);
#pragma unroll
            for (int p = 0; p < 8; p++) {
                vhst[p] = vhn[tid + p * ATT_THREADS];
                vlst[p] = vln[tid + p * ATT_THREADS];
            }
        }

        // --- QK^T (tf32): warp m16 x n64, S in registers ---
        float s[8][4];
#pragma unroll
        for (int nt = 0; nt < 8; nt++)
#pragma unroll
            for (int r = 0; r < 4; r++) s[nt][r] = 0.0f;

#pragma unroll
        for (int ks = 0; ks < 16; ks++) {
            uint4 aq = Qf4[(ks * 8 + warp) * 32 + lane];
#pragma unroll
            for (int nt = 0; nt < 8; nt++) {
                uint2 bk = Kf2[(ks * 8 + nt) * 32 + lane];
                mma_tf32(s[nt], reinterpret_cast<uint32_t*>(&aq),
                         reinterpret_cast<uint32_t*>(&bk));
            }
        }

        // --- scale + mask ---
        float pmax0 = -INFINITY, pmax1 = -INFINITY;
#pragma unroll
        for (int nt = 0; nt < 8; nt++) {
            int cc = t0 + nt * 8 + 2 * cq;
            uchar2 mk0 = *reinterpret_cast<const uchar2*>(mr0 + cc);
            uchar2 mk1 = *reinterpret_cast<const uchar2*>(mr1 + cc);
            float v0 = s[nt][0] * inv_norm; if (mk0.x) v0 = MASK_VALUE;
            float v1 = s[nt][1] * inv_norm; if (mk0.y) v1 = MASK_VALUE;
            float v2 = s[nt][2] * inv_norm; if (mk1.x) v2 = MASK_VALUE;
            float v3 = s[nt][3] * inv_norm; if (mk1.y) v3 = MASK_VALUE;
            s[nt][0] = v0; s[nt][1] = v1; s[nt][2] = v2; s[nt][3] = v3;
            pmax0 = fmaxf(pmax0, fmaxf(v0, v1));
            pmax1 = fmaxf(pmax1, fmaxf(v2, v3));
        }
        pmax0 = fmaxf(pmax0, __shfl_xor_sync(0xffffffffu, pmax0, 1));
        pmax0 = fmaxf(pmax0, __shfl_xor_sync(0xffffffffu, pmax0, 2));
        pmax1 = fmaxf(pmax1, __shfl_xor_sync(0xffffffffu, pmax1, 1));
        pmax1 = fmaxf(pmax1, __shfl_xor_sync(0xffffffffu, pmax1, 2));

        float mn0 = fmaxf(m0r, pmax0);
        float mn1 = fmaxf(m1r, pmax1);
        float alpha0 = __expf(m0r - mn0);
        float alpha1 = __expf(m1r - mn1);

        uint32_t ph[4][4], pl[4][4];
        float sum0 = 0.0f, sum1 = 0.0f;
#pragma unroll
        for (int nt = 0; nt < 8; nt++) {
            float p0 = __expf(s[nt][0] - mn0);
            float p1 = __expf(s[nt][1] - mn0);
            float p2 = __expf(s[nt][2] - mn1);
            float p3 = __expf(s[nt][3] - mn1);
            sum0 += p0 + p1;
            sum1 += p2 + p3;
            int ks  = nt >> 1;
            int half = nt & 1;
            split2_pack(p0, p1, ph[ks][half * 2 + 0], pl[ks][half * 2 + 0]);
            split2_pack(p2, p3, ph[ks][half * 2 + 1], pl[ks][half * 2 + 1]);
        }
        sum0 += __shfl_xor_sync(0xffffffffu, sum0, 1);
        sum0 += __shfl_xor_sync(0xffffffffu, sum0, 2);
        sum1 += __shfl_xor_sync(0xffffffffu, sum1, 1);
        sum1 += __shfl_xor_sync(0xffffffffu, sum1, 2);

        l0r = l0r * alpha0 + sum0;
        l1r = l1r * alpha1 + sum1;
        m0r = mn0; m1r = mn1;

#pragma unroll
        for (int nt = 0; nt < 16; nt++) {
            o[nt][0] *= alpha0; o[nt][1] *= alpha0;
            o[nt][2] *= alpha1; o[nt][3] *= alpha1;
        }

        // --- P@V (bf16 3-split), V frag-ordered ---
#pragma unroll
        for (int ks = 0; ks < 4; ks++) {
#pragma unroll
            for (int nt = 0; nt < 16; nt++) {
                uint2 bhv = Vh2[(ks * 16 + nt) * 32 + lane];
                uint2 blv = Vl2[(ks * 16 + nt) * 32 + lane];
                mma_bf16(o[nt], ph[ks], reinterpret_cast<uint32_t*>(&bhv));
                mma_bf16(o[nt], ph[ks], reinterpret_cast<uint32_t*>(&blv));
                mma_bf16(o[nt], pl[ks], reinterpret_cast<uint32_t*>(&bhv));
            }
        }
        __syncthreads();

        if (has_next) {
#pragma unroll
            for (int p = 0; p < 16; p++)
                Kf2[tid + p * ATT_THREADS] = kst[p];
#pragma unroll
            for (int p = 0; p < 8; p++) {
                Vh2[tid + p * ATT_THREADS] = vhst[p];
                Vl2[tid + p * ATT_THREADS] = vlst[p];
            }
            __syncthreads();
        }
    }

    // Epilogue: O /= l, write ctx as bf16 hi/lo pair words
    {
        float li0 = 1.0f / l0r;
        float li1 = 1.0f / l1r;
        int s0r = q0 + mb + g;
        int s1r = s0r + 8;
#pragma unroll
        for (int nt = 0; nt < 16; nt++) {
            int colw = h * (DH / 2) + nt * 4 + cq;
            uint32_t hw0, lw0, hw1, lw1;
            split2_pack(o[nt][0] * li0, o[nt][1] * li0, hw0, lw0);
            split2_pack(o[nt][2] * li1, o[nt][3] * li1, hw1, lw1);
            size_t r0 = ((size_t)s0r * B_SZ + b) * HP + colw;
            size_t r1 = ((size_t)s1r * B_SZ + b) * HP + colw;
            gchi[r0] = hw0; gclo[r0] = lw0;
            gchi[r1] = hw1; gclo[r1] = lw1;
        }
    }
}

extern "C" void kernel_launch(void* const* d_in, const int* in_sizes, int n_in,
                              void* d_out, int out_size)
{
    const float* hidden = (const float*)d_in[0];
    const unsigned char* mask = (const unsigned char*)d_in[1];
    const float* W_qkv = (const float*)d_in[2];
    const float* b_qkv = (const float*)d_in[3];
    const float* W_dense = (const float*)d_in[4];
    const float* b_dense = (const float*)d_in[5];
    float* out = (float*)d_out;

    float *qd, *kd, *vd;
    uint32_t *ahi, *alo, *wqhi, *wqlo, *wdhi, *wdlo, *chi, *clo, *vhi, *vlo;
    cudaGetSymbolAddress((void**)&qd,   g_q);
    cudaGetSymbolAddress((void**)&kd,   g_k);
    cudaGetSymbolAddress((void**)&vd,   g_v);
    cudaGetSymbolAddress((void**)&ahi,  g_ahi);
    cudaGetSymbolAddress((void**)&alo,  g_alo);
    cudaGetSymbolAddress((void**)&wqhi, g_wqhi);
    cudaGetSymbolAddress((void**)&wqlo, g_wqlo);
    cudaGetSymbolAddress((void**)&wdhi, g_wdhi);
    cudaGetSymbolAddress((void**)&wdlo, g_wdlo);
    cudaGetSymbolAddress((void**)&chi,  g_chi);
    cudaGetSymbolAddress((void**)&clo,  g_clo);
    cudaGetSymbolAddress((void**)&vhi,  g_vhi);
    cudaGetSymbolAddress((void**)&vlo,  g_vlo);

    cudaFuncSetAttribute(attn_tc,
                         cudaFuncAttributeMaxDynamicSharedMemorySize,
                         ATT_SMEM_BYTES);

    const float* bdt = (out_size >= M_ROWS * H_DIM + H_DIM) ? b_dense : nullptr;

    // 0) Pre-split inputs
    {
        long f4 = (long)M_ROWS * H_DIM / 4;
        presplit_rows<<<(unsigned)((f4 + 255) / 256), 256>>>(hidden, ahi, alo, f4);
        long wq = (long)HP * N3;
        presplit_cols<<<(unsigned)((wq + 255) / 256), 256>>>(W_qkv, wqhi, wqlo, N3, wq);
        long wd = (long)HP * H_DIM;
        presplit_cols<<<(unsigned)((wd + 255) / 256), 256>>>(W_dense, wdhi, wdlo, H_DIM, wd);
    }
    // 1) QKV GEMM + scatter (q,k in frag order; v linear)
    {
        dim3 grid(N3 / 128, M_ROWS / 128);
        gemm_tc<<<grid, 256>>>(ahi, alo, wqhi, wqlo, b_qkv, nullptr,
                               qd, kd, vd, nullptr, M_ROWS, N3, H_DIM, 0);
    }
    // 1b) Pre-split V into frag order
    {
        long vw = (long)B_SZ * NH * (S_LEN / 2) * DH;
        presplit_v_frag<<<(unsigned)((vw + 255) / 256), 256>>>(vd, vhi, vlo, vw);
    }
    // 2) Flash attention
    {
        dim3 grid(S_LEN / 128, B_SZ * NH);
        attn_tc<<<grid, ATT_THREADS, ATT_SMEM_BYTES>>>(mask, qd, kd, vhi, vlo, chi, clo);
    }
    // 3) Dense GEMM -> out (+ folded b_dense tail)
    {
        dim3 grid(H_DIM / 128, M_ROWS / 128);
        gemm_tc<<<grid, 256>>>(chi, clo, wdhi, wdlo, nullptr, out,
                               nullptr, nullptr, nullptr, bdt,
                               M_ROWS, H_DIM, H_DIM, 1);
    }
}

// round 12
// speedup vs baseline: 2.8330x; 1.0241x over previous
#include <cuda_runtime.h>
#include <cuda_bf16.h>
#include <math.h>
#include <stdint.h>

// Problem constants
#define S_LEN 2048
#define B_SZ  2
#define H_DIM 2048
#define NH    16
#define DH    128
#define N3    (3 * H_DIM)          // 6144
#define M_ROWS (S_LEN * B_SZ)      // 4096
#define HP    (H_DIM / 2)          // 1024 pair-words per row
#define MASK_VALUE (-10000.0f)

// fp32 scratch.
// g_q: per bh, per 128-row q-tile, tf32 A-frag order
// g_k: per bh, per 64-row k-tile, tf32 B-frag order
// g_v: linear fp32 [bh][s][d]
__device__ float g_q[B_SZ * NH * S_LEN * DH];
__device__ float g_k[B_SZ * NH * S_LEN * DH];
__device__ float g_v[B_SZ * NH * S_LEN * DH];
// pre-split bf16-pair words
__device__ uint32_t g_ahi[M_ROWS * HP];
__device__ uint32_t g_alo[M_ROWS * HP];
__device__ uint32_t g_wqhi[HP * N3];
__device__ uint32_t g_wqlo[HP * N3];
__device__ uint32_t g_wdhi[HP * H_DIM];
__device__ uint32_t g_wdlo[HP * H_DIM];
__device__ uint32_t g_chi[M_ROWS * HP];
__device__ uint32_t g_clo[M_ROWS * HP];
// v in bf16 B-frag (n8k16) order per 64-key tile
__device__ uint32_t g_vhi[B_SZ * NH * (S_LEN/2) * DH];
__device__ uint32_t g_vlo[B_SZ * NH * (S_LEN/2) * DH];

// ---------------------------------------------------------------------------
// helpers
// ---------------------------------------------------------------------------
__device__ __forceinline__ float to_tf32(float x)
{
    uint32_t u;
    asm("cvt.rna.tf32.f32 %0, %1;" : "=r"(u) : "f"(x));
    return __uint_as_float(u);
}

__device__ __forceinline__ void mma_tf32(float* c, const uint32_t* a, const uint32_t* b)
{
    asm volatile(
        "mma.sync.aligned.m16n8k8.row.col.f32.tf32.tf32.f32 "
        "{%0,%1,%2,%3}, {%4,%5,%6,%7}, {%8,%9}, {%0,%1,%2,%3};"
        : "+f"(c[0]), "+f"(c[1]), "+f"(c[2]), "+f"(c[3])
        : "r"(a[0]), "r"(a[1]), "r"(a[2]), "r"(a[3]),
          "r"(b[0]), "r"(b[1]));
}

__device__ __forceinline__ void mma_bf16(float* c, const uint32_t* a, const uint32_t* b)
{
    asm volatile(
        "mma.sync.aligned.m16n8k16.row.col.f32.bf16.bf16.f32 "
        "{%0,%1,%2,%3}, {%4,%5,%6,%7}, {%8,%9}, {%0,%1,%2,%3};"
        : "+f"(c[0]), "+f"(c[1]), "+f"(c[2]), "+f"(c[3])
        : "r"(a[0]), "r"(a[1]), "r"(a[2]), "r"(a[3]),
          "r"(b[0]), "r"(b[1]));
}

__device__ __forceinline__ void split2_pack(float x0, float x1,
                                            uint32_t& hi, uint32_t& lo)
{
    __nv_bfloat16 h0 = __float2bfloat16_rn(x0);
    __nv_bfloat16 h1 = __float2bfloat16_rn(x1);
    __nv_bfloat16 l0 = __float2bfloat16_rn(x0 - __bfloat162float(h0));
    __nv_bfloat16 l1 = __float2bfloat16_rn(x1 - __bfloat162float(h1));
    __nv_bfloat162 hp = __halves2bfloat162(h0, h1);
    __nv_bfloat162 lp = __halves2bfloat162(l0, l1);
    hi = *reinterpret_cast<uint32_t*>(&hp);
    lo = *reinterpret_cast<uint32_t*>(&lp);
}

__device__ __forceinline__ void cp_async16(uint32_t smem_addr, const void* gptr)
{
    asm volatile("cp.async.cg.shared.global [%0], [%1], 16;"
                 :: "r"(smem_addr), "l"(gptr));
}
#define CP_COMMIT() asm volatile("cp.async.commit_group;")
#define CP_WAIT1()  asm volatile("cp.async.wait_group 1;")
#define CP_WAIT0()  asm volatile("cp.async.wait_group 0;")

// ---------------------------------------------------------------------------
// Pre-split kernels
// ---------------------------------------------------------------------------
__global__ void presplit_rows(const float* __restrict__ src,
                              uint32_t* __restrict__ hi, uint32_t* __restrict__ lo,
                              long total_f4)
{
    long i = (long)blockIdx.x * blockDim.x + threadIdx.x;
    if (i >= total_f4) return;
    float4 v = reinterpret_cast<const float4*>(src)[i];
    uint32_t h0, l0, h1, l1;
    split2_pack(v.x, v.y, h0, l0);
    split2_pack(v.z, v.w, h1, l1);
    reinterpret_cast<uint2*>(hi)[i] = make_uint2(h0, h1);
    reinterpret_cast<uint2*>(lo)[i] = make_uint2(l0, l1);
}

__global__ void presplit_cols(const float* __restrict__ src,
                              uint32_t* __restrict__ hi, uint32_t* __restrict__ lo,
                              int N, long total_words)
{
    long w = (long)blockIdx.x * blockDim.x + threadIdx.x;
    if (w >= total_words) return;
    long pr = w / N;
    int  n  = (int)(w - pr * N);
    float a = src[(2 * pr) * (long)N + n];
    float b = src[(2 * pr + 1) * (long)N + n];
    uint32_t h, l;
    split2_pack(a, b, h, l);
    hi[w] = h; lo[w] = l;
}

// V: linear fp32 [bh][s][d] -> bf16 hi/lo in B-frag (n8k16) order per 64-key tile.
__global__ void presplit_v_frag(const float* __restrict__ vd,
                                uint32_t* __restrict__ hi, uint32_t* __restrict__ lo,
                                long total_words)
{
    long w = (long)blockIdx.x * blockDim.x + threadIdx.x;
    if (w >= total_words) return;
    long bhw  = w >> 17;
    int  rem  = (int)(w & 131071);
    int  tile = rem >> 12;
    int  r2   = rem & 4095;
    int  reg  = r2 & 1;
    int  t2   = r2 >> 1;
    int  lane = t2 & 31;
    int  t3   = t2 >> 5;
    int  nt   = t3 & 15;
    int  ks   = t3 >> 4;
    int  gt   = lane >> 2;
    int  cqq  = lane & 3;
    int  pwi  = cqq + (reg << 2);
    int  s0   = tile * 64 + (ks * 8 + pwi) * 2;
    int  d    = nt * 8 + gt;
    const float* vb = vd + bhw * (long)S_LEN * DH;
    float a = vb[(size_t)s0 * DH + d];
    float b = vb[(size_t)(s0 + 1) * DH + d];
    uint32_t h, l;
    split2_pack(a, b, h, l);
    hi[w] = h; lo[w] = l;
}

// ---------------------------------------------------------------------------
// Tensor-core GEMM (unchanged from R11)
// ---------------------------------------------------------------------------
#define APK_STRIDE 20
#define BPK_STRIDE 136

__global__ __launch_bounds__(256)
void gemm_tc(const uint32_t* __restrict__ Ahi_g, const uint32_t* __restrict__ Alo_g,
             const uint32_t* __restrict__ Bhi_g, const uint32_t* __restrict__ Blo_g,
             const float* __restrict__ bias, float* __restrict__ C,
             float* __restrict__ qd, float* __restrict__ kd, float* __restrict__ vd,
             const float* __restrict__ bdt,
             int M, int N, int K, int mode)
{
    __shared__ uint32_t Ahi[128][APK_STRIDE];
    __shared__ uint32_t Alo[128][APK_STRIDE];
    __shared__ uint32_t Bhi[16][BPK_STRIDE];
    __shared__ uint32_t Blo[16][BPK_STRIDE];

    const int tid  = threadIdx.x;
    const int lane = tid & 31;
    const int warp = tid >> 5;
    const int wm   = warp & 1;
    const int wn   = warp >> 1;
    const int g    = lane >> 2;
    const int cq   = lane & 3;

    const int m0 = blockIdx.y * 128;
    const int n0 = blockIdx.x * 128;
    const int Kp = K >> 1;

    float acc[4][4][4];
#pragma unroll
    for (int mt = 0; mt < 4; mt++)
#pragma unroll
        for (int nt = 0; nt < 4; nt++)
#pragma unroll
            for (int r = 0; r < 4; r++) acc[mt][nt][r] = 0.0f;

    const int arw = tid >> 3;
    const int akp = (tid & 7) << 1;
    const int bpr = tid >> 5;
    const int bnc = (tid & 31) << 2;

    for (int k0p = 0; k0p < Kp; k0p += 16) {
#pragma unroll
        for (int p = 0; p < 4; p++) {
            int m = arw + p * 32;
            size_t ai = (size_t)(m0 + m) * Kp + k0p + akp;
            uint2 h = *reinterpret_cast<const uint2*>(&Ahi_g[ai]);
            uint2 l = *reinterpret_cast<const uint2*>(&Alo_g[ai]);
            *reinterpret_cast<uint2*>(&Ahi[m][akp]) = h;
            *reinterpret_cast<uint2*>(&Alo[m][akp]) = l;
        }
#pragma unroll
        for (int p = 0; p < 2; p++) {
            int pr = bpr + p * 8;
            size_t bi = (size_t)(k0p + pr) * N + n0 + bnc;
            uint4 h = *reinterpret_cast<const uint4*>(&Bhi_g[bi]);
            uint4 l = *reinterpret_cast<const uint4*>(&Blo_g[bi]);
            *reinterpret_cast<uint4*>(&Bhi[pr][bnc]) = h;
            *reinterpret_cast<uint4*>(&Blo[pr][bnc]) = l;
        }
        __syncthreads();

#pragma unroll
        for (int kk = 0; kk < 2; kk++) {
            const int kb = kk * 8;
            uint32_t ah[4][4], al[4][4];
#pragma unroll
            for (int mt = 0; mt < 4; mt++) {
                const int mb = wm * 64 + mt * 16;
                ah[mt][0] = Ahi[mb + g][kb + cq];
                ah[mt][1] = Ahi[mb + g + 8][kb + cq];
                ah[mt][2] = Ahi[mb + g][kb + cq + 4];
                ah[mt][3] = Ahi[mb + g + 8][kb + cq + 4];
                al[mt][0] = Alo[mb + g][kb + cq];
                al[mt][1] = Alo[mb + g + 8][kb + cq];
                al[mt][2] = Alo[mb + g][kb + cq + 4];
                al[mt][3] = Alo[mb + g + 8][kb + cq + 4];
            }
            uint32_t bh[4][2], bl[4][2];
#pragma unroll
            for (int nt = 0; nt < 4; nt++) {
                const int nb = wn * 32 + nt * 8;
                bh[nt][0] = Bhi[kb + cq][nb + g];
                bh[nt][1] = Bhi[kb + cq + 4][nb + g];
                bl[nt][0] = Blo[kb + cq][nb + g];
                bl[nt][1] = Blo[kb + cq + 4][nb + g];
            }
#pragma unroll
            for (int mt = 0; mt < 4; mt++)
#pragma unroll
                for (int nt = 0; nt < 4; nt++) {
                    mma_bf16(acc[mt][nt], ah[mt], bh[nt]);
                    mma_bf16(acc[mt][nt], ah[mt], bl[nt]);
                    mma_bf16(acc[mt][nt], al[mt], bh[nt]);
                }
        }
        __syncthreads();
    }

    if (mode == 0) {
#pragma unroll
        for (int mt = 0; mt < 4; mt++) {
#pragma unroll
            for (int nt = 0; nt < 4; nt++) {
#pragma unroll
                for (int r = 0; r < 4; r++) {
                    int m = m0 + wm * 64 + mt * 16 + g + ((r >> 1) << 3);
                    int n = n0 + wn * 32 + nt * 8 + 2 * cq + (r & 1);
                    float v = acc[mt][nt][r] + bias[n];
                    int b = m & 1;
                    int s = m >> 1;
                    int head = n / (3 * DH);
                    int rem  = n - head * (3 * DH);
                    int part = rem >> 7;
                    int d    = rem & 127;
                    size_t bhbase = (size_t)(b * NH + head) * S_LEN * DH;
                    int ks = d >> 3, kk = d & 7;
                    if (part == 0) {
                        int qtile = s >> 7;
                        int wmr   = (s >> 4) & 7;
                        int r16   = s & 15;
                        int lt    = ((r16 & 7) << 2) + (kk & 3);
                        int rg    = (r16 >> 3) + ((kk >> 2) << 1);
                        size_t idx = bhbase + (size_t)qtile * 16384
                                   + (((ks * 8 + wmr) * 32 + lt) << 2) + rg;
                        qd[idx] = to_tf32(v);
                    } else if (part == 1) {
                        int ktile = s >> 6;
                        int ntk   = (s >> 3) & 7;
                        int lt    = ((s & 7) << 2) + (kk & 3);
                        int rg    = kk >> 2;
                        size_t idx = bhbase + (size_t)ktile * 8192
                                   + (((ks * 8 + ntk) * 32 + lt) << 1) + rg;
                        kd[idx] = to_tf32(v);
                    } else {
                        vd[bhbase + (size_t)s * DH + d] = v;
                    }
                }
            }
        }
    } else {
#pragma unroll
        for (int mt = 0; mt < 4; mt++) {
#pragma unroll
            for (int nt = 0; nt < 4; nt++) {
                int n = n0 + wn * 32 + nt * 8 + 2 * cq;
                int mA = m0 + wm * 64 + mt * 16 + g;
                int mB = mA + 8;
                float2 vA = make_float2(acc[mt][nt][0], acc[mt][nt][1]);
                float2 vB = make_float2(acc[mt][nt][2], acc[mt][nt][3]);
                *reinterpret_cast<float2*>(&C[(size_t)mA * N + n]) = vA;
                *reinterpret_cast<float2*>(&C[(size_t)mB * N + n]) = vB;
            }
        }
        if (bdt && blockIdx.x == 0 && blockIdx.y == 0) {
            for (int i = tid; i < H_DIM; i += 256)
                C[(size_t)M_ROWS * H_DIM + i] = bdt[i];
        }
    }
}

// ---------------------------------------------------------------------------
// Flash attention: FA2 register-resident S/P/m/l, frag-ordered smem,
// cp.async double-buffered K/V (no register staging). 256 threads.
// smem words: Qf 16384 | Kf 2x8192 | Vhi 2x4096 | Vlo 2x4096 = 49152 (192KB)
// ---------------------------------------------------------------------------
#define ATT_THREADS 256
#define AQF_OFF  0
#define AKF_OFF  16384
#define AVH_OFF  32768
#define AVL_OFF  40960
#define ATT_SMEM_BYTES (49152 * 4)

__global__ __launch_bounds__(ATT_THREADS)
void attn_tc(const unsigned char* __restrict__ mask,
             const float* __restrict__ gq, const float* __restrict__ gk,
             const uint32_t* __restrict__ gvhi, const uint32_t* __restrict__ gvlo,
             uint32_t* __restrict__ gchi, uint32_t* __restrict__ gclo)
{
    extern __shared__ uint32_t smw[];
    uint4* Qf4 = reinterpret_cast<uint4*>(smw + AQF_OFF);

    const int tid  = threadIdx.x;
    const int lane = tid & 31;
    const int warp = tid >> 5;
    const int g    = lane >> 2;
    const int cq   = lane & 3;
    const int mb   = warp * 16;

    const int bh = blockIdx.y;
    const int b  = bh / NH;
    const int h  = bh - b * NH;
    const int q0 = blockIdx.x * 128;

    const uint32_t* qw = reinterpret_cast<const uint32_t*>(gq)
                       + (size_t)bh * S_LEN * DH + (size_t)blockIdx.x * 16384;
    const uint32_t* kw = reinterpret_cast<const uint32_t*>(gk)
                       + (size_t)bh * S_LEN * DH;
    const uint32_t* vhp = gvhi + (size_t)bh * (S_LEN / 2) * DH;
    const uint32_t* vlp = gvlo + (size_t)bh * (S_LEN / 2) * DH;
    const unsigned char* mp = mask + (size_t)b * S_LEN * S_LEN;
    const float inv_norm = 1.0f / sqrtf((float)H_DIM);

    // cp.async tile loader: K tile (2048 uint4) + Vhi/Vlo (1024 uint4 each)
    auto issue_tile = [&](int kt, int buf) {
        const uint4* ksn = reinterpret_cast<const uint4*>(kw + (size_t)kt * 8192);
        uint32_t kb = (uint32_t)__cvta_generic_to_shared(smw + AKF_OFF + buf * 8192)
                    + tid * 16;
#pragma unroll
        for (int p = 0; p < 8; p++)
            cp_async16(kb + p * ATT_THREADS * 16, &ksn[tid + p * ATT_THREADS]);
        const uint4* vhn = reinterpret_cast<const uint4*>(vhp + (size_t)kt * 4096);
        const uint4* vln = reinterpret_cast<const uint4*>(vlp + (size_t)kt * 4096);
        uint32_t vhb = (uint32_t)__cvta_generic_to_shared(smw + AVH_OFF + buf * 4096)
                     + tid * 16;
        uint32_t vlb = (uint32_t)__cvta_generic_to_shared(smw + AVL_OFF + buf * 4096)
                     + tid * 16;
#pragma unroll
        for (int p = 0; p < 4; p++) {
            cp_async16(vhb + p * ATT_THREADS * 16, &vhn[tid + p * ATT_THREADS]);
            cp_async16(vlb + p * ATT_THREADS * 16, &vln[tid + p * ATT_THREADS]);
        }
    };

    // Prologue: async-load tiles 0 and 1; load Q synchronously.
    issue_tile(0, 0); CP_COMMIT();
    issue_tile(1, 1); CP_COMMIT();
    {
        const uint4* src = reinterpret_cast<const uint4*>(qw);
#pragma unroll
        for (int p = 0; p < 16; p++)
            Qf4[tid + p * ATT_THREADS] = src[tid + p * ATT_THREADS];
    }
    CP_WAIT1();            // tile 0 complete
    __syncthreads();

    float o[16][4];
#pragma unroll
    for (int nt = 0; nt < 16; nt++)
#pragma unroll
        for (int r = 0; r < 4; r++) o[nt][r] = 0.0f;
    float m0r = -INFINITY, m1r = -INFINITY;
    float l0r = 0.0f, l1r = 0.0f;

    const unsigned char* mr0 = mp + (size_t)(q0 + mb + g) * S_LEN;
    const unsigned char* mr1 = mp + (size_t)(q0 + mb + g + 8) * S_LEN;

    const int NT = S_LEN / 64;
    for (int kt = 0; kt < NT; kt++) {
        const int t0 = kt * 64;
        const int buf = kt & 1;
        const uint2* Kf2 = reinterpret_cast<const uint2*>(smw + AKF_OFF + buf * 8192);
        const uint2* Vh2 = reinterpret_cast<const uint2*>(smw + AVH_OFF + buf * 4096);
        const uint2* Vl2 = reinterpret_cast<const uint2*>(smw + AVL_OFF + buf * 4096);

        // Hoist mask loads so LDG latency hides under the QK mma block
        uchar2 mk0[8], mk1[8];
#pragma unroll
        for (int nt = 0; nt < 8; nt++) {
            int cc = t0 + nt * 8 + 2 * cq;
            mk0[nt] = *reinterpret_cast<const uchar2*>(mr0 + cc);
            mk1[nt] = *reinterpret_cast<const uchar2*>(mr1 + cc);
        }

        // --- QK^T (tf32): warp m16 x n64, S in registers ---
        float s[8][4];
#pragma unroll
        for (int nt = 0; nt < 8; nt++)
#pragma unroll
            for (int r = 0; r < 4; r++) s[nt][r] = 0.0f;

#pragma unroll
        for (int ks = 0; ks < 16; ks++) {
            uint4 aq = Qf4[(ks * 8 + warp) * 32 + lane];
#pragma unroll
            for (int nt = 0; nt < 8; nt++) {
                uint2 bk = Kf2[(ks * 8 + nt) * 32 + lane];
                mma_tf32(s[nt], reinterpret_cast<uint32_t*>(&aq),
                         reinterpret_cast<uint32_t*>(&bk));
            }
        }

        // --- scale + mask (from prefetched regs) ---
        float pmax0 = -INFINITY, pmax1 = -INFINITY;
#pragma unroll
        for (int nt = 0; nt < 8; nt++) {
            float v0 = s[nt][0] * inv_norm; if (mk0[nt].x) v0 = MASK_VALUE;
            float v1 = s[nt][1] * inv_norm; if (mk0[nt].y) v1 = MASK_VALUE;
            float v2 = s[nt][2] * inv_norm; if (mk1[nt].x) v2 = MASK_VALUE;
            float v3 = s[nt][3] * inv_norm; if (mk1[nt].y) v3 = MASK_VALUE;
            s[nt][0] = v0; s[nt][1] = v1; s[nt][2] = v2; s[nt][3] = v3;
            pmax0 = fmaxf(pmax0, fmaxf(v0, v1));
            pmax1 = fmaxf(pmax1, fmaxf(v2, v3));
        }
        pmax0 = fmaxf(pmax0, __shfl_xor_sync(0xffffffffu, pmax0, 1));
        pmax0 = fmaxf(pmax0, __shfl_xor_sync(0xffffffffu, pmax0, 2));
        pmax1 = fmaxf(pmax1, __shfl_xor_sync(0xffffffffu, pmax1, 1));
        pmax1 = fmaxf(pmax1, __shfl_xor_sync(0xffffffffu, pmax1, 2));

        float mn0 = fmaxf(m0r, pmax0);
        float mn1 = fmaxf(m1r, pmax1);
        float alpha0 = __expf(m0r - mn0);
        float alpha1 = __expf(m1r - mn1);

        uint32_t ph[4][4], pl[4][4];
        float sum0 = 0.0f, sum1 = 0.0f;
#pragma unroll
        for (int nt = 0; nt < 8; nt++) {
            float p0 = __expf(s[nt][0] - mn0);
            float p1 = __expf(s[nt][1] - mn0);
            float p2 = __expf(s[nt][2] - mn1);
            float p3 = __expf(s[nt][3] - mn1);
            sum0 += p0 + p1;
            sum1 += p2 + p3;
            int ks  = nt >> 1;
            int half = nt & 1;
            split2_pack(p0, p1, ph[ks][half * 2 + 0], pl[ks][half * 2 + 0]);
            split2_pack(p2, p3, ph[ks][half * 2 + 1], pl[ks][half * 2 + 1]);
        }
        sum0 += __shfl_xor_sync(0xffffffffu, sum0, 1);
        sum0 += __shfl_xor_sync(0xffffffffu, sum0, 2);
        sum1 += __shfl_xor_sync(0xffffffffu, sum1, 1);
        sum1 += __shfl_xor_sync(0xffffffffu, sum1, 2);

        l0r = l0r * alpha0 + sum0;
        l1r = l1r * alpha1 + sum1;
        m0r = mn0; m1r = mn1;

#pragma unroll
        for (int nt = 0; nt < 16; nt++) {
            o[nt][0] *= alpha0; o[nt][1] *= alpha0;
            o[nt][2] *= alpha1; o[nt][3] *= alpha1;
        }

        // --- P@V (bf16 3-split), V frag-ordered ---
#pragma unroll
        for (int ks = 0; ks < 4; ks++) {
#pragma unroll
            for (int nt = 0; nt < 16; nt++) {
                uint2 bhv = Vh2[(ks * 16 + nt) * 32 + lane];
                uint2 blv = Vl2[(ks * 16 + nt) * 32 + lane];
                mma_bf16(o[nt], ph[ks], reinterpret_cast<uint32_t*>(&bhv));
                mma_bf16(o[nt], ph[ks], reinterpret_cast<uint32_t*>(&blv));
                mma_bf16(o[nt], pl[ks], reinterpret_cast<uint32_t*>(&bhv));
            }
        }
        __syncthreads();   // all warps done reading buf before overwrite

        if (kt + 1 < NT) {
            if (kt + 2 < NT) {
                issue_tile(kt + 2, buf);
                CP_COMMIT();
                CP_WAIT1();   // ensure tile kt+1 is resident
            } else {
                CP_WAIT0();
            }
            __syncthreads();
        }
    }

    // Epilogue: O /= l, write ctx as bf16 hi/lo pair words
    {
        float li0 = 1.0f / l0r;
        float li1 = 1.0f / l1r;
        int s0r = q0 + mb + g;
        int s1r = s0r + 8;
#pragma unroll
        for (int nt = 0; nt < 16; nt++) {
            int colw = h * (DH / 2) + nt * 4 + cq;
            uint32_t hw0, lw0, hw1, lw1;
            split2_pack(o[nt][0] * li0, o[nt][1] * li0, hw0, lw0);
            split2_pack(o[nt][2] * li1, o[nt][3] * li1, hw1, lw1);
            size_t r0 = ((size_t)s0r * B_SZ + b) * HP + colw;
            size_t r1 = ((size_t)s1r * B_SZ + b) * HP + colw;
            gchi[r0] = hw0; gclo[r0] = lw0;
            gchi[r1] = hw1; gclo[r1] = lw1;
        }
    }
}

extern "C" void kernel_launch(void* const* d_in, const int* in_sizes, int n_in,
                              void* d_out, int out_size)
{
    const float* hidden = (const float*)d_in[0];
    const unsigned char* mask = (const unsigned char*)d_in[1];
    const float* W_qkv = (const float*)d_in[2];
    const float* b_qkv = (const float*)d_in[3];
    const float* W_dense = (const float*)d_in[4];
    const float* b_dense = (const float*)d_in[5];
    float* out = (float*)d_out;

    float *qd, *kd, *vd;
    uint32_t *ahi, *alo, *wqhi, *wqlo, *wdhi, *wdlo, *chi, *clo, *vhi, *vlo;
    cudaGetSymbolAddress((void**)&qd,   g_q);
    cudaGetSymbolAddress((void**)&kd,   g_k);
    cudaGetSymbolAddress((void**)&vd,   g_v);
    cudaGetSymbolAddress((void**)&ahi,  g_ahi);
    cudaGetSymbolAddress((void**)&alo,  g_alo);
    cudaGetSymbolAddress((void**)&wqhi, g_wqhi);
    cudaGetSymbolAddress((void**)&wqlo, g_wqlo);
    cudaGetSymbolAddress((void**)&wdhi, g_wdhi);
    cudaGetSymbolAddress((void**)&wdlo, g_wdlo);
    cudaGetSymbolAddress((void**)&chi,  g_chi);
    cudaGetSymbolAddress((void**)&clo,  g_clo);
    cudaGetSymbolAddress((void**)&vhi,  g_vhi);
    cudaGetSymbolAddress((void**)&vlo,  g_vlo);

    cudaFuncSetAttribute(attn_tc,
                         cudaFuncAttributeMaxDynamicSharedMemorySize,
                         ATT_SMEM_BYTES);

    const float* bdt = (out_size >= M_ROWS * H_DIM + H_DIM) ? b_dense : nullptr;

    // 0) Pre-split inputs
    {
        long f4 = (long)M_ROWS * H_DIM / 4;
        presplit_rows<<<(unsigned)((f4 + 255) / 256), 256>>>(hidden, ahi, alo, f4);
        long wq = (long)HP * N3;
        presplit_cols<<<(unsigned)((wq + 255) / 256), 256>>>(W_qkv, wqhi, wqlo, N3, wq);
        long wd = (long)HP * H_DIM;
        presplit_cols<<<(unsigned)((wd + 255) / 256), 256>>>(W_dense, wdhi, wdlo, H_DIM, wd);
    }
    // 1) QKV GEMM + scatter (q,k frag order; v linear)
    {
        dim3 grid(N3 / 128, M_ROWS / 128);
        gemm_tc<<<grid, 256>>>(ahi, alo, wqhi, wqlo, b_qkv, nullptr,
                               qd, kd, vd, nullptr, M_ROWS, N3, H_DIM, 0);
    }
    // 1b) Pre-split V into frag order
    {
        long vw = (long)B_SZ * NH * (S_LEN / 2) * DH;
        presplit_v_frag<<<(unsigned)((vw + 255) / 256), 256>>>(vd, vhi, vlo, vw);
    }
    // 2) Flash attention (cp.async double-buffered)
    {
        dim3 grid(S_LEN / 128, B_SZ * NH);
        attn_tc<<<grid, ATT_THREADS, ATT_SMEM_BYTES>>>(mask, qd, kd, vhi, vlo, chi, clo);
    }
    // 3) Dense GEMM -> out (+ folded b_dense tail)
    {
        dim3 grid(H_DIM / 128, M_ROWS / 128);
        gemm_tc<<<grid, 256>>>(chi, clo, wdhi, wdlo, nullptr, out,
                               nullptr, nullptr, nullptr, bdt,
                               M_ROWS, H_DIM, H_DIM, 1);
    }
}

// round 13
// speedup vs baseline: 2.8645x; 1.0111x over previous
#include <cuda_runtime.h>
#include <cuda_bf16.h>
#include <math.h>
#include <stdint.h>

// Problem constants
#define S_LEN 2048
#define B_SZ  2
#define H_DIM 2048
#define NH    16
#define DH    128
#define N3    (3 * H_DIM)          // 6144
#define M_ROWS (S_LEN * B_SZ)      // 4096
#define HP    (H_DIM / 2)          // 1024 pair-words per row
#define MASK_VALUE (-10000.0f)

// fp32 scratch.
// g_q: per bh, per 128-row q-tile, tf32 A-frag order
// g_k: per bh, per 64-row k-tile, tf32 B-frag order
// g_v: linear fp32 [bh][s][d]
__device__ float g_q[B_SZ * NH * S_LEN * DH];
__device__ float g_k[B_SZ * NH * S_LEN * DH];
__device__ float g_v[B_SZ * NH * S_LEN * DH];
// pre-split bf16-pair words
__device__ uint32_t g_ahi[M_ROWS * HP];
__device__ uint32_t g_alo[M_ROWS * HP];
__device__ uint32_t g_wqhi[HP * N3];
__device__ uint32_t g_wqlo[HP * N3];
__device__ uint32_t g_wdhi[HP * H_DIM];
__device__ uint32_t g_wdlo[HP * H_DIM];
__device__ uint32_t g_chi[M_ROWS * HP];
__device__ uint32_t g_clo[M_ROWS * HP];
// v in bf16 B-frag (n8k16) order per 64-key tile
__device__ uint32_t g_vhi[B_SZ * NH * (S_LEN/2) * DH];
__device__ uint32_t g_vlo[B_SZ * NH * (S_LEN/2) * DH];

// ---------------------------------------------------------------------------
// helpers
// ---------------------------------------------------------------------------
__device__ __forceinline__ float to_tf32(float x)
{
    uint32_t u;
    asm("cvt.rna.tf32.f32 %0, %1;" : "=r"(u) : "f"(x));
    return __uint_as_float(u);
}

__device__ __forceinline__ void mma_tf32(float* c, const uint32_t* a, const uint32_t* b)
{
    asm volatile(
        "mma.sync.aligned.m16n8k8.row.col.f32.tf32.tf32.f32 "
        "{%0,%1,%2,%3}, {%4,%5,%6,%7}, {%8,%9}, {%0,%1,%2,%3};"
        : "+f"(c[0]), "+f"(c[1]), "+f"(c[2]), "+f"(c[3])
        : "r"(a[0]), "r"(a[1]), "r"(a[2]), "r"(a[3]),
          "r"(b[0]), "r"(b[1]));
}

__device__ __forceinline__ void mma_bf16(float* c, const uint32_t* a, const uint32_t* b)
{
    asm volatile(
        "mma.sync.aligned.m16n8k16.row.col.f32.bf16.bf16.f32 "
        "{%0,%1,%2,%3}, {%4,%5,%6,%7}, {%8,%9}, {%0,%1,%2,%3};"
        : "+f"(c[0]), "+f"(c[1]), "+f"(c[2]), "+f"(c[3])
        : "r"(a[0]), "r"(a[1]), "r"(a[2]), "r"(a[3]),
          "r"(b[0]), "r"(b[1]));
}

__device__ __forceinline__ void ldsm_x4(uint32_t& r0, uint32_t& r1,
                                        uint32_t& r2, uint32_t& r3, uint32_t addr)
{
    asm volatile("ldmatrix.sync.aligned.m8n8.x4.shared.b16 {%0,%1,%2,%3}, [%4];"
                 : "=r"(r0), "=r"(r1), "=r"(r2), "=r"(r3) : "r"(addr));
}

__device__ __forceinline__ void split2_pack(float x0, float x1,
                                            uint32_t& hi, uint32_t& lo)
{
    __nv_bfloat16 h0 = __float2bfloat16_rn(x0);
    __nv_bfloat16 h1 = __float2bfloat16_rn(x1);
    __nv_bfloat16 l0 = __float2bfloat16_rn(x0 - __bfloat162float(h0));
    __nv_bfloat16 l1 = __float2bfloat16_rn(x1 - __bfloat162float(h1));
    __nv_bfloat162 hp = __halves2bfloat162(h0, h1);
    __nv_bfloat162 lp = __halves2bfloat162(l0, l1);
    hi = *reinterpret_cast<uint32_t*>(&hp);
    lo = *reinterpret_cast<uint32_t*>(&lp);
}

__device__ __forceinline__ void cp_async16(uint32_t smem_addr, const void* gptr)
{
    asm volatile("cp.async.cg.shared.global [%0], [%1], 16;"
                 :: "r"(smem_addr), "l"(gptr));
}
#define CP_COMMIT() asm volatile("cp.async.commit_group;")
#define CP_WAIT1()  asm volatile("cp.async.wait_group 1;")
#define CP_WAIT0()  asm volatile("cp.async.wait_group 0;")

// ---------------------------------------------------------------------------
// Fused input presplit (hidden rows + W_qkv cols + W_dense cols) — ONE launch
// ---------------------------------------------------------------------------
#define PS_F4 ((long)M_ROWS * H_DIM / 4)          // 2097152 float4 of hidden
#define PS_WQ ((long)HP * N3)                     // 6291456 words of W_qkv
#define PS_WD ((long)HP * H_DIM)                  // 2097152 words of W_dense
#define PS_TOTAL (PS_F4 + PS_WQ + PS_WD)

__global__ void presplit_all(const float* __restrict__ hidden,
                             const float* __restrict__ wq,
                             const float* __restrict__ wdn,
                             uint32_t* __restrict__ ahi, uint32_t* __restrict__ alo,
                             uint32_t* __restrict__ wqhi, uint32_t* __restrict__ wqlo,
                             uint32_t* __restrict__ wdhi, uint32_t* __restrict__ wdlo)
{
    long i = (long)blockIdx.x * blockDim.x + threadIdx.x;
    if (i < PS_F4) {
        float4 v = reinterpret_cast<const float4*>(hidden)[i];
        uint32_t h0, l0, h1, l1;
        split2_pack(v.x, v.y, h0, l0);
        split2_pack(v.z, v.w, h1, l1);
        reinterpret_cast<uint2*>(ahi)[i] = make_uint2(h0, h1);
        reinterpret_cast<uint2*>(alo)[i] = make_uint2(l0, l1);
    } else if (i < PS_F4 + PS_WQ) {
        long w = i - PS_F4;
        long pr = w / N3;
        int  n  = (int)(w - pr * N3);
        float a = wq[(2 * pr) * (long)N3 + n];
        float b = wq[(2 * pr + 1) * (long)N3 + n];
        uint32_t h, l;
        split2_pack(a, b, h, l);
        wqhi[w] = h; wqlo[w] = l;
    } else if (i < PS_TOTAL) {
        long w = i - PS_F4 - PS_WQ;
        long pr = w / H_DIM;
        int  n  = (int)(w - pr * H_DIM);
        float a = wdn[(2 * pr) * (long)H_DIM + n];
        float b = wdn[(2 * pr + 1) * (long)H_DIM + n];
        uint32_t h, l;
        split2_pack(a, b, h, l);
        wdhi[w] = h; wdlo[w] = l;
    }
}

// V: linear fp32 [bh][s][d] -> bf16 hi/lo in B-frag (n8k16) order per 64-key tile.
__global__ void presplit_v_frag(const float* __restrict__ vd,
                                uint32_t* __restrict__ hi, uint32_t* __restrict__ lo,
                                long total_words)
{
    long w = (long)blockIdx.x * blockDim.x + threadIdx.x;
    if (w >= total_words) return;
    long bhw  = w >> 17;
    int  rem  = (int)(w & 131071);
    int  tile = rem >> 12;
    int  r2   = rem & 4095;
    int  reg  = r2 & 1;
    int  t2   = r2 >> 1;
    int  lane = t2 & 31;
    int  t3   = t2 >> 5;
    int  nt   = t3 & 15;
    int  ks   = t3 >> 4;
    int  gt   = lane >> 2;
    int  cqq  = lane & 3;
    int  pwi  = cqq + (reg << 2);
    int  s0   = tile * 64 + (ks * 8 + pwi) * 2;
    int  d    = nt * 8 + gt;
    const float* vb = vd + bhw * (long)S_LEN * DH;
    float a = vb[(size_t)s0 * DH + d];
    float b = vb[(size_t)(s0 + 1) * DH + d];
    uint32_t h, l;
    split2_pack(a, b, h, l);
    hi[w] = h; lo[w] = l;
}

// ---------------------------------------------------------------------------
// Tensor-core GEMM — A-frag loads via ldmatrix.x4 (B frags stay scalar LDS)
// ---------------------------------------------------------------------------
#define APK_STRIDE 20
#define BPK_STRIDE 136

__global__ __launch_bounds__(256)
void gemm_tc(const uint32_t* __restrict__ Ahi_g, const uint32_t* __restrict__ Alo_g,
             const uint32_t* __restrict__ Bhi_g, const uint32_t* __restrict__ Blo_g,
             const float* __restrict__ bias, float* __restrict__ C,
             float* __restrict__ qd, float* __restrict__ kd, float* __restrict__ vd,
             const float* __restrict__ bdt,
             int M, int N, int K, int mode)
{
    __shared__ uint32_t Ahi[128][APK_STRIDE];
    __shared__ uint32_t Alo[128][APK_STRIDE];
    __shared__ uint32_t Bhi[16][BPK_STRIDE];
    __shared__ uint32_t Blo[16][BPK_STRIDE];

    const int tid  = threadIdx.x;
    const int lane = tid & 31;
    const int warp = tid >> 5;
    const int wm   = warp & 1;
    const int wn   = warp >> 1;
    const int g    = lane >> 2;
    const int cq   = lane & 3;

    const int m0 = blockIdx.y * 128;
    const int n0 = blockIdx.x * 128;
    const int Kp = K >> 1;

    float acc[4][4][4];
#pragma unroll
    for (int mt = 0; mt < 4; mt++)
#pragma unroll
        for (int nt = 0; nt < 4; nt++)
#pragma unroll
            for (int r = 0; r < 4; r++) acc[mt][nt][r] = 0.0f;

    const int arw = tid >> 3;
    const int akp = (tid & 7) << 1;
    const int bpr = tid >> 5;
    const int bnc = (tid & 31) << 2;

    // ldmatrix lane address components: row = mb + (lane&15), colbase = (lane>>4)*4
    const int lrow = lane & 15;
    const int lcol = (lane >> 4) << 2;
    const uint32_t ahi_base = (uint32_t)__cvta_generic_to_shared(&Ahi[0][0]);
    const uint32_t alo_base = (uint32_t)__cvta_generic_to_shared(&Alo[0][0]);

    for (int k0p = 0; k0p < Kp; k0p += 16) {
#pragma unroll
        for (int p = 0; p < 4; p++) {
            int m = arw + p * 32;
            size_t ai = (size_t)(m0 + m) * Kp + k0p + akp;
            uint2 h = *reinterpret_cast<const uint2*>(&Ahi_g[ai]);
            uint2 l = *reinterpret_cast<const uint2*>(&Alo_g[ai]);
            *reinterpret_cast<uint2*>(&Ahi[m][akp]) = h;
            *reinterpret_cast<uint2*>(&Alo[m][akp]) = l;
        }
#pragma unroll
        for (int p = 0; p < 2; p++) {
            int pr = bpr + p * 8;
            size_t bi = (size_t)(k0p + pr) * N + n0 + bnc;
            uint4 h = *reinterpret_cast<const uint4*>(&Bhi_g[bi]);
            uint4 l = *reinterpret_cast<const uint4*>(&Blo_g[bi]);
            *reinterpret_cast<uint4*>(&Bhi[pr][bnc]) = h;
            *reinterpret_cast<uint4*>(&Blo[pr][bnc]) = l;
        }
        __syncthreads();

#pragma unroll
        for (int kk = 0; kk < 2; kk++) {
            const int kb = kk * 8;
            uint32_t ah[4][4], al[4][4];
#pragma unroll
            for (int mt = 0; mt < 4; mt++) {
                const int mb = wm * 64 + mt * 16;
                uint32_t addr_h = ahi_base +
                    (((mb + lrow) * APK_STRIDE) + kb + lcol) * 4;
                uint32_t addr_l = alo_base +
                    (((mb + lrow) * APK_STRIDE) + kb + lcol) * 4;
                ldsm_x4(ah[mt][0], ah[mt][1], ah[mt][2], ah[mt][3], addr_h);
                ldsm_x4(al[mt][0], al[mt][1], al[mt][2], al[mt][3], addr_l);
            }
            uint32_t bh[4][2], bl[4][2];
#pragma unroll
            for (int nt = 0; nt < 4; nt++) {
                const int nb = wn * 32 + nt * 8;
                bh[nt][0] = Bhi[kb + cq][nb + g];
                bh[nt][1] = Bhi[kb + cq + 4][nb + g];
                bl[nt][0] = Blo[kb + cq][nb + g];
                bl[nt][1] = Blo[kb + cq + 4][nb + g];
            }
#pragma unroll
            for (int mt = 0; mt < 4; mt++)
#pragma unroll
                for (int nt = 0; nt < 4; nt++) {
                    mma_bf16(acc[mt][nt], ah[mt], bh[nt]);
                    mma_bf16(acc[mt][nt], ah[mt], bl[nt]);
                    mma_bf16(acc[mt][nt], al[mt], bh[nt]);
                }
        }
        __syncthreads();
    }

    if (mode == 0) {
#pragma unroll
        for (int mt = 0; mt < 4; mt++) {
#pragma unroll
            for (int nt = 0; nt < 4; nt++) {
#pragma unroll
                for (int r = 0; r < 4; r++) {
                    int m = m0 + wm * 64 + mt * 16 + g + ((r >> 1) << 3);
                    int n = n0 + wn * 32 + nt * 8 + 2 * cq + (r & 1);
                    float v = acc[mt][nt][r] + bias[n];
                    int b = m & 1;
                    int s = m >> 1;
                    int head = n / (3 * DH);
                    int rem  = n - head * (3 * DH);
                    int part = rem >> 7;
                    int d    = rem & 127;
                    size_t bhbase = (size_t)(b * NH + head) * S_LEN * DH;
                    int ks = d >> 3, kk = d & 7;
                    if (part == 0) {
                        int qtile = s >> 7;
                        int wmr   = (s >> 4) & 7;
                        int r16   = s & 15;
                        int lt    = ((r16 & 7) << 2) + (kk & 3);
                        int rg    = (r16 >> 3) + ((kk >> 2) << 1);
                        size_t idx = bhbase + (size_t)qtile * 16384
                                   + (((ks * 8 + wmr) * 32 + lt) << 2) + rg;
                        qd[idx] = to_tf32(v);
                    } else if (part == 1) {
                        int ktile = s >> 6;
                        int ntk   = (s >> 3) & 7;
                        int lt    = ((s & 7) << 2) + (kk & 3);
                        int rg    = kk >> 2;
                        size_t idx = bhbase + (size_t)ktile * 8192
                                   + (((ks * 8 + ntk) * 32 + lt) << 1) + rg;
                        kd[idx] = to_tf32(v);
                    } else {
                        vd[bhbase + (size_t)s * DH + d] = v;
                    }
                }
            }
        }
    } else {
#pragma unroll
        for (int mt = 0; mt < 4; mt++) {
#pragma unroll
            for (int nt = 0; nt < 4; nt++) {
                int n = n0 + wn * 32 + nt * 8 + 2 * cq;
                int mA = m0 + wm * 64 + mt * 16 + g;
                int mB = mA + 8;
                float2 vA = make_float2(acc[mt][nt][0], acc[mt][nt][1]);
                float2 vB = make_float2(acc[mt][nt][2], acc[mt][nt][3]);
                *reinterpret_cast<float2*>(&C[(size_t)mA * N + n]) = vA;
                *reinterpret_cast<float2*>(&C[(size_t)mB * N + n]) = vB;
            }
        }
        if (bdt && blockIdx.x == 0 && blockIdx.y == 0) {
            for (int i = tid; i < H_DIM; i += 256)
                C[(size_t)M_ROWS * H_DIM + i] = bdt[i];
        }
    }
}

// ---------------------------------------------------------------------------
// Flash attention (unchanged from R12): FA2 register-resident, frag-ordered
// smem, cp.async double-buffered K/V. 256 threads, 192KB smem.
// ---------------------------------------------------------------------------
#define ATT_THREADS 256
#define AQF_OFF  0
#define AKF_OFF  16384
#define AVH_OFF  32768
#define AVL_OFF  40960
#define ATT_SMEM_BYTES (49152 * 4)

__global__ __launch_bounds__(ATT_THREADS)
void attn_tc(const unsigned char* __restrict__ mask,
             const float* __restrict__ gq, const float* __restrict__ gk,
             const uint32_t* __restrict__ gvhi, const uint32_t* __restrict__ gvlo,
             uint32_t* __restrict__ gchi, uint32_t* __restrict__ gclo)
{
    extern __shared__ uint32_t smw[];
    uint4* Qf4 = reinterpret_cast<uint4*>(smw + AQF_OFF);

    const int tid  = threadIdx.x;
    const int lane = tid & 31;
    const int warp = tid >> 5;
    const int g    = lane >> 2;
    const int cq   = lane & 3;
    const int mb   = warp * 16;

    const int bh = blockIdx.y;
    const int b  = bh / NH;
    const int h  = bh - b * NH;
    const int q0 = blockIdx.x * 128;

    const uint32_t* qw = reinterpret_cast<const uint32_t*>(gq)
                       + (size_t)bh * S_LEN * DH + (size_t)blockIdx.x * 16384;
    const uint32_t* kw = reinterpret_cast<const uint32_t*>(gk)
                       + (size_t)bh * S_LEN * DH;
    const uint32_t* vhp = gvhi + (size_t)bh * (S_LEN / 2) * DH;
    const uint32_t* vlp = gvlo + (size_t)bh * (S_LEN / 2) * DH;
    const unsigned char* mp = mask + (size_t)b * S_LEN * S_LEN;
    const float inv_norm = 1.0f / sqrtf((float)H_DIM);

    auto issue_tile = [&](int kt, int buf) {
        const uint4* ksn = reinterpret_cast<const uint4*>(kw + (size_t)kt * 8192);
        uint32_t kb = (uint32_t)__cvta_generic_to_shared(smw + AKF_OFF + buf * 8192)
                    + tid * 16;
#pragma unroll
        for (int p = 0; p < 8; p++)
            cp_async16(kb + p * ATT_THREADS * 16, &ksn[tid + p * ATT_THREADS]);
        const uint4* vhn = reinterpret_cast<const uint4*>(vhp + (size_t)kt * 4096);
        const uint4* vln = reinterpret_cast<const uint4*>(vlp + (size_t)kt * 4096);
        uint32_t vhb = (uint32_t)__cvta_generic_to_shared(smw + AVH_OFF + buf * 4096)
                     + tid * 16;
        uint32_t vlb = (uint32_t)__cvta_generic_to_shared(smw + AVL_OFF + buf * 4096)
                     + tid * 16;
#pragma unroll
        for (int p = 0; p < 4; p++) {
            cp_async16(vhb + p * ATT_THREADS * 16, &vhn[tid + p * ATT_THREADS]);
            cp_async16(vlb + p * ATT_THREADS * 16, &vln[tid + p * ATT_THREADS]);
        }
    };

    issue_tile(0, 0); CP_COMMIT();
    issue_tile(1, 1); CP_COMMIT();
    {
        const uint4* src = reinterpret_cast<const uint4*>(qw);
#pragma unroll
        for (int p = 0; p < 16; p++)
            Qf4[tid + p * ATT_THREADS] = src[tid + p * ATT_THREADS];
    }
    CP_WAIT1();
    __syncthreads();

    float o[16][4];
#pragma unroll
    for (int nt = 0; nt < 16; nt++)
#pragma unroll
        for (int r = 0; r < 4; r++) o[nt][r] = 0.0f;
    float m0r = -INFINITY, m1r = -INFINITY;
    float l0r = 0.0f, l1r = 0.0f;

    const unsigned char* mr0 = mp + (size_t)(q0 + mb + g) * S_LEN;
    const unsigned char* mr1 = mp + (size_t)(q0 + mb + g + 8) * S_LEN;

    const int NT = S_LEN / 64;
    for (int kt = 0; kt < NT; kt++) {
        const int t0 = kt * 64;
        const int buf = kt & 1;
        const uint2* Kf2 = reinterpret_cast<const uint2*>(smw + AKF_OFF + buf * 8192);
        const uint2* Vh2 = reinterpret_cast<const uint2*>(smw + AVH_OFF + buf * 4096);
        const uint2* Vl2 = reinterpret_cast<const uint2*>(smw + AVL_OFF + buf * 4096);

        uchar2 mk0[8], mk1[8];
#pragma unroll
        for (int nt = 0; nt < 8; nt++) {
            int cc = t0 + nt * 8 + 2 * cq;
            mk0[nt] = *reinterpret_cast<const uchar2*>(mr0 + cc);
            mk1[nt] = *reinterpret_cast<const uchar2*>(mr1 + cc);
        }

        float s[8][4];
#pragma unroll
        for (int nt = 0; nt < 8; nt++)
#pragma unroll
            for (int r = 0; r < 4; r++) s[nt][r] = 0.0f;

#pragma unroll
        for (int ks = 0; ks < 16; ks++) {
            uint4 aq = Qf4[(ks * 8 + warp) * 32 + lane];
#pragma unroll
            for (int nt = 0; nt < 8; nt++) {
                uint2 bk = Kf2[(ks * 8 + nt) * 32 + lane];
                mma_tf32(s[nt], reinterpret_cast<uint32_t*>(&aq),
                         reinterpret_cast<uint32_t*>(&bk));
            }
        }

        float pmax0 = -INFINITY, pmax1 = -INFINITY;
#pragma unroll
        for (int nt = 0; nt < 8; nt++) {
            float v0 = s[nt][0] * inv_norm; if (mk0[nt].x) v0 = MASK_VALUE;
            float v1 = s[nt][1] * inv_norm; if (mk0[nt].y) v1 = MASK_VALUE;
            float v2 = s[nt][2] * inv_norm; if (mk1[nt].x) v2 = MASK_VALUE;
            float v3 = s[nt][3] * inv_norm; if (mk1[nt].y) v3 = MASK_VALUE;
            s[nt][0] = v0; s[nt][1] = v1; s[nt][2] = v2; s[nt][3] = v3;
            pmax0 = fmaxf(pmax0, fmaxf(v0, v1));
            pmax1 = fmaxf(pmax1, fmaxf(v2, v3));
        }
        pmax0 = fmaxf(pmax0, __shfl_xor_sync(0xffffffffu, pmax0, 1));
        pmax0 = fmaxf(pmax0, __shfl_xor_sync(0xffffffffu, pmax0, 2));
        pmax1 = fmaxf(pmax1, __shfl_xor_sync(0xffffffffu, pmax1, 1));
        pmax1 = fmaxf(pmax1, __shfl_xor_sync(0xffffffffu, pmax1, 2));

        float mn0 = fmaxf(m0r, pmax0);
        float mn1 = fmaxf(m1r, pmax1);
        float alpha0 = __expf(m0r - mn0);
        float alpha1 = __expf(m1r - mn1);

        uint32_t ph[4][4], pl[4][4];
        float sum0 = 0.0f, sum1 = 0.0f;
#pragma unroll
        for (int nt = 0; nt < 8; nt++) {
            float p0 = __expf(s[nt][0] - mn0);
            float p1 = __expf(s[nt][1] - mn0);
            float p2 = __expf(s[nt][2] - mn1);
            float p3 = __expf(s[nt][3] - mn1);
            sum0 += p0 + p1;
            sum1 += p2 + p3;
            int ks  = nt >> 1;
            int half = nt & 1;
            split2_pack(p0, p1, ph[ks][half * 2 + 0], pl[ks][half * 2 + 0]);
            split2_pack(p2, p3, ph[ks][half * 2 + 1], pl[ks][half * 2 + 1]);
        }
        sum0 += __shfl_xor_sync(0xffffffffu, sum0, 1);
        sum0 += __shfl_xor_sync(0xffffffffu, sum0, 2);
        sum1 += __shfl_xor_sync(0xffffffffu, sum1, 1);
        sum1 += __shfl_xor_sync(0xffffffffu, sum1, 2);

        l0r = l0r * alpha0 + sum0;
        l1r = l1r * alpha1 + sum1;
        m0r = mn0; m1r = mn1;

#pragma unroll
        for (int nt = 0; nt < 16; nt++) {
            o[nt][0] *= alpha0; o[nt][1] *= alpha0;
            o[nt][2] *= alpha1; o[nt][3] *= alpha1;
        }

#pragma unroll
        for (int ks = 0; ks < 4; ks++) {
#pragma unroll
            for (int nt = 0; nt < 16; nt++) {
                uint2 bhv = Vh2[(ks * 16 + nt) * 32 + lane];
                uint2 blv = Vl2[(ks * 16 + nt) * 32 + lane];
                mma_bf16(o[nt], ph[ks], reinterpret_cast<uint32_t*>(&bhv));
                mma_bf16(o[nt], ph[ks], reinterpret_cast<uint32_t*>(&blv));
                mma_bf16(o[nt], pl[ks], reinterpret_cast<uint32_t*>(&bhv));
            }
        }
        __syncthreads();

        if (kt + 1 < NT) {
            if (kt + 2 < NT) {
                issue_tile(kt + 2, buf);
                CP_COMMIT();
                CP_WAIT1();
            } else {
                CP_WAIT0();
            }
            __syncthreads();
        }
    }

    {
        float li0 = 1.0f / l0r;
        float li1 = 1.0f / l1r;
        int s0r = q0 + mb + g;
        int s1r = s0r + 8;
#pragma unroll
        for (int nt = 0; nt < 16; nt++) {
            int colw = h * (DH / 2) + nt * 4 + cq;
            uint32_t hw0, lw0, hw1, lw1;
            split2_pack(o[nt][0] * li0, o[nt][1] * li0, hw0, lw0);
            split2_pack(o[nt][2] * li1, o[nt][3] * li1, hw1, lw1);
            size_t r0 = ((size_t)s0r * B_SZ + b) * HP + colw;
            size_t r1 = ((size_t)s1r * B_SZ + b) * HP + colw;
            gchi[r0] = hw0; gclo[r0] = lw0;
            gchi[r1] = hw1; gclo[r1] = lw1;
        }
    }
}

extern "C" void kernel_launch(void* const* d_in, const int* in_sizes, int n_in,
                              void* d_out, int out_size)
{
    const float* hidden = (const float*)d_in[0];
    const unsigned char* mask = (const unsigned char*)d_in[1];
    const float* W_qkv = (const float*)d_in[2];
    const float* b_qkv = (const float*)d_in[3];
    const float* W_dense = (const float*)d_in[4];
    const float* b_dense = (const float*)d_in[5];
    float* out = (float*)d_out;

    float *qd, *kd, *vd;
    uint32_t *ahi, *alo, *wqhi, *wqlo, *wdhi, *wdlo, *chi, *clo, *vhi, *vlo;
    cudaGetSymbolAddress((void**)&qd,   g_q);
    cudaGetSymbolAddress((void**)&kd,   g_k);
    cudaGetSymbolAddress((void**)&vd,   g_v);
    cudaGetSymbolAddress((void**)&ahi,  g_ahi);
    cudaGetSymbolAddress((void**)&alo,  g_alo);
    cudaGetSymbolAddress((void**)&wqhi, g_wqhi);
    cudaGetSymbolAddress((void**)&wqlo, g_wqlo);
    cudaGetSymbolAddress((void**)&wdhi, g_wdhi);
    cudaGetSymbolAddress((void**)&wdlo, g_wdlo);
    cudaGetSymbolAddress((void**)&chi,  g_chi);
    cudaGetSymbolAddress((void**)&clo,  g_clo);
    cudaGetSymbolAddress((void**)&vhi,  g_vhi);
    cudaGetSymbolAddress((void**)&vlo,  g_vlo);

    cudaFuncSetAttribute(attn_tc,
                         cudaFuncAttributeMaxDynamicSharedMemorySize,
                         ATT_SMEM_BYTES);

    const float* bdt = (out_size >= M_ROWS * H_DIM + H_DIM) ? b_dense : nullptr;

    // [1] Fused presplit of all GEMM inputs (one launch)
    {
        long total = PS_TOTAL;
        presplit_all<<<(unsigned)((total + 255) / 256), 256>>>(
            hidden, W_qkv, W_dense, ahi, alo, wqhi, wqlo, wdhi, wdlo);
    }
    // [2] QKV GEMM + scatter (q,k frag order; v linear)
    {
        dim3 grid(N3 / 128, M_ROWS / 128);
        gemm_tc<<<grid, 256>>>(ahi, alo, wqhi, wqlo, b_qkv, nullptr,
                               qd, kd, vd, nullptr, M_ROWS, N3, H_DIM, 0);
    }
    // [3] Pre-split V into frag order
    {
        long vw = (long)B_SZ * NH * (S_LEN / 2) * DH;
        presplit_v_frag<<<(unsigned)((vw + 255) / 256), 256>>>(vd, vhi, vlo, vw);
    }
    // [4] Flash attention  (lands in the ncu capture slot)
    {
        dim3 grid(S_LEN / 128, B_SZ * NH);
        attn_tc<<<grid, ATT_THREADS, ATT_SMEM_BYTES>>>(mask, qd, kd, vhi, vlo, chi, clo);
    }
    // [5] Dense GEMM -> out (+ folded b_dense tail)
    {
        dim3 grid(H_DIM / 128, M_ROWS / 128);
        gemm_tc<<<grid, 256>>>(chi, clo, wdhi, wdlo, nullptr, out,
                               nullptr, nullptr, nullptr, bdt,
                               M_ROWS, H_DIM, H_DIM, 1);
    }
}

// round 15
// speedup vs baseline: 3.2877x; 1.1477x over previous
#include <cuda_runtime.h>
#include <cuda_bf16.h>
#include <math.h>
#include <stdint.h>

// Problem constants
#define S_LEN 2048
#define B_SZ  2
#define H_DIM 2048
#define NH    16
#define DH    128
#define N3    (3 * H_DIM)          // 6144
#define M_ROWS (S_LEN * B_SZ)      // 4096
#define HP    (H_DIM / 2)          // 1024 pair-words per row
#define MASK_VALUE (-10000.0f)

// scratch
__device__ float g_q[B_SZ * NH * S_LEN * DH];   // tf32 A-frag order per q-tile
__device__ float g_k[B_SZ * NH * S_LEN * DH];   // tf32 B-frag order per k-tile
__device__ float g_v[B_SZ * NH * S_LEN * DH];   // linear fp32 [bh][s][d]
// pre-split bf16-pair words: a/ctx rows [M][K/2]; W cols [K/2][N]
__device__ uint32_t g_ahi[M_ROWS * HP];
__device__ uint32_t g_alo[M_ROWS * HP];
__device__ uint32_t g_wqhi[HP * N3];
__device__ uint32_t g_wqlo[HP * N3];
__device__ uint32_t g_wdhi[HP * H_DIM];
__device__ uint32_t g_wdlo[HP * H_DIM];
__device__ uint32_t g_chi[M_ROWS * HP];
__device__ uint32_t g_clo[M_ROWS * HP];
// v in bf16 B-frag (n8k16) order per 64-key tile
__device__ uint32_t g_vhi[B_SZ * NH * (S_LEN/2) * DH];
__device__ uint32_t g_vlo[B_SZ * NH * (S_LEN/2) * DH];

// ---------------------------------------------------------------------------
// helpers
// ---------------------------------------------------------------------------
__device__ __forceinline__ float to_tf32(float x)
{
    uint32_t u;
    asm("cvt.rna.tf32.f32 %0, %1;" : "=r"(u) : "f"(x));
    return __uint_as_float(u);
}

__device__ __forceinline__ void mma_tf32(float* c, const uint32_t* a, const uint32_t* b)
{
    asm volatile(
        "mma.sync.aligned.m16n8k8.row.col.f32.tf32.tf32.f32 "
        "{%0,%1,%2,%3}, {%4,%5,%6,%7}, {%8,%9}, {%0,%1,%2,%3};"
        : "+f"(c[0]), "+f"(c[1]), "+f"(c[2]), "+f"(c[3])
        : "r"(a[0]), "r"(a[1]), "r"(a[2]), "r"(a[3]),
          "r"(b[0]), "r"(b[1]));
}

__device__ __forceinline__ void mma_bf16(float* c, const uint32_t* a, const uint32_t* b)
{
    asm volatile(
        "mma.sync.aligned.m16n8k16.row.col.f32.bf16.bf16.f32 "
        "{%0,%1,%2,%3}, {%4,%5,%6,%7}, {%8,%9}, {%0,%1,%2,%3};"
        : "+f"(c[0]), "+f"(c[1]), "+f"(c[2]), "+f"(c[3])
        : "r"(a[0]), "r"(a[1]), "r"(a[2]), "r"(a[3]),
          "r"(b[0]), "r"(b[1]));
}

__device__ __forceinline__ void ldsm_x4(uint32_t& r0, uint32_t& r1,
                                        uint32_t& r2, uint32_t& r3, uint32_t addr)
{
    asm volatile("ldmatrix.sync.aligned.m8n8.x4.shared.b16 {%0,%1,%2,%3}, [%4];"
                 : "=r"(r0), "=r"(r1), "=r"(r2), "=r"(r3) : "r"(addr));
}

__device__ __forceinline__ void split2_pack(float x0, float x1,
                                            uint32_t& hi, uint32_t& lo)
{
    __nv_bfloat16 h0 = __float2bfloat16_rn(x0);
    __nv_bfloat16 h1 = __float2bfloat16_rn(x1);
    __nv_bfloat16 l0 = __float2bfloat16_rn(x0 - __bfloat162float(h0));
    __nv_bfloat16 l1 = __float2bfloat16_rn(x1 - __bfloat162float(h1));
    __nv_bfloat162 hp = __halves2bfloat162(h0, h1);
    __nv_bfloat162 lp = __halves2bfloat162(l0, l1);
    hi = *reinterpret_cast<uint32_t*>(&hp);
    lo = *reinterpret_cast<uint32_t*>(&lp);
}

__device__ __forceinline__ void cp_async16(uint32_t smem_addr, const void* gptr)
{
    asm volatile("cp.async.cg.shared.global [%0], [%1], 16;"
                 :: "r"(smem_addr), "l"(gptr));
}
#define CP_COMMIT() asm volatile("cp.async.commit_group;")
#define CP_WAIT1()  asm volatile("cp.async.wait_group 1;")
#define CP_WAIT0()  asm volatile("cp.async.wait_group 0;")

// ---------------------------------------------------------------------------
// Fused input presplit (hidden rows + W_qkv cols + W_dense cols)
// ---------------------------------------------------------------------------
#define PS_F4 ((long)M_ROWS * H_DIM / 4)          // 2097152 float4 of hidden
#define PS_WQ ((long)HP * N3)                     // 6291456 words of W_qkv
#define PS_WD ((long)HP * H_DIM)                  // 2097152 words of W_dense
#define PS_TOTAL (PS_F4 + PS_WQ + PS_WD)

__global__ void presplit_all(const float* __restrict__ hidden,
                             const float* __restrict__ wq,
                             const float* __restrict__ wdn,
                             uint32_t* __restrict__ ahi, uint32_t* __restrict__ alo,
                             uint32_t* __restrict__ wqhi, uint32_t* __restrict__ wqlo,
                             uint32_t* __restrict__ wdhi, uint32_t* __restrict__ wdlo)
{
    long i = (long)blockIdx.x * blockDim.x + threadIdx.x;
    if (i < PS_F4) {
        float4 v = reinterpret_cast<const float4*>(hidden)[i];
        uint32_t h0, l0, h1, l1;
        split2_pack(v.x, v.y, h0, l0);
        split2_pack(v.z, v.w, h1, l1);
        reinterpret_cast<uint2*>(ahi)[i] = make_uint2(h0, h1);
        reinterpret_cast<uint2*>(alo)[i] = make_uint2(l0, l1);
    } else if (i < PS_F4 + PS_WQ) {
        long w = i - PS_F4;
        long pr = w / N3;
        int  n  = (int)(w - pr * N3);
        float a = wq[(2 * pr) * (long)N3 + n];
        float b = wq[(2 * pr + 1) * (long)N3 + n];
        uint32_t h, l;
        split2_pack(a, b, h, l);
        wqhi[w] = h; wqlo[w] = l;
    } else if (i < PS_TOTAL) {
        long w = i - PS_F4 - PS_WQ;
        long pr = w / H_DIM;
        int  n  = (int)(w - pr * H_DIM);
        float a = wdn[(2 * pr) * (long)H_DIM + n];
        float b = wdn[(2 * pr + 1) * (long)H_DIM + n];
        uint32_t h, l;
        split2_pack(a, b, h, l);
        wdhi[w] = h; wdlo[w] = l;
    }
}

// V: linear fp32 [bh][s][d] -> bf16 hi/lo in B-frag (n8k16) order per 64-key tile.
__global__ void presplit_v_frag(const float* __restrict__ vd,
                                uint32_t* __restrict__ hi, uint32_t* __restrict__ lo,
                                long total_words)
{
    long w = (long)blockIdx.x * blockDim.x + threadIdx.x;
    if (w >= total_words) return;
    long bhw  = w >> 17;
    int  rem  = (int)(w & 131071);
    int  tile = rem >> 12;
    int  r2   = rem & 4095;
    int  reg  = r2 & 1;
    int  t2   = r2 >> 1;
    int  lane = t2 & 31;
    int  t3   = t2 >> 5;
    int  nt   = t3 & 15;
    int  ks   = t3 >> 4;
    int  gt   = lane >> 2;
    int  cqq  = lane & 3;
    int  pwi  = cqq + (reg << 2);
    int  s0   = tile * 64 + (ks * 8 + pwi) * 2;
    int  d    = nt * 8 + gt;
    const float* vb = vd + bhw * (long)S_LEN * DH;
    float a = vb[(size_t)s0 * DH + d];
    float b = vb[(size_t)(s0 + 1) * DH + d];
    uint32_t h, l;
    split2_pack(a, b, h, l);
    hi[w] = h; lo[w] = l;
}

// ---------------------------------------------------------------------------
// Tensor-core GEMM — cp.async double-buffered k-chunks, ldmatrix A frags.
// C[M,N] = A[M,K] @ B[K,N]. 128x128 tile, 256 thr (8 warps), warp 64x32.
// K chunk = 32 floats (16 pair-words). Buffers: Ahi|Alo [128][20],
// Bhi|Blo [16][136]; 9472 words/buf, x2 = 75776 B dynamic smem.
// ---------------------------------------------------------------------------
#define APK_STRIDE 20
#define BPK_STRIDE 136
#define GBUF_WORDS 9472
#define GA_HI 0
#define GA_LO 2560
#define GB_HI 5120
#define GB_LO 7296
#define GT_SMEM_BYTES (2 * GBUF_WORDS * 4)

__global__ __launch_bounds__(256)
void gemm_tc(const uint32_t* __restrict__ Ahi_g, const uint32_t* __restrict__ Alo_g,
             const uint32_t* __restrict__ Bhi_g, const uint32_t* __restrict__ Blo_g,
             const float* __restrict__ bias, float* __restrict__ C,
             float* __restrict__ qd, float* __restrict__ kd, float* __restrict__ vd,
             const float* __restrict__ bdt,
             int M, int N, int K, int mode)
{
    extern __shared__ uint32_t smg[];
    const uint32_t sbase = (uint32_t)__cvta_generic_to_shared(smg);

    const int tid  = threadIdx.x;
    const int lane = tid & 31;
    const int warp = tid >> 5;
    const int wm   = warp & 1;
    const int wn   = warp >> 1;
    const int g    = lane >> 2;
    const int cq   = lane & 3;

    const int m0 = blockIdx.y * 128;
    const int n0 = blockIdx.x * 128;
    const int Kp = K >> 1;

    float acc[4][4][4];
#pragma unroll
    for (int mt = 0; mt < 4; mt++)
#pragma unroll
        for (int nt = 0; nt < 4; nt++)
#pragma unroll
            for (int r = 0; r < 4; r++) acc[mt][nt][r] = 0.0f;

    // cp.async slot mapping
    const int arow = tid >> 2;          // 0..63, x2 passes of 64
    const int aseg = (tid & 3) << 2;    // 16B segment within 16-word row
    const int brow = tid >> 5;          // 0..7, x2 passes of 8
    const int bseg = (tid & 31) << 2;   // 16B segment within 128-word row

    auto issue_chunk = [&](int c, int buf) {
        const int k0p = c * 16;
        const uint32_t bb = sbase + buf * GBUF_WORDS * 4;
        // A planes: rows of 16 contiguous pair-words
#pragma unroll
        for (int j = 0; j < 2; j++) {
            int row = arow + j * 64;
            size_t gi = (size_t)(m0 + row) * Kp + k0p + aseg;
            uint32_t so = (row * APK_STRIDE + aseg) * 4;
            cp_async16(bb + GA_HI * 4 + so, &Ahi_g[gi]);
            cp_async16(bb + GA_LO * 4 + so, &Alo_g[gi]);
        }
        // B planes: 16 pair-rows of 128 contiguous words
#pragma unroll
        for (int j = 0; j < 2; j++) {
            int row = brow + j * 8;
            size_t gi = (size_t)(k0p + row) * N + n0 + bseg;
            uint32_t so = (row * BPK_STRIDE + bseg) * 4;
            cp_async16(bb + GB_HI * 4 + so, &Bhi_g[gi]);
            cp_async16(bb + GB_LO * 4 + so, &Blo_g[gi]);
        }
    };

    // ldmatrix lane address components
    const int lrow = lane & 15;
    const int lcol = (lane >> 4) << 2;

    const int NC = Kp / 16;
    issue_chunk(0, 0); CP_COMMIT();
    issue_chunk(1, 1); CP_COMMIT();

    for (int c = 0; c < NC; c++) {
        const int buf = c & 1;
        if (c + 1 < NC) { CP_WAIT1(); } else { CP_WAIT0(); }
        __syncthreads();

        const uint32_t bb = sbase + buf * GBUF_WORDS * 4;
        const uint32_t* Bhi = smg + buf * GBUF_WORDS + GB_HI;
        const uint32_t* Blo = smg + buf * GBUF_WORDS + GB_LO;

#pragma unroll
        for (int kk = 0; kk < 2; kk++) {
            const int kb = kk * 8;
            uint32_t ah[4][4], al[4][4];
#pragma unroll
            for (int mt = 0; mt < 4; mt++) {
                const int mb = wm * 64 + mt * 16;
                uint32_t aoff = (((mb + lrow) * APK_STRIDE) + kb + lcol) * 4;
                ldsm_x4(ah[mt][0], ah[mt][1], ah[mt][2], ah[mt][3],
                        bb + GA_HI * 4 + aoff);
                ldsm_x4(al[mt][0], al[mt][1], al[mt][2], al[mt][3],
                        bb + GA_LO * 4 + aoff);
            }
            uint32_t bh[4][2], bl[4][2];
#pragma unroll
            for (int nt = 0; nt < 4; nt++) {
                const int nb = wn * 32 + nt * 8;
                bh[nt][0] = Bhi[(kb + cq) * BPK_STRIDE + nb + g];
                bh[nt][1] = Bhi[(kb + cq + 4) * BPK_STRIDE + nb + g];
                bl[nt][0] = Blo[(kb + cq) * BPK_STRIDE + nb + g];
                bl[nt][1] = Blo[(kb + cq + 4) * BPK_STRIDE + nb + g];
            }
#pragma unroll
            for (int mt = 0; mt < 4; mt++)
#pragma unroll
                for (int nt = 0; nt < 4; nt++) {
                    mma_bf16(acc[mt][nt], ah[mt], bh[nt]);
                    mma_bf16(acc[mt][nt], ah[mt], bl[nt]);
                    mma_bf16(acc[mt][nt], al[mt], bh[nt]);
                }
        }
        __syncthreads();
        if (c + 2 < NC) { issue_chunk(c + 2, buf); CP_COMMIT(); }
    }

    if (mode == 0) {
#pragma unroll
        for (int mt = 0; mt < 4; mt++) {
#pragma unroll
            for (int nt = 0; nt < 4; nt++) {
#pragma unroll
                for (int r = 0; r < 4; r++) {
                    int m = m0 + wm * 64 + mt * 16 + g + ((r >> 1) << 3);
                    int n = n0 + wn * 32 + nt * 8 + 2 * cq + (r & 1);
                    float v = acc[mt][nt][r] + bias[n];
                    int b = m & 1;
                    int s = m >> 1;
                    int head = n / (3 * DH);
                    int rem  = n - head * (3 * DH);
                    int part = rem >> 7;
                    int d    = rem & 127;
                    size_t bhbase = (size_t)(b * NH + head) * S_LEN * DH;
                    int ks = d >> 3, kk = d & 7;
                    if (part == 0) {
                        int qtile = s >> 7;
                        int wmr   = (s >> 4) & 7;
                        int r16   = s & 15;
                        int lt    = ((r16 & 7) << 2) + (kk & 3);
                        int rg    = (r16 >> 3) + ((kk >> 2) << 1);
                        size_t idx = bhbase + (size_t)qtile * 16384
                                   + (((ks * 8 + wmr) * 32 + lt) << 2) + rg;
                        qd[idx] = to_tf32(v);
                    } else if (part == 1) {
                        int ktile = s >> 6;
                        int ntk   = (s >> 3) & 7;
                        int lt    = ((s & 7) << 2) + (kk & 3);
                        int rg    = kk >> 2;
                        size_t idx = bhbase + (size_t)ktile * 8192
                                   + (((ks * 8 + ntk) * 32 + lt) << 1) + rg;
                        kd[idx] = to_tf32(v);
                    } else {
                        vd[bhbase + (size_t)s * DH + d] = v;
                    }
                }
            }
        }
    } else {
#pragma unroll
        for (int mt = 0; mt < 4; mt++) {
#pragma unroll
            for (int nt = 0; nt < 4; nt++) {
                int n = n0 + wn * 32 + nt * 8 + 2 * cq;
                int mA = m0 + wm * 64 + mt * 16 + g;
                int mB = mA + 8;
                float2 vA = make_float2(acc[mt][nt][0], acc[mt][nt][1]);
                float2 vB = make_float2(acc[mt][nt][2], acc[mt][nt][3]);
                *reinterpret_cast<float2*>(&C[(size_t)mA * N + n]) = vA;
                *reinterpret_cast<float2*>(&C[(size_t)mB * N + n]) = vB;
            }
        }
        if (bdt && blockIdx.x == 0 && blockIdx.y == 0) {
            for (int i = tid; i < H_DIM; i += 256)
                C[(size_t)M_ROWS * H_DIM + i] = bdt[i];
        }
    }
}

// ---------------------------------------------------------------------------
// Flash attention (unchanged from R13): FA2 register-resident, frag-ordered
// smem, cp.async double-buffered K/V. 256 threads, 192KB smem. ~606us.
// ---------------------------------------------------------------------------
#define ATT_THREADS 256
#define AQF_OFF  0
#define AKF_OFF  16384
#define AVH_OFF  32768
#define AVL_OFF  40960
#define ATT_SMEM_BYTES (49152 * 4)

__global__ __launch_bounds__(ATT_THREADS)
void attn_tc(const unsigned char* __restrict__ mask,
             const float* __restrict__ gq, const float* __restrict__ gk,
             const uint32_t* __restrict__ gvhi, const uint32_t* __restrict__ gvlo,
             uint32_t* __restrict__ gchi, uint32_t* __restrict__ gclo)
{
    extern __shared__ uint32_t smw[];
    uint4* Qf4 = reinterpret_cast<uint4*>(smw + AQF_OFF);

    const int tid  = threadIdx.x;
    const int lane = tid & 31;
    const int warp = tid >> 5;
    const int g    = lane >> 2;
    const int cq   = lane & 3;
    const int mb   = warp * 16;

    const int bh = blockIdx.y;
    const int b  = bh / NH;
    const int h  = bh - b * NH;
    const int q0 = blockIdx.x * 128;

    const uint32_t* qw = reinterpret_cast<const uint32_t*>(gq)
                       + (size_t)bh * S_LEN * DH + (size_t)blockIdx.x * 16384;
    const uint32_t* kw = reinterpret_cast<const uint32_t*>(gk)
                       + (size_t)bh * S_LEN * DH;
    const uint32_t* vhp = gvhi + (size_t)bh * (S_LEN / 2) * DH;
    const uint32_t* vlp = gvlo + (size_t)bh * (S_LEN / 2) * DH;
    const unsigned char* mp = mask + (size_t)b * S_LEN * S_LEN;
    const float inv_norm = 1.0f / sqrtf((float)H_DIM);

    auto issue_tile = [&](int kt, int buf) {
        const uint4* ksn = reinterpret_cast<const uint4*>(kw + (size_t)kt * 8192);
        uint32_t kb = (uint32_t)__cvta_generic_to_shared(smw + AKF_OFF + buf * 8192)
                    + tid * 16;
#pragma unroll
        for (int p = 0; p < 8; p++)
            cp_async16(kb + p * ATT_THREADS * 16, &ksn[tid + p * ATT_THREADS]);
        const uint4* vhn = reinterpret_cast<const uint4*>(vhp + (size_t)kt * 4096);
        const uint4* vln = reinterpret_cast<const uint4*>(vlp + (size_t)kt * 4096);
        uint32_t vhb = (uint32_t)__cvta_generic_to_shared(smw + AVH_OFF + buf * 4096)
                     + tid * 16;
        uint32_t vlb = (uint32_t)__cvta_generic_to_shared(smw + AVL_OFF + buf * 4096)
                     + tid * 16;
#pragma unroll
        for (int p = 0; p < 4; p++) {
            cp_async16(vhb + p * ATT_THREADS * 16, &vhn[tid + p * ATT_THREADS]);
            cp_async16(vlb + p * ATT_THREADS * 16, &vln[tid + p * ATT_THREADS]);
        }
    };

    issue_tile(0, 0); CP_COMMIT();
    issue_tile(1, 1); CP_COMMIT();
    {
        const uint4* src = reinterpret_cast<const uint4*>(qw);
#pragma unroll
        for (int p = 0; p < 16; p++)
            Qf4[tid + p * ATT_THREADS] = src[tid + p * ATT_THREADS];
    }
    CP_WAIT1();
    __syncthreads();

    float o[16][4];
#pragma unroll
    for (int nt = 0; nt < 16; nt++)
#pragma unroll
        for (int r = 0; r < 4; r++) o[nt][r] = 0.0f;
    float m0r = -INFINITY, m1r = -INFINITY;
    float l0r = 0.0f, l1r = 0.0f;

    const unsigned char* mr0 = mp + (size_t)(q0 + mb + g) * S_LEN;
    const unsigned char* mr1 = mp + (size_t)(q0 + mb + g + 8) * S_LEN;

    const int NT = S_LEN / 64;
    for (int kt = 0; kt < NT; kt++) {
        const int t0 = kt * 64;
        const int buf = kt & 1;
        const uint2* Kf2 = reinterpret_cast<const uint2*>(smw + AKF_OFF + buf * 8192);
        const uint2* Vh2 = reinterpret_cast<const uint2*>(smw + AVH_OFF + buf * 4096);
        const uint2* Vl2 = reinterpret_cast<const uint2*>(smw + AVL_OFF + buf * 4096);

        uchar2 mk0[8], mk1[8];
#pragma unroll
        for (int nt = 0; nt < 8; nt++) {
            int cc = t0 + nt * 8 + 2 * cq;
            mk0[nt] = *reinterpret_cast<const uchar2*>(mr0 + cc);
            mk1[nt] = *reinterpret_cast<const uchar2*>(mr1 + cc);
        }

        float s[8][4];
#pragma unroll
        for (int nt = 0; nt < 8; nt++)
#pragma unroll
            for (int r = 0; r < 4; r++) s[nt][r] = 0.0f;

#pragma unroll
        for (int ks = 0; ks < 16; ks++) {
            uint4 aq = Qf4[(ks * 8 + warp) * 32 + lane];
#pragma unroll
            for (int nt = 0; nt < 8; nt++) {
                uint2 bk = Kf2[(ks * 8 + nt) * 32 + lane];
                mma_tf32(s[nt], reinterpret_cast<uint32_t*>(&aq),
                         reinterpret_cast<uint32_t*>(&bk));
            }
        }

        float pmax0 = -INFINITY, pmax1 = -INFINITY;
#pragma unroll
        for (int nt = 0; nt < 8; nt++) {
            float v0 = s[nt][0] * inv_norm; if (mk0[nt].x) v0 = MASK_VALUE;
            float v1 = s[nt][1] * inv_norm; if (mk0[nt].y) v1 = MASK_VALUE;
            float v2 = s[nt][2] * inv_norm; if (mk1[nt].x) v2 = MASK_VALUE;
            float v3 = s[nt][3] * inv_norm; if (mk1[nt].y) v3 = MASK_VALUE;
            s[nt][0] = v0; s[nt][1] = v1; s[nt][2] = v2; s[nt][3] = v3;
            pmax0 = fmaxf(pmax0, fmaxf(v0, v1));
            pmax1 = fmaxf(pmax1, fmaxf(v2, v3));
        }
        pmax0 = fmaxf(pmax0, __shfl_xor_sync(0xffffffffu, pmax0, 1));
        pmax0 = fmaxf(pmax0, __shfl_xor_sync(0xffffffffu, pmax0, 2));
        pmax1 = fmaxf(pmax1, __shfl_xor_sync(0xffffffffu, pmax1, 1));
        pmax1 = fmaxf(pmax1, __shfl_xor_sync(0xffffffffu, pmax1, 2));

        float mn0 = fmaxf(m0r, pmax0);
        float mn1 = fmaxf(m1r, pmax1);
        float alpha0 = __expf(m0r - mn0);
        float alpha1 = __expf(m1r - mn1);

        uint32_t ph[4][4], pl[4][4];
        float sum0 = 0.0f, sum1 = 0.0f;
#pragma unroll
        for (int nt = 0; nt < 8; nt++) {
            float p0 = __expf(s[nt][0] - mn0);
            float p1 = __expf(s[nt][1] - mn0);
            float p2 = __expf(s[nt][2] - mn1);
            float p3 = __expf(s[nt][3] - mn1);
            sum0 += p0 + p1;
            sum1 += p2 + p3;
            int ks  = nt >> 1;
            int half = nt & 1;
            split2_pack(p0, p1, ph[ks][half * 2 + 0], pl[ks][half * 2 + 0]);
            split2_pack(p2, p3, ph[ks][half * 2 + 1], pl[ks][half * 2 + 1]);
        }
        sum0 += __shfl_xor_sync(0xffffffffu, sum0, 1);
        sum0 += __shfl_xor_sync(0xffffffffu, sum0, 2);
        sum1 += __shfl_xor_sync(0xffffffffu, sum1, 1);
        sum1 += __shfl_xor_sync(0xffffffffu, sum1, 2);

        l0r = l0r * alpha0 + sum0;
        l1r = l1r * alpha1 + sum1;
        m0r = mn0; m1r = mn1;

#pragma unroll
        for (int nt = 0; nt < 16; nt++) {
            o[nt][0] *= alpha0; o[nt][1] *= alpha0;
            o[nt][2] *= alpha1; o[nt][3] *= alpha1;
        }

#pragma unroll
        for (int ks = 0; ks < 4; ks++) {
#pragma unroll
            for (int nt = 0; nt < 16; nt++) {
                uint2 bhv = Vh2[(ks * 16 + nt) * 32 + lane];
                uint2 blv = Vl2[(ks * 16 + nt) * 32 + lane];
                mma_bf16(o[nt], ph[ks], reinterpret_cast<uint32_t*>(&bhv));
                mma_bf16(o[nt], ph[ks], reinterpret_cast<uint32_t*>(&blv));
                mma_bf16(o[nt], pl[ks], reinterpret_cast<uint32_t*>(&bhv));
            }
        }
        __syncthreads();

        if (kt + 1 < NT) {
            if (kt + 2 < NT) {
                issue_tile(kt + 2, buf);
                CP_COMMIT();
                CP_WAIT1();
            } else {
                CP_WAIT0();
            }
            __syncthreads();
        }
    }

    {
        float li0 = 1.0f / l0r;
        float li1 = 1.0f / l1r;
        int s0r = q0 + mb + g;
        int s1r = s0r + 8;
#pragma unroll
        for (int nt = 0; nt < 16; nt++) {
            int colw = h * (DH / 2) + nt * 4 + cq;
            uint32_t hw0, lw0, hw1, lw1;
            split2_pack(o[nt][0] * li0, o[nt][1] * li0, hw0, lw0);
            split2_pack(o[nt][2] * li1, o[nt][3] * li1, hw1, lw1);
            size_t r0 = ((size_t)s0r * B_SZ + b) * HP + colw;
            size_t r1 = ((size_t)s1r * B_SZ + b) * HP + colw;
            gchi[r0] = hw0; gclo[r0] = lw0;
            gchi[r1] = hw1; gclo[r1] = lw1;
        }
    }
}

extern "C" void kernel_launch(void* const* d_in, const int* in_sizes, int n_in,
                              void* d_out, int out_size)
{
    const float* hidden = (const float*)d_in[0];
    const unsigned char* mask = (const unsigned char*)d_in[1];
    const float* W_qkv = (const float*)d_in[2];
    const float* b_qkv = (const float*)d_in[3];
    const float* W_dense = (const float*)d_in[4];
    const float* b_dense = (const float*)d_in[5];
    float* out = (float*)d_out;

    float *qd, *kd, *vd;
    uint32_t *ahi, *alo, *wqhi, *wqlo, *wdhi, *wdlo, *chi, *clo, *vhi, *vlo;
    cudaGetSymbolAddress((void**)&qd,   g_q);
    cudaGetSymbolAddress((void**)&kd,   g_k);
    cudaGetSymbolAddress((void**)&vd,   g_v);
    cudaGetSymbolAddress((void**)&ahi,  g_ahi);
    cudaGetSymbolAddress((void**)&alo,  g_alo);
    cudaGetSymbolAddress((void**)&wqhi, g_wqhi);
    cudaGetSymbolAddress((void**)&wqlo, g_wqlo);
    cudaGetSymbolAddress((void**)&wdhi, g_wdhi);
    cudaGetSymbolAddress((void**)&wdlo, g_wdlo);
    cudaGetSymbolAddress((void**)&chi,  g_chi);
    cudaGetSymbolAddress((void**)&clo,  g_clo);
    cudaGetSymbolAddress((void**)&vhi,  g_vhi);
    cudaGetSymbolAddress((void**)&vlo,  g_vlo);

    cudaFuncSetAttribute(gemm_tc,
                         cudaFuncAttributeMaxDynamicSharedMemorySize,
                         GT_SMEM_BYTES);
    cudaFuncSetAttribute(attn_tc,
                         cudaFuncAttributeMaxDynamicSharedMemorySize,
                         ATT_SMEM_BYTES);

    const float* bdt = (out_size >= M_ROWS * H_DIM + H_DIM) ? b_dense : nullptr;

    // [1] Fused presplit of all GEMM inputs
    {
        long total = PS_TOTAL;
        presplit_all<<<(unsigned)((total + 255) / 256), 256>>>(
            hidden, W_qkv, W_dense, ahi, alo, wqhi, wqlo, wdhi, wdlo);
    }
    // [2] QKV GEMM (cp.async double-buffered) + scatter
    {
        dim3 grid(N3 / 128, M_ROWS / 128);
        gemm_tc<<<grid, 256, GT_SMEM_BYTES>>>(ahi, alo, wqhi, wqlo, b_qkv, nullptr,
                                              qd, kd, vd, nullptr,
                                              M_ROWS, N3, H_DIM, 0);
    }
    // [3] Pre-split V into frag order
    {
        long vw = (long)B_SZ * NH * (S_LEN / 2) * DH;
        presplit_v_frag<<<(unsigned)((vw + 255) / 256), 256>>>(vd, vhi, vlo, vw);
    }
    // [4] Flash attention  (ncu capture slot)
    {
        dim3 grid(S_LEN / 128, B_SZ * NH);
        attn_tc<<<grid, ATT_THREADS, ATT_SMEM_BYTES>>>(mask, qd, kd, vhi, vlo, chi, clo);
    }
    // [5] Dense GEMM -> out (+ folded b_dense tail)
    {
        dim3 grid(H_DIM / 128, M_ROWS / 128);
        gemm_tc<<<grid, 256, GT_SMEM_BYTES>>>(chi, clo, wdhi, wdlo, nullptr, out,
                                              nullptr, nullptr, nullptr, bdt,
                                              M_ROWS, H_DIM, H_DIM, 1);
    }
}

// round 16
// speedup vs baseline: 3.3387x; 1.0155x over previous
#include <cuda_runtime.h>
#include <cuda_bf16.h>
#include <math.h>
#include <stdint.h>

// Problem constants
#define S_LEN 2048
#define B_SZ  2
#define H_DIM 2048
#define NH    16
#define DH    128
#define N3    (3 * H_DIM)          // 6144
#define M_ROWS (S_LEN * B_SZ)      // 4096
#define HP    (H_DIM / 2)          // 1024 pair-words per row
#define MASK_VALUE (-10000.0f)
#define LOG2E 1.44269504088896f

// scratch
__device__ float g_q[B_SZ * NH * S_LEN * DH];   // tf32 A-frag order per q-tile
__device__ float g_k[B_SZ * NH * S_LEN * DH];   // tf32 B-frag order per k-tile
__device__ float g_v[B_SZ * NH * S_LEN * DH];   // linear fp32 [bh][s][d]
// pre-split bf16-pair words: a/ctx rows [M][K/2]; W cols [K/2][N]
__device__ uint32_t g_ahi[M_ROWS * HP];
__device__ uint32_t g_alo[M_ROWS * HP];
__device__ uint32_t g_wqhi[HP * N3];
__device__ uint32_t g_wqlo[HP * N3];
__device__ uint32_t g_wdhi[HP * H_DIM];
__device__ uint32_t g_wdlo[HP * H_DIM];
__device__ uint32_t g_chi[M_ROWS * HP];
__device__ uint32_t g_clo[M_ROWS * HP];
// v in bf16 B-frag (n8k16) order per 64-key tile
__device__ uint32_t g_vhi[B_SZ * NH * (S_LEN/2) * DH];
__device__ uint32_t g_vlo[B_SZ * NH * (S_LEN/2) * DH];

// ---------------------------------------------------------------------------
// helpers
// ---------------------------------------------------------------------------
__device__ __forceinline__ float to_tf32(float x)
{
    uint32_t u;
    asm("cvt.rna.tf32.f32 %0, %1;" : "=r"(u) : "f"(x));
    return __uint_as_float(u);
}

__device__ __forceinline__ void mma_tf32(float* c, const uint32_t* a, const uint32_t* b)
{
    asm volatile(
        "mma.sync.aligned.m16n8k8.row.col.f32.tf32.tf32.f32 "
        "{%0,%1,%2,%3}, {%4,%5,%6,%7}, {%8,%9}, {%0,%1,%2,%3};"
        : "+f"(c[0]), "+f"(c[1]), "+f"(c[2]), "+f"(c[3])
        : "r"(a[0]), "r"(a[1]), "r"(a[2]), "r"(a[3]),
          "r"(b[0]), "r"(b[1]));
}

__device__ __forceinline__ void mma_bf16(float* c, const uint32_t* a, const uint32_t* b)
{
    asm volatile(
        "mma.sync.aligned.m16n8k16.row.col.f32.bf16.bf16.f32 "
        "{%0,%1,%2,%3}, {%4,%5,%6,%7}, {%8,%9}, {%0,%1,%2,%3};"
        : "+f"(c[0]), "+f"(c[1]), "+f"(c[2]), "+f"(c[3])
        : "r"(a[0]), "r"(a[1]), "r"(a[2]), "r"(a[3]),
          "r"(b[0]), "r"(b[1]));
}

__device__ __forceinline__ void ldsm_x4(uint32_t& r0, uint32_t& r1,
                                        uint32_t& r2, uint32_t& r3, uint32_t addr)
{
    asm volatile("ldmatrix.sync.aligned.m8n8.x4.shared.b16 {%0,%1,%2,%3}, [%4];"
                 : "=r"(r0), "=r"(r1), "=r"(r2), "=r"(r3) : "r"(addr));
}

__device__ __forceinline__ void split2_pack(float x0, float x1,
                                            uint32_t& hi, uint32_t& lo)
{
    __nv_bfloat16 h0 = __float2bfloat16_rn(x0);
    __nv_bfloat16 h1 = __float2bfloat16_rn(x1);
    __nv_bfloat16 l0 = __float2bfloat16_rn(x0 - __bfloat162float(h0));
    __nv_bfloat16 l1 = __float2bfloat16_rn(x1 - __bfloat162float(h1));
    __nv_bfloat162 hp = __halves2bfloat162(h0, h1);
    __nv_bfloat162 lp = __halves2bfloat162(l0, l1);
    hi = *reinterpret_cast<uint32_t*>(&hp);
    lo = *reinterpret_cast<uint32_t*>(&lp);
}

__device__ __forceinline__ void cp_async16(uint32_t smem_addr, const void* gptr)
{
    asm volatile("cp.async.cg.shared.global [%0], [%1], 16;"
                 :: "r"(smem_addr), "l"(gptr));
}
#define CP_COMMIT() asm volatile("cp.async.commit_group;")
#define CP_WAIT1()  asm volatile("cp.async.wait_group 1;")
#define CP_WAIT0()  asm volatile("cp.async.wait_group 0;")

// ---------------------------------------------------------------------------
// Fused input presplit (hidden rows + W_qkv cols + W_dense cols)
// ---------------------------------------------------------------------------
#define PS_F4 ((long)M_ROWS * H_DIM / 4)
#define PS_WQ ((long)HP * N3)
#define PS_WD ((long)HP * H_DIM)
#define PS_TOTAL (PS_F4 + PS_WQ + PS_WD)

__global__ void presplit_all(const float* __restrict__ hidden,
                             const float* __restrict__ wq,
                             const float* __restrict__ wdn,
                             uint32_t* __restrict__ ahi, uint32_t* __restrict__ alo,
                             uint32_t* __restrict__ wqhi, uint32_t* __restrict__ wqlo,
                             uint32_t* __restrict__ wdhi, uint32_t* __restrict__ wdlo)
{
    long i = (long)blockIdx.x * blockDim.x + threadIdx.x;
    if (i < PS_F4) {
        float4 v = reinterpret_cast<const float4*>(hidden)[i];
        uint32_t h0, l0, h1, l1;
        split2_pack(v.x, v.y, h0, l0);
        split2_pack(v.z, v.w, h1, l1);
        reinterpret_cast<uint2*>(ahi)[i] = make_uint2(h0, h1);
        reinterpret_cast<uint2*>(alo)[i] = make_uint2(l0, l1);
    } else if (i < PS_F4 + PS_WQ) {
        long w = i - PS_F4;
        long pr = w / N3;
        int  n  = (int)(w - pr * N3);
        float a = wq[(2 * pr) * (long)N3 + n];
        float b = wq[(2 * pr + 1) * (long)N3 + n];
        uint32_t h, l;
        split2_pack(a, b, h, l);
        wqhi[w] = h; wqlo[w] = l;
    } else if (i < PS_TOTAL) {
        long w = i - PS_F4 - PS_WQ;
        long pr = w / H_DIM;
        int  n  = (int)(w - pr * H_DIM);
        float a = wdn[(2 * pr) * (long)H_DIM + n];
        float b = wdn[(2 * pr + 1) * (long)H_DIM + n];
        uint32_t h, l;
        split2_pack(a, b, h, l);
        wdhi[w] = h; wdlo[w] = l;
    }
}

// V: linear fp32 [bh][s][d] -> bf16 hi/lo in B-frag (n8k16) order per 64-key tile.
__global__ void presplit_v_frag(const float* __restrict__ vd,
                                uint32_t* __restrict__ hi, uint32_t* __restrict__ lo,
                                long total_words)
{
    long w = (long)blockIdx.x * blockDim.x + threadIdx.x;
    if (w >= total_words) return;
    long bhw  = w >> 17;
    int  rem  = (int)(w & 131071);
    int  tile = rem >> 12;
    int  r2   = rem & 4095;
    int  reg  = r2 & 1;
    int  t2   = r2 >> 1;
    int  lane = t2 & 31;
    int  t3   = t2 >> 5;
    int  nt   = t3 & 15;
    int  ks   = t3 >> 4;
    int  gt   = lane >> 2;
    int  cqq  = lane & 3;
    int  pwi  = cqq + (reg << 2);
    int  s0   = tile * 64 + (ks * 8 + pwi) * 2;
    int  d    = nt * 8 + gt;
    const float* vb = vd + bhw * (long)S_LEN * DH;
    float a = vb[(size_t)s0 * DH + d];
    float b = vb[(size_t)(s0 + 1) * DH + d];
    uint32_t h, l;
    split2_pack(a, b, h, l);
    hi[w] = h; lo[w] = l;
}

// ---------------------------------------------------------------------------
// Tensor-core GEMM — 3-stage cp.async pipeline, ONE barrier per chunk,
// ldmatrix A frags. 128x128 tile, 256 thr, warp 64x32, K-chunk 32 floats.
// Buffer = Ahi|Alo [128][20] + Bhi|Blo [16][136] = 9472 words; x3 = 113664 B.
// ---------------------------------------------------------------------------
#define APK_STRIDE 20
#define BPK_STRIDE 136
#define GBUF_WORDS 9472
#define GA_HI 0
#define GA_LO 2560
#define GB_HI 5120
#define GB_LO 7296
#define GT_SMEM_BYTES (3 * GBUF_WORDS * 4)

__global__ __launch_bounds__(256)
void gemm_tc(const uint32_t* __restrict__ Ahi_g, const uint32_t* __restrict__ Alo_g,
             const uint32_t* __restrict__ Bhi_g, const uint32_t* __restrict__ Blo_g,
             const float* __restrict__ bias, float* __restrict__ C,
             float* __restrict__ qd, float* __restrict__ kd, float* __restrict__ vd,
             const float* __restrict__ bdt,
             int M, int N, int K, int mode)
{
    extern __shared__ uint32_t smg[];
    const uint32_t sbase = (uint32_t)__cvta_generic_to_shared(smg);

    const int tid  = threadIdx.x;
    const int lane = tid & 31;
    const int warp = tid >> 5;
    const int wm   = warp & 1;
    const int wn   = warp >> 1;
    const int g    = lane >> 2;
    const int cq   = lane & 3;

    const int m0 = blockIdx.y * 128;
    const int n0 = blockIdx.x * 128;
    const int Kp = K >> 1;

    float acc[4][4][4];
#pragma unroll
    for (int mt = 0; mt < 4; mt++)
#pragma unroll
        for (int nt = 0; nt < 4; nt++)
#pragma unroll
            for (int r = 0; r < 4; r++) acc[mt][nt][r] = 0.0f;

    const int arow = tid >> 2;
    const int aseg = (tid & 3) << 2;
    const int brow = tid >> 5;
    const int bseg = (tid & 31) << 2;

    auto issue_chunk = [&](int c, int buf) {
        const int k0p = c * 16;
        const uint32_t bb = sbase + buf * GBUF_WORDS * 4;
#pragma unroll
        for (int j = 0; j < 2; j++) {
            int row = arow + j * 64;
            size_t gi = (size_t)(m0 + row) * Kp + k0p + aseg;
            uint32_t so = (row * APK_STRIDE + aseg) * 4;
            cp_async16(bb + GA_HI * 4 + so, &Ahi_g[gi]);
            cp_async16(bb + GA_LO * 4 + so, &Alo_g[gi]);
        }
#pragma unroll
        for (int j = 0; j < 2; j++) {
            int row = brow + j * 8;
            size_t gi = (size_t)(k0p + row) * N + n0 + bseg;
            uint32_t so = (row * BPK_STRIDE + bseg) * 4;
            cp_async16(bb + GB_HI * 4 + so, &Bhi_g[gi]);
            cp_async16(bb + GB_LO * 4 + so, &Blo_g[gi]);
        }
    };

    const int lrow = lane & 15;
    const int lcol = (lane >> 4) << 2;

    const int NC = Kp / 16;
    issue_chunk(0, 0); CP_COMMIT();
    issue_chunk(1, 1); CP_COMMIT();

    int buf = 0;
    for (int c = 0; c < NC; c++) {
        if (c + 1 < NC) { CP_WAIT1(); } else { CP_WAIT0(); }
        __syncthreads();          // chunk c resident; buf (c+2)%3 drained (read at c-1)
        if (c + 2 < NC) { issue_chunk(c + 2, (buf + 2 >= 3) ? buf - 1 : buf + 2); CP_COMMIT(); }

        const uint32_t bb = sbase + buf * GBUF_WORDS * 4;
        const uint32_t* Bhi = smg + buf * GBUF_WORDS + GB_HI;
        const uint32_t* Blo = smg + buf * GBUF_WORDS + GB_LO;

#pragma unroll
        for (int kk = 0; kk < 2; kk++) {
            const int kb = kk * 8;
            uint32_t ah[4][4], al[4][4];
#pragma unroll
            for (int mt = 0; mt < 4; mt++) {
                const int mb = wm * 64 + mt * 16;
                uint32_t aoff = (((mb + lrow) * APK_STRIDE) + kb + lcol) * 4;
                ldsm_x4(ah[mt][0], ah[mt][1], ah[mt][2], ah[mt][3],
                        bb + GA_HI * 4 + aoff);
                ldsm_x4(al[mt][0], al[mt][1], al[mt][2], al[mt][3],
                        bb + GA_LO * 4 + aoff);
            }
            uint32_t bh[4][2], bl[4][2];
#pragma unroll
            for (int nt = 0; nt < 4; nt++) {
                const int nb = wn * 32 + nt * 8;
                bh[nt][0] = Bhi[(kb + cq) * BPK_STRIDE + nb + g];
                bh[nt][1] = Bhi[(kb + cq + 4) * BPK_STRIDE + nb + g];
                bl[nt][0] = Blo[(kb + cq) * BPK_STRIDE + nb + g];
                bl[nt][1] = Blo[(kb + cq + 4) * BPK_STRIDE + nb + g];
            }
#pragma unroll
            for (int mt = 0; mt < 4; mt++)
#pragma unroll
                for (int nt = 0; nt < 4; nt++) {
                    mma_bf16(acc[mt][nt], ah[mt], bh[nt]);
                    mma_bf16(acc[mt][nt], ah[mt], bl[nt]);
                    mma_bf16(acc[mt][nt], al[mt], bh[nt]);
                }
        }
        buf = (buf + 1 == 3) ? 0 : buf + 1;
    }

    if (mode == 0) {
#pragma unroll
        for (int mt = 0; mt < 4; mt++) {
#pragma unroll
            for (int nt = 0; nt < 4; nt++) {
#pragma unroll
                for (int r = 0; r < 4; r++) {
                    int m = m0 + wm * 64 + mt * 16 + g + ((r >> 1) << 3);
                    int n = n0 + wn * 32 + nt * 8 + 2 * cq + (r & 1);
                    float v = acc[mt][nt][r] + bias[n];
                    int b = m & 1;
                    int s = m >> 1;
                    int head = n / (3 * DH);
                    int rem  = n - head * (3 * DH);
                    int part = rem >> 7;
                    int d    = rem & 127;
                    size_t bhbase = (size_t)(b * NH + head) * S_LEN * DH;
                    int ks = d >> 3, kk = d & 7;
                    if (part == 0) {
                        int qtile = s >> 7;
                        int wmr   = (s >> 4) & 7;
                        int r16   = s & 15;
                        int lt    = ((r16 & 7) << 2) + (kk & 3);
                        int rg    = (r16 >> 3) + ((kk >> 2) << 1);
                        size_t idx = bhbase + (size_t)qtile * 16384
                                   + (((ks * 8 + wmr) * 32 + lt) << 2) + rg;
                        qd[idx] = to_tf32(v);
                    } else if (part == 1) {
                        int ktile = s >> 6;
                        int ntk   = (s >> 3) & 7;
                        int lt    = ((s & 7) << 2) + (kk & 3);
                        int rg    = kk >> 2;
                        size_t idx = bhbase + (size_t)ktile * 8192
                                   + (((ks * 8 + ntk) * 32 + lt) << 1) + rg;
                        kd[idx] = to_tf32(v);
                    } else {
                        vd[bhbase + (size_t)s * DH + d] = v;
                    }
                }
            }
        }
    } else {
#pragma unroll
        for (int mt = 0; mt < 4; mt++) {
#pragma unroll
            for (int nt = 0; nt < 4; nt++) {
                int n = n0 + wn * 32 + nt * 8 + 2 * cq;
                int mA = m0 + wm * 64 + mt * 16 + g;
                int mB = mA + 8;
                float2 vA = make_float2(acc[mt][nt][0], acc[mt][nt][1]);
                float2 vB = make_float2(acc[mt][nt][2], acc[mt][nt][3]);
                *reinterpret_cast<float2*>(&C[(size_t)mA * N + n]) = vA;
                *reinterpret_cast<float2*>(&C[(size_t)mB * N + n]) = vB;
            }
        }
        if (bdt && blockIdx.x == 0 && blockIdx.y == 0) {
            for (int i = tid; i < H_DIM; i += 256)
                C[(size_t)M_ROWS * H_DIM + i] = bdt[i];
        }
    }
}

// ---------------------------------------------------------------------------
// Flash attention: FA2 register-resident, frag-ordered smem, cp.async
// double-buffered K/V + MASK tile. Softmax in exp2 domain. 256 threads.
// smem words: Qf 16384 | Kf 2x8192 | Vhi 2x4096 | Vlo 2x4096 | Mask 2x2048
// ---------------------------------------------------------------------------
#define ATT_THREADS 256
#define AQF_OFF  0
#define AKF_OFF  16384
#define AVH_OFF  32768
#define AVL_OFF  40960
#define AMS_OFF  49152
#define ATT_SMEM_BYTES ((49152 + 4096) * 4)

__global__ __launch_bounds__(ATT_THREADS)
void attn_tc(const unsigned char* __restrict__ mask,
             const float* __restrict__ gq, const float* __restrict__ gk,
             const uint32_t* __restrict__ gvhi, const uint32_t* __restrict__ gvlo,
             uint32_t* __restrict__ gchi, uint32_t* __restrict__ gclo)
{
    extern __shared__ uint32_t smw[];
    uint4* Qf4 = reinterpret_cast<uint4*>(smw + AQF_OFF);

    const int tid  = threadIdx.x;
    const int lane = tid & 31;
    const int warp = tid >> 5;
    const int g    = lane >> 2;
    const int cq   = lane & 3;
    const int mb   = warp * 16;

    const int bh = blockIdx.y;
    const int b  = bh / NH;
    const int h  = bh - b * NH;
    const int q0 = blockIdx.x * 128;

    const uint32_t* qw = reinterpret_cast<const uint32_t*>(gq)
                       + (size_t)bh * S_LEN * DH + (size_t)blockIdx.x * 16384;
    const uint32_t* kw = reinterpret_cast<const uint32_t*>(gk)
                       + (size_t)bh * S_LEN * DH;
    const uint32_t* vhp = gvhi + (size_t)bh * (S_LEN / 2) * DH;
    const uint32_t* vlp = gvlo + (size_t)bh * (S_LEN / 2) * DH;
    const unsigned char* mp = mask + (size_t)b * S_LEN * S_LEN;
    // exp2-domain scale: scores * (1/sqrt(H)) * log2(e)
    const float sc   = (1.0f / sqrtf((float)H_DIM)) * LOG2E;
    const float mval = MASK_VALUE * sc;

    auto issue_tile = [&](int kt, int buf) {
        const int t0 = kt * 64;
        const uint4* ksn = reinterpret_cast<const uint4*>(kw + (size_t)kt * 8192);
        uint32_t kb = (uint32_t)__cvta_generic_to_shared(smw + AKF_OFF + buf * 8192)
                    + tid * 16;
#pragma unroll
        for (int p = 0; p < 8; p++)
            cp_async16(kb + p * ATT_THREADS * 16, &ksn[tid + p * ATT_THREADS]);
        const uint4* vhn = reinterpret_cast<const uint4*>(vhp + (size_t)kt * 4096);
        const uint4* vln = reinterpret_cast<const uint4*>(vlp + (size_t)kt * 4096);
        uint32_t vhb = (uint32_t)__cvta_generic_to_shared(smw + AVH_OFF + buf * 4096)
                     + tid * 16;
        uint32_t vlb = (uint32_t)__cvta_generic_to_shared(smw + AVL_OFF + buf * 4096)
                     + tid * 16;
#pragma unroll
        for (int p = 0; p < 4; p++) {
            cp_async16(vhb + p * ATT_THREADS * 16, &vhn[tid + p * ATT_THREADS]);
            cp_async16(vlb + p * ATT_THREADS * 16, &vln[tid + p * ATT_THREADS]);
        }
        // mask tile: 128 rows x 64 B -> 512 x 16B segments
        uint32_t mbs = (uint32_t)__cvta_generic_to_shared(smw + AMS_OFF + buf * 2048);
#pragma unroll
        for (int p = 0; p < 2; p++) {
            int seg = tid + p * ATT_THREADS;
            int row = seg >> 2;
            int col = (seg & 3) << 4;
            cp_async16(mbs + seg * 16, mp + (size_t)(q0 + row) * S_LEN + t0 + col);
        }
    };

    issue_tile(0, 0); CP_COMMIT();
    issue_tile(1, 1); CP_COMMIT();
    {
        const uint4* src = reinterpret_cast<const uint4*>(qw);
#pragma unroll
        for (int p = 0; p < 16; p++)
            Qf4[tid + p * ATT_THREADS] = src[tid + p * ATT_THREADS];
    }
    CP_WAIT1();
    __syncthreads();

    float o[16][4];
#pragma unroll
    for (int nt = 0; nt < 16; nt++)
#pragma unroll
        for (int r = 0; r < 4; r++) o[nt][r] = 0.0f;
    float m0r = -INFINITY, m1r = -INFINITY;
    float l0r = 0.0f, l1r = 0.0f;

    const int NT = S_LEN / 64;
    for (int kt = 0; kt < NT; kt++) {
        const int buf = kt & 1;
        const uint2* Kf2 = reinterpret_cast<const uint2*>(smw + AKF_OFF + buf * 8192);
        const uint2* Vh2 = reinterpret_cast<const uint2*>(smw + AVH_OFF + buf * 4096);
        const uint2* Vl2 = reinterpret_cast<const uint2*>(smw + AVL_OFF + buf * 4096);
        const unsigned char* Msk =
            reinterpret_cast<const unsigned char*>(smw + AMS_OFF + buf * 2048);

        // --- QK^T (tf32): warp m16 x n64, S in registers ---
        float s[8][4];
#pragma unroll
        for (int nt = 0; nt < 8; nt++)
#pragma unroll
            for (int r = 0; r < 4; r++) s[nt][r] = 0.0f;

#pragma unroll
        for (int ks = 0; ks < 16; ks++) {
            uint4 aq = Qf4[(ks * 8 + warp) * 32 + lane];
#pragma unroll
            for (int nt = 0; nt < 8; nt++) {
                uint2 bk = Kf2[(ks * 8 + nt) * 32 + lane];
                mma_tf32(s[nt], reinterpret_cast<uint32_t*>(&aq),
                         reinterpret_cast<uint32_t*>(&bk));
            }
        }

        // --- scale + mask (smem), exp2 domain ---
        const unsigned char* msk0 = Msk + (mb + g) * 64 + 2 * cq;
        const unsigned char* msk1 = Msk + (mb + g + 8) * 64 + 2 * cq;
        float pmax0 = -INFINITY, pmax1 = -INFINITY;
#pragma unroll
        for (int nt = 0; nt < 8; nt++) {
            uchar2 mk0 = *reinterpret_cast<const uchar2*>(msk0 + nt * 8);
            uchar2 mk1 = *reinterpret_cast<const uchar2*>(msk1 + nt * 8);
            float v0 = s[nt][0] * sc; if (mk0.x) v0 = mval;
            float v1 = s[nt][1] * sc; if (mk0.y) v1 = mval;
            float v2 = s[nt][2] * sc; if (mk1.x) v2 = mval;
            float v3 = s[nt][3] * sc; if (mk1.y) v3 = mval;
            s[nt][0] = v0; s[nt][1] = v1; s[nt][2] = v2; s[nt][3] = v3;
            pmax0 = fmaxf(pmax0, fmaxf(v0, v1));
            pmax1 = fmaxf(pmax1, fmaxf(v2, v3));
        }
        pmax0 = fmaxf(pmax0, __shfl_xor_sync(0xffffffffu, pmax0, 1));
        pmax0 = fmaxf(pmax0, __shfl_xor_sync(0xffffffffu, pmax0, 2));
        pmax1 = fmaxf(pmax1, __shfl_xor_sync(0xffffffffu, pmax1, 1));
        pmax1 = fmaxf(pmax1, __shfl_xor_sync(0xffffffffu, pmax1, 2));

        float mn0 = fmaxf(m0r, pmax0);
        float mn1 = fmaxf(m1r, pmax1);
        float alpha0 = exp2f(m0r - mn0);
        float alpha1 = exp2f(m1r - mn1);

        uint32_t ph[4][4], pl[4][4];
        float sum0 = 0.0f, sum1 = 0.0f;
#pragma unroll
        for (int nt = 0; nt < 8; nt++) {
            float p0 = exp2f(s[nt][0] - mn0);
            float p1 = exp2f(s[nt][1] - mn0);
            float p2 = exp2f(s[nt][2] - mn1);
            float p3 = exp2f(s[nt][3] - mn1);
            sum0 += p0 + p1;
            sum1 += p2 + p3;
            int ks  = nt >> 1;
            int half = nt & 1;
            split2_pack(p0, p1, ph[ks][half * 2 + 0], pl[ks][half * 2 + 0]);
            split2_pack(p2, p3, ph[ks][half * 2 + 1], pl[ks][half * 2 + 1]);
        }
        sum0 += __shfl_xor_sync(0xffffffffu, sum0, 1);
        sum0 += __shfl_xor_sync(0xffffffffu, sum0, 2);
        sum1 += __shfl_xor_sync(0xffffffffu, sum1, 1);
        sum1 += __shfl_xor_sync(0xffffffffu, sum1, 2);

        l0r = l0r * alpha0 + sum0;
        l1r = l1r * alpha1 + sum1;
        m0r = mn0; m1r = mn1;

#pragma unroll
        for (int nt = 0; nt < 16; nt++) {
            o[nt][0] *= alpha0; o[nt][1] *= alpha0;
            o[nt][2] *= alpha1; o[nt][3] *= alpha1;
        }

        // --- P@V (bf16 3-split), V frag-ordered ---
#pragma unroll
        for (int ks = 0; ks < 4; ks++) {
#pragma unroll
            for (int nt = 0; nt < 16; nt++) {
                uint2 bhv = Vh2[(ks * 16 + nt) * 32 + lane];
                uint2 blv = Vl2[(ks * 16 + nt) * 32 + lane];
                mma_bf16(o[nt], ph[ks], reinterpret_cast<uint32_t*>(&bhv));
                mma_bf16(o[nt], ph[ks], reinterpret_cast<uint32_t*>(&blv));
                mma_bf16(o[nt], pl[ks], reinterpret_cast<uint32_t*>(&bhv));
            }
        }
        __syncthreads();

        if (kt + 1 < NT) {
            if (kt + 2 < NT) {
                issue_tile(kt + 2, buf);
                CP_COMMIT();
                CP_WAIT1();
            } else {
                CP_WAIT0();
            }
            __syncthreads();
        }
    }

    {
        float li0 = 1.0f / l0r;
        float li1 = 1.0f / l1r;
        int s0r = q0 + mb + g;
        int s1r = s0r + 8;
#pragma unroll
        for (int nt = 0; nt < 16; nt++) {
            int colw = h * (DH / 2) + nt * 4 + cq;
            uint32_t hw0, lw0, hw1, lw1;
            split2_pack(o[nt][0] * li0, o[nt][1] * li0, hw0, lw0);
            split2_pack(o[nt][2] * li1, o[nt][3] * li1, hw1, lw1);
            size_t r0 = ((size_t)s0r * B_SZ + b) * HP + colw;
            size_t r1 = ((size_t)s1r * B_SZ + b) * HP + colw;
            gchi[r0] = hw0; gclo[r0] = lw0;
            gchi[r1] = hw1; gclo[r1] = lw1;
        }
    }
}

extern "C" void kernel_launch(void* const* d_in, const int* in_sizes, int n_in,
                              void* d_out, int out_size)
{
    const float* hidden = (const float*)d_in[0];
    const unsigned char* mask = (const unsigned char*)d_in[1];
    const float* W_qkv = (const float*)d_in[2];
    const float* b_qkv = (const float*)d_in[3];
    const float* W_dense = (const float*)d_in[4];
    const float* b_dense = (const float*)d_in[5];
    float* out = (float*)d_out;

    float *qd, *kd, *vd;
    uint32_t *ahi, *alo, *wqhi, *wqlo, *wdhi, *wdlo, *chi, *clo, *vhi, *vlo;
    cudaGetSymbolAddress((void**)&qd,   g_q);
    cudaGetSymbolAddress((void**)&kd,   g_k);
    cudaGetSymbolAddress((void**)&vd,   g_v);
    cudaGetSymbolAddress((void**)&ahi,  g_ahi);
    cudaGetSymbolAddress((void**)&alo,  g_alo);
    cudaGetSymbolAddress((void**)&wqhi, g_wqhi);
    cudaGetSymbolAddress((void**)&wqlo, g_wqlo);
    cudaGetSymbolAddress((void**)&wdhi, g_wdhi);
    cudaGetSymbolAddress((void**)&wdlo, g_wdlo);
    cudaGetSymbolAddress((void**)&chi,  g_chi);
    cudaGetSymbolAddress((void**)&clo,  g_clo);
    cudaGetSymbolAddress((void**)&vhi,  g_vhi);
    cudaGetSymbolAddress((void**)&vlo,  g_vlo);

    cudaFuncSetAttribute(gemm_tc,
                         cudaFuncAttributeMaxDynamicSharedMemorySize,
                         GT_SMEM_BYTES);
    cudaFuncSetAttribute(attn_tc,
                         cudaFuncAttributeMaxDynamicSharedMemorySize,
                         ATT_SMEM_BYTES);

    const float* bdt = (out_size >= M_ROWS * H_DIM + H_DIM) ? b_dense : nullptr;

    // [1] Fused presplit of all GEMM inputs
    {
        long total = PS_TOTAL;
        presplit_all<<<(unsigned)((total + 255) / 256), 256>>>(
            hidden, W_qkv, W_dense, ahi, alo, wqhi, wqlo, wdhi, wdlo);
    }
    // [2] QKV GEMM (3-stage cp.async) + scatter
    {
        dim3 grid(N3 / 128, M_ROWS / 128);
        gemm_tc<<<grid, 256, GT_SMEM_BYTES>>>(ahi, alo, wqhi, wqlo, b_qkv, nullptr,
                                              qd, kd, vd, nullptr,
                                              M_ROWS, N3, H_DIM, 0);
    }
    // [3] Pre-split V into frag order
    {
        long vw = (long)B_SZ * NH * (S_LEN / 2) * DH;
        presplit_v_frag<<<(unsigned)((vw + 255) / 256), 256>>>(vd, vhi, vlo, vw);
    }
    // [4] Flash attention  (ncu capture slot)
    {
        dim3 grid(S_LEN / 128, B_SZ * NH);
        attn_tc<<<grid, ATT_THREADS, ATT_SMEM_BYTES>>>(mask, qd, kd, vhi, vlo, chi, clo);
    }
    // [5] Dense GEMM -> out (+ folded b_dense tail)
    {
        dim3 grid(H_DIM / 128, M_ROWS / 128);
        gemm_tc<<<grid, 256, GT_SMEM_BYTES>>>(chi, clo, wdhi, wdlo, nullptr, out,
                                              nullptr, nullptr, nullptr, bdt,
                                              M_ROWS, H_DIM, H_DIM, 1);
    }
}